// round 2
// baseline (speedup 1.0000x reference)
#include <cuda_runtime.h>
#include <math.h>

// Problem constants
#define Bq 2
#define Sq 2048
#define Dm 1024
#define Ff 4096
#define Hh 16
#define Dhd 64
#define Mrows 4096  // B*S

// Scratch (device globals: allowed; cudaMalloc is not)
__device__ float g_qkv[(size_t)Mrows * 3 * Dm];   // 50 MB
__device__ float g_attn[(size_t)Mrows * Dm];      // 16.8 MB
__device__ float g_tmp[(size_t)Mrows * Dm];       // attn_out, then ff2 out
__device__ float g_h[(size_t)Mrows * Dm];         // after LN1
__device__ float g_ff[(size_t)Mrows * Ff];        // 67 MB
__device__ float g_cos[Sq * 32];                  // RoPE tables
__device__ float g_sin[Sq * 32];

// ---------------------------------------------------------------------------
// RoPE table kernel: double-precision trig (immune to --use_fast_math MUFU
// range-reduction error at angles up to 2047 rad). Mirrors the reference's
// fp32 rounding: fp32 inv_freq, fp32 product s*inv, exact trig of that angle.
// ---------------------------------------------------------------------------
__global__ __launch_bounds__(256) void rope_table_kernel()
{
    int idx = blockIdx.x * 256 + threadIdx.x;
    if (idx >= Sq * 32) return;
    int s = idx >> 5;
    int i = idx & 31;
    // inv_freq = 10000^(-2i/64), correctly rounded to fp32
    double invd = exp(-(double)i * (9.210340371976184 / 32.0));
    float invf = (float)invd;
    float angf = (float)s * invf;           // fp32 product, as in reference
    double a = (double)angf;
    g_cos[idx] = (float)cos(a);             // accurate double trig
    g_sin[idx] = (float)sin(a);
}

// ---------------------------------------------------------------------------
// Generic fp32 GEMM: C[m,n] = sum_k A[m,k] * W[n,k] + bias[n], optional ReLU.
// BM=128, BN=64, BK=16, 256 threads, 8x4 per-thread tile.
// ---------------------------------------------------------------------------
__global__ __launch_bounds__(256) void gemm_kernel(
    const float* __restrict__ A, const float* __restrict__ W,
    const float* __restrict__ bias, float* __restrict__ C,
    int M, int N, int K, int relu)
{
    __shared__ float As[16][128];  // [k][m] transposed
    __shared__ float Ws[16][64];   // [k][n] transposed

    int tid = threadIdx.x;
    int tx = tid & 15;      // 0..15 -> n
    int ty = tid >> 4;      // 0..15 -> m
    int row0 = blockIdx.y * 128;
    int col0 = blockIdx.x * 64;

    float acc[8][4];
#pragma unroll
    for (int i = 0; i < 8; i++)
#pragma unroll
        for (int j = 0; j < 4; j++) acc[i][j] = 0.f;

    for (int kt = 0; kt < K; kt += 16) {
#pragma unroll
        for (int l = 0; l < 2; l++) {
            int f = tid + l * 256;
            int r = f >> 2;
            int kq = (f & 3) << 2;
            float4 v = *(const float4*)(A + (size_t)(row0 + r) * K + kt + kq);
            As[kq + 0][r] = v.x; As[kq + 1][r] = v.y;
            As[kq + 2][r] = v.z; As[kq + 3][r] = v.w;
        }
        {
            int r = tid >> 2;
            int kq = (tid & 3) << 2;
            float4 v = *(const float4*)(W + (size_t)(col0 + r) * K + kt + kq);
            Ws[kq + 0][r] = v.x; Ws[kq + 1][r] = v.y;
            Ws[kq + 2][r] = v.z; Ws[kq + 3][r] = v.w;
        }
        __syncthreads();

#pragma unroll
        for (int k = 0; k < 16; k++) {
            float4 a0 = *(const float4*)&As[k][ty * 8];
            float4 a1 = *(const float4*)&As[k][ty * 8 + 4];
            float4 b  = *(const float4*)&Ws[k][tx * 4];
            float av[8] = {a0.x, a0.y, a0.z, a0.w, a1.x, a1.y, a1.z, a1.w};
            float bv[4] = {b.x, b.y, b.z, b.w};
#pragma unroll
            for (int i = 0; i < 8; i++)
#pragma unroll
                for (int j = 0; j < 4; j++)
                    acc[i][j] += av[i] * bv[j];
        }
        __syncthreads();
    }

#pragma unroll
    for (int j = 0; j < 4; j++) {
        int col = col0 + tx * 4 + j;
        float bs = bias[col];
#pragma unroll
        for (int i = 0; i < 8; i++) {
            float v = acc[i][j] + bs;
            if (relu) v = fmaxf(v, 0.f);
            C[(size_t)(row0 + ty * 8 + i) * N + col] = v;
        }
    }
}

// ---------------------------------------------------------------------------
// RoPE applied in-place to q and k sections of g_qkv, reading precomputed
// tables. One thread per (m, h, pair i).
// ---------------------------------------------------------------------------
__global__ __launch_bounds__(256) void rope_kernel(float* __restrict__ qkv)
{
    int idx = blockIdx.x * 256 + threadIdx.x;
    if (idx >= Mrows * Hh * 32) return;
    int i = idx & 31;          // pair index 0..31
    int t = idx >> 5;
    int h = t & 15;
    int m = t >> 4;            // 0..4095
    int s = m & (Sq - 1);      // seq position

    float c  = g_cos[s * 32 + i];
    float sn = g_sin[s * 32 + i];

    size_t rowbase = (size_t)m * (3 * Dm);
    int col = h * Dhd + 2 * i;

    float qe = qkv[rowbase + col];
    float qo = qkv[rowbase + col + 1];
    qkv[rowbase + col]     = qe * c - qo * sn;
    qkv[rowbase + col + 1] = qe * sn + qo * c;

    float ke = qkv[rowbase + Dm + col];
    float ko = qkv[rowbase + Dm + col + 1];
    qkv[rowbase + Dm + col]     = ke * c - ko * sn;
    qkv[rowbase + Dm + col + 1] = ke * sn + ko * c;
}

// ---------------------------------------------------------------------------
// Flash attention (fp32, online softmax). Block = (b,h, 64-row q tile),
// iterates 32-row k/v tiles. 256 threads.
// ---------------------------------------------------------------------------
__global__ __launch_bounds__(256) void attn_kernel(
    const float* __restrict__ qkv, float* __restrict__ attn)
{
    __shared__ float Qt[64][68];   // [d][r]
    __shared__ float Kt[64][34];   // [d][c]
    __shared__ float Vs[32][64];   // [kk][c]
    __shared__ float Pt[32][68];   // [kk][r]
    __shared__ float mrow[64], lrow[64], corr[64], mnew[64];
    __shared__ float red[4][64];

    int tid = threadIdx.x;
    int tx = tid & 15;
    int ty = tid >> 4;
    int bh = blockIdx.y;
    int b = bh >> 4, h = bh & 15;
    int q0 = blockIdx.x << 6;

    const size_t rs = 3 * Dm;
    const float* base = qkv + (size_t)b * Sq * rs + h * Dhd;

    for (int e = tid; e < 64 * 64; e += 256) {
        int r = e >> 6, d = e & 63;
        Qt[d][r] = base[(size_t)(q0 + r) * rs + d];
    }
    if (tid < 64) { mrow[tid] = -1e30f; lrow[tid] = 0.f; }

    float acc[4][4];
#pragma unroll
    for (int i = 0; i < 4; i++)
#pragma unroll
        for (int j = 0; j < 4; j++) acc[i][j] = 0.f;

    int r_ = tid & 63;
    int seg = tid >> 6;

    for (int kt = 0; kt < Sq; kt += 32) {
        __syncthreads();
        for (int e = tid; e < 32 * 64; e += 256) {
            int r = e >> 6, d = e & 63;
            Kt[d][r] = base[(size_t)(kt + r) * rs + Dm + d];
            Vs[r][d] = base[(size_t)(kt + r) * rs + 2 * Dm + d];
        }
        __syncthreads();

        float s[4][2] = {{0.f, 0.f}, {0.f, 0.f}, {0.f, 0.f}, {0.f, 0.f}};
#pragma unroll 8
        for (int d = 0; d < 64; d++) {
            float4 a  = *(const float4*)&Qt[d][ty * 4];
            float2 kb = *(const float2*)&Kt[d][tx * 2];
            s[0][0] += a.x * kb.x; s[0][1] += a.x * kb.y;
            s[1][0] += a.y * kb.x; s[1][1] += a.y * kb.y;
            s[2][0] += a.z * kb.x; s[2][1] += a.z * kb.y;
            s[3][0] += a.w * kb.x; s[3][1] += a.w * kb.y;
        }
#pragma unroll
        for (int i = 0; i < 4; i++)
#pragma unroll
            for (int j = 0; j < 2; j++)
                Pt[tx * 2 + j][ty * 4 + i] = s[i][j] * 0.125f;
        __syncthreads();

        float tm = -1e30f;
#pragma unroll
        for (int kk = seg * 8; kk < seg * 8 + 8; kk++)
            tm = fmaxf(tm, Pt[kk][r_]);
        red[seg][r_] = tm;
        __syncthreads();

        if (tid < 64) {
            float mo = mrow[tid];
            float mn = fmaxf(fmaxf(red[0][tid], red[1][tid]),
                             fmaxf(red[2][tid], red[3][tid]));
            mn = fmaxf(mo, mn);
            mnew[tid] = mn;
            corr[tid] = __expf(mo - mn);
        }
        __syncthreads();

        float mn = mnew[r_];
        float ps = 0.f;
#pragma unroll
        for (int kk = seg * 8; kk < seg * 8 + 8; kk++) {
            float p = __expf(Pt[kk][r_] - mn);
            Pt[kk][r_] = p;
            ps += p;
        }
        red[seg][r_] = ps;
        __syncthreads();

        if (tid < 64) {
            lrow[tid] = lrow[tid] * corr[tid]
                      + red[0][tid] + red[1][tid] + red[2][tid] + red[3][tid];
            mrow[tid] = mnew[tid];
        }

#pragma unroll
        for (int i = 0; i < 4; i++) {
            float f = corr[ty * 4 + i];
#pragma unroll
            for (int j = 0; j < 4; j++) acc[i][j] *= f;
        }

#pragma unroll 8
        for (int kk = 0; kk < 32; kk++) {
            float4 p = *(const float4*)&Pt[kk][ty * 4];
            float4 v = *(const float4*)&Vs[kk][tx * 4];
            acc[0][0] += p.x * v.x; acc[0][1] += p.x * v.y; acc[0][2] += p.x * v.z; acc[0][3] += p.x * v.w;
            acc[1][0] += p.y * v.x; acc[1][1] += p.y * v.y; acc[1][2] += p.y * v.z; acc[1][3] += p.y * v.w;
            acc[2][0] += p.z * v.x; acc[2][1] += p.z * v.y; acc[2][2] += p.z * v.z; acc[2][3] += p.z * v.w;
            acc[3][0] += p.w * v.x; acc[3][1] += p.w * v.y; acc[3][2] += p.w * v.z; acc[3][3] += p.w * v.w;
        }
    }

    __syncthreads();
#pragma unroll
    for (int i = 0; i < 4; i++) {
        float inv = 1.f / lrow[ty * 4 + i];
#pragma unroll
        for (int j = 0; j < 4; j++)
            attn[(size_t)(b * Sq + q0 + ty * 4 + i) * Dm + h * Dhd + tx * 4 + j]
                = acc[i][j] * inv;
    }
}

// ---------------------------------------------------------------------------
// Fused residual add + LayerNorm. One block per row.
// ---------------------------------------------------------------------------
__device__ __forceinline__ float block_allreduce(float v, float* sred)
{
#pragma unroll
    for (int o = 16; o; o >>= 1) v += __shfl_xor_sync(0xffffffffu, v, o);
    int w = threadIdx.x >> 5;
    if ((threadIdx.x & 31) == 0) sred[w] = v;
    __syncthreads();
    float t = (threadIdx.x < 8) ? sred[threadIdx.x] : 0.f;
    if (threadIdx.x < 32) {
#pragma unroll
        for (int o = 4; o; o >>= 1) t += __shfl_xor_sync(0xffffffffu, t, o);
        if (threadIdx.x == 0) sred[0] = t;
    }
    __syncthreads();
    float r = sred[0];
    __syncthreads();
    return r;
}

__global__ __launch_bounds__(256) void add_ln_kernel(
    const float* __restrict__ x, const float* __restrict__ y,
    const float* __restrict__ g, const float* __restrict__ bta,
    float* __restrict__ out)
{
    __shared__ float sred[8];
    int row = blockIdx.x;
    int tid = threadIdx.x;
    const float* xr = x + (size_t)row * Dm;
    const float* yr = y + (size_t)row * Dm;

    float4 xv = *(const float4*)(xr + tid * 4);
    float4 yv = *(const float4*)(yr + tid * 4);
    float v[4] = {xv.x + yv.x, xv.y + yv.y, xv.z + yv.z, xv.w + yv.w};

    float sum = v[0] + v[1] + v[2] + v[3];
    sum = block_allreduce(sum, sred);
    float mean = sum * (1.f / (float)Dm);

    float sq = 0.f;
#pragma unroll
    for (int i = 0; i < 4; i++) {
        float d = v[i] - mean;
        sq += d * d;
    }
    sq = block_allreduce(sq, sred);
    float inv = rsqrtf(sq * (1.f / (float)Dm) + 1e-5f);

    float4 gv = *(const float4*)(g + tid * 4);
    float4 bv = *(const float4*)(bta + tid * 4);
    float4 o;
    o.x = (v[0] - mean) * inv * gv.x + bv.x;
    o.y = (v[1] - mean) * inv * gv.y + bv.y;
    o.z = (v[2] - mean) * inv * gv.z + bv.z;
    o.w = (v[3] - mean) * inv * gv.w + bv.w;
    *(float4*)(out + (size_t)row * Dm + tid * 4) = o;
}

// ---------------------------------------------------------------------------
extern "C" void kernel_launch(void* const* d_in, const int* in_sizes, int n_in,
                              void* d_out, int out_size)
{
    const float* x     = (const float*)d_in[0];
    const float* in_w  = (const float*)d_in[1];
    const float* in_b  = (const float*)d_in[2];
    const float* out_w = (const float*)d_in[3];
    const float* out_b = (const float*)d_in[4];
    const float* w1    = (const float*)d_in[5];
    const float* b1    = (const float*)d_in[6];
    const float* w2    = (const float*)d_in[7];
    const float* b2    = (const float*)d_in[8];
    const float* ln1g  = (const float*)d_in[9];
    const float* ln1b  = (const float*)d_in[10];
    const float* ln2g  = (const float*)d_in[11];
    const float* ln2b  = (const float*)d_in[12];
    float* out = (float*)d_out;

    float *qkv, *attn, *tmp, *hbuf, *ff;
    cudaGetSymbolAddress((void**)&qkv,  g_qkv);
    cudaGetSymbolAddress((void**)&attn, g_attn);
    cudaGetSymbolAddress((void**)&tmp,  g_tmp);
    cudaGetSymbolAddress((void**)&hbuf, g_h);
    cudaGetSymbolAddress((void**)&ff,   g_ff);

    dim3 tb(256);

    // RoPE tables (accurate double trig — independent of GEMMs, run first)
    rope_table_kernel<<<(Sq * 32 + 255) / 256, tb>>>();
    // QKV projection
    gemm_kernel<<<dim3(3072 / 64, 4096 / 128), tb>>>(x, in_w, in_b, qkv,
                                                     Mrows, 3 * Dm, Dm, 0);
    // RoPE on q and k
    rope_kernel<<<(Mrows * Hh * 32 + 255) / 256, tb>>>(qkv);
    // Flash attention
    attn_kernel<<<dim3(Sq / 64, Bq * Hh), tb>>>(qkv, attn);
    // Output projection
    gemm_kernel<<<dim3(Dm / 64, Mrows / 128), tb>>>(attn, out_w, out_b, tmp,
                                                    Mrows, Dm, Dm, 0);
    // h = LN1(x + attn_out)
    add_ln_kernel<<<Mrows, tb>>>(x, tmp, ln1g, ln1b, hbuf);
    // FF1 + ReLU
    gemm_kernel<<<dim3(Ff / 64, Mrows / 128), tb>>>(hbuf, w1, b1, ff,
                                                    Mrows, Ff, Dm, 1);
    // FF2
    gemm_kernel<<<dim3(Dm / 64, Mrows / 128), tb>>>(ff, w2, b2, tmp,
                                                    Mrows, Dm, Ff, 0);
    // out = LN2(h + ff_out)
    add_ln_kernel<<<Mrows, tb>>>(hbuf, tmp, ln2g, ln2b, out);
}

// round 4
// speedup vs baseline: 1.7595x; 1.7595x over previous
#include <cuda_runtime.h>
#include <cuda_bf16.h>
#include <math.h>
#include <stdint.h>

// Problem constants
#define Bq 2
#define Sq 2048
#define Dm 1024
#define Ff 4096
#define Hh 16
#define Dhd 64
#define Mrows 4096  // B*S

// Scratch (device globals: allowed; cudaMalloc is not)
__device__ float g_qkv[(size_t)Mrows * 3 * Dm];
__device__ float g_attn[(size_t)Mrows * Dm];
__device__ float g_tmp[(size_t)Mrows * Dm];
__device__ float g_h[(size_t)Mrows * Dm];
__device__ float g_ff[(size_t)Mrows * Ff];
__device__ float g_cos[Sq * 32];
__device__ float g_sin[Sq * 32];

__device__ __forceinline__ uint32_t smem_u32(const void* p) {
    uint32_t a;
    asm("{ .reg .u64 t; cvta.to.shared.u64 t, %1; cvt.u32.u64 %0, t; }"
        : "=r"(a) : "l"(p));
    return a;
}

// ===========================================================================
// RoPE table kernel (double trig, immune to fast-math MUFU range reduction)
// ===========================================================================
__global__ __launch_bounds__(256) void rope_table_kernel()
{
    int idx = blockIdx.x * 256 + threadIdx.x;
    if (idx >= Sq * 32) return;
    int s = idx >> 5;
    int i = idx & 31;
    double invd = exp(-(double)i * (9.210340371976184 / 32.0));
    float invf = (float)invd;
    float angf = (float)s * invf;
    double a = (double)angf;
    g_cos[idx] = (float)cos(a);
    g_sin[idx] = (float)sin(a);
}

// ===========================================================================
// mma.sync bf16x3 GEMM (base sm_103 ISA — no 'a' features).
// C[m,n] = sum_k A[m,k]*W[n,k] + bias[n], optional ReLU.
// CTA 128x128, BK=32, 8 warps (2m x 4n), warp tile 64x32.
// A,W converted fp32 -> bf16 hi/lo in staging; 3 mma passes (hh, hl, lh)
// accumulate into fp32 fragments -> rel err ~1e-5.
// smem rows padded to 40 bf16 (80B) -> conflict-free ldmatrix.
// ===========================================================================
#define LDAB 40  // bf16 elems per smem row (32 data + 8 pad)

__device__ __forceinline__ void ldsm_x4(uint32_t* r, uint32_t addr)
{
    asm volatile("ldmatrix.sync.aligned.m8n8.x4.shared.b16 {%0,%1,%2,%3}, [%4];"
                 : "=r"(r[0]), "=r"(r[1]), "=r"(r[2]), "=r"(r[3]) : "r"(addr));
}
__device__ __forceinline__ void mma_bf16(float* c, const uint32_t* a,
                                         uint32_t b0, uint32_t b1)
{
    asm volatile(
        "mma.sync.aligned.m16n8k16.row.col.f32.bf16.bf16.f32 "
        "{%0,%1,%2,%3}, {%4,%5,%6,%7}, {%8,%9}, {%0,%1,%2,%3};"
        : "+f"(c[0]), "+f"(c[1]), "+f"(c[2]), "+f"(c[3])
        : "r"(a[0]), "r"(a[1]), "r"(a[2]), "r"(a[3]), "r"(b0), "r"(b1));
}

__device__ __forceinline__ void cvt_hilo(float4 v, uint2& hi, uint2& lo)
{
    __nv_bfloat16 h0 = __float2bfloat16(v.x);
    __nv_bfloat16 h1 = __float2bfloat16(v.y);
    __nv_bfloat16 h2 = __float2bfloat16(v.z);
    __nv_bfloat16 h3 = __float2bfloat16(v.w);
    __nv_bfloat16 l0 = __float2bfloat16(v.x - __bfloat162float(h0));
    __nv_bfloat16 l1 = __float2bfloat16(v.y - __bfloat162float(h1));
    __nv_bfloat16 l2 = __float2bfloat16(v.z - __bfloat162float(h2));
    __nv_bfloat16 l3 = __float2bfloat16(v.w - __bfloat162float(h3));
    __nv_bfloat162 p0, p1, q0, q1;
    p0.x = h0; p0.y = h1; p1.x = h2; p1.y = h3;
    q0.x = l0; q0.y = l1; q1.x = l2; q1.y = l3;
    hi.x = *(unsigned*)&p0; hi.y = *(unsigned*)&p1;
    lo.x = *(unsigned*)&q0; lo.y = *(unsigned*)&q1;
}

__global__ __launch_bounds__(256) void gemm_mma(
    const float* __restrict__ A, const float* __restrict__ W,
    const float* __restrict__ bias, float* __restrict__ C,
    int M, int N, int K, int relu)
{
    __shared__ __align__(16) __nv_bfloat16 sAh[128 * LDAB];
    __shared__ __align__(16) __nv_bfloat16 sAl[128 * LDAB];
    __shared__ __align__(16) __nv_bfloat16 sWh[128 * LDAB];
    __shared__ __align__(16) __nv_bfloat16 sWl[128 * LDAB];

    int tid = threadIdx.x;
    int lane = tid & 31, warp = tid >> 5;
    int wm = warp & 1;        // 0..1  (64 rows each)
    int wn = warp >> 1;       // 0..3  (32 cols each)
    int row0 = blockIdx.y * 128;
    int col0 = blockIdx.x * 128;

    float acc[4][4][4];       // [mtile][ntile][frag]
#pragma unroll
    for (int i = 0; i < 4; i++)
#pragma unroll
        for (int j = 0; j < 4; j++)
#pragma unroll
            for (int f = 0; f < 4; f++) acc[i][j][f] = 0.f;

    // ldmatrix row/k mapping (same for A and W)
    int frow = lane & 15;
    int fko  = (lane >> 4) << 3;

    uint32_t aAh = smem_u32(sAh), aAl = smem_u32(sAl);
    uint32_t aWh = smem_u32(sWh), aWl = smem_u32(sWl);

    for (int kt = 0; kt < K; kt += 32) {
        // ---- stage A/W slab (128x32 fp32 -> bf16 hi/lo) ----
#pragma unroll
        for (int i = 0; i < 4; i++) {
            int f = tid + i * 256;
            int r = f >> 3, q = f & 7;
            uint2 hi, lo;
            float4 va = *(const float4*)(A + (size_t)(row0 + r) * K + kt + q * 4);
            cvt_hilo(va, hi, lo);
            *(uint2*)(sAh + r * LDAB + q * 4) = hi;
            *(uint2*)(sAl + r * LDAB + q * 4) = lo;
            float4 vb = *(const float4*)(W + (size_t)(col0 + r) * K + kt + q * 4);
            cvt_hilo(vb, hi, lo);
            *(uint2*)(sWh + r * LDAB + q * 4) = hi;
            *(uint2*)(sWl + r * LDAB + q * 4) = lo;
        }
        __syncthreads();

        // ---- compute: two k16 substeps ----
#pragma unroll
        for (int s = 0; s < 2; s++) {
            int ko = s * 16 + fko;
            uint32_t afh[4][4], afl[4][4], bfh[2][4], bfl[2][4];
#pragma unroll
            for (int mt = 0; mt < 4; mt++) {
                int off = ((wm * 64 + mt * 16 + frow) * LDAB + ko) * 2;
                ldsm_x4(afh[mt], aAh + off);
                ldsm_x4(afl[mt], aAl + off);
            }
#pragma unroll
            for (int bt = 0; bt < 2; bt++) {
                int off = ((wn * 32 + bt * 16 + frow) * LDAB + ko) * 2;
                ldsm_x4(bfh[bt], aWh + off);
                ldsm_x4(bfl[bt], aWl + off);
            }
#pragma unroll
            for (int mt = 0; mt < 4; mt++)
#pragma unroll
                for (int bt = 0; bt < 2; bt++)
#pragma unroll
                    for (int h = 0; h < 2; h++) {
                        int nt = bt * 2 + h;
                        mma_bf16(acc[mt][nt], afh[mt], bfh[bt][h], bfh[bt][h + 2]);
                        mma_bf16(acc[mt][nt], afh[mt], bfl[bt][h], bfl[bt][h + 2]);
                        mma_bf16(acc[mt][nt], afl[mt], bfh[bt][h], bfh[bt][h + 2]);
                    }
        }
        __syncthreads();
    }

    // ---- epilogue ----
    int tr = lane >> 2, tc = (lane & 3) * 2;
#pragma unroll
    for (int mt = 0; mt < 4; mt++) {
#pragma unroll
        for (int nt = 0; nt < 4; nt++) {
            int col = col0 + wn * 32 + nt * 8 + tc;
            float2 bv = *(const float2*)(bias + col);
            int r0 = row0 + wm * 64 + mt * 16 + tr;
            float2 o0, o1;
            o0.x = acc[mt][nt][0] + bv.x;
            o0.y = acc[mt][nt][1] + bv.y;
            o1.x = acc[mt][nt][2] + bv.x;
            o1.y = acc[mt][nt][3] + bv.y;
            if (relu) {
                o0.x = fmaxf(o0.x, 0.f); o0.y = fmaxf(o0.y, 0.f);
                o1.x = fmaxf(o1.x, 0.f); o1.y = fmaxf(o1.y, 0.f);
            }
            *(float2*)(C + (size_t)r0 * N + col) = o0;
            *(float2*)(C + (size_t)(r0 + 8) * N + col) = o1;
        }
    }
}

// ===========================================================================
// RoPE apply (reads precomputed tables)
// ===========================================================================
__global__ __launch_bounds__(256) void rope_kernel(float* __restrict__ qkv)
{
    int idx = blockIdx.x * 256 + threadIdx.x;
    if (idx >= Mrows * Hh * 32) return;
    int i = idx & 31;
    int t = idx >> 5;
    int h = t & 15;
    int m = t >> 4;
    int s = m & (Sq - 1);

    float c  = g_cos[s * 32 + i];
    float sn = g_sin[s * 32 + i];

    size_t rowbase = (size_t)m * (3 * Dm);
    int col = h * Dhd + 2 * i;

    float qe = qkv[rowbase + col];
    float qo = qkv[rowbase + col + 1];
    qkv[rowbase + col]     = qe * c - qo * sn;
    qkv[rowbase + col + 1] = qe * sn + qo * c;

    float ke = qkv[rowbase + Dm + col];
    float ko = qkv[rowbase + Dm + col + 1];
    qkv[rowbase + Dm + col]     = ke * c - ko * sn;
    qkv[rowbase + Dm + col + 1] = ke * sn + ko * c;
}

// ===========================================================================
// Flash attention (fp32, online softmax) — unchanged
// ===========================================================================
__global__ __launch_bounds__(256) void attn_kernel(
    const float* __restrict__ qkv, float* __restrict__ attn)
{
    __shared__ float Qt[64][68];
    __shared__ float Kt[64][34];
    __shared__ float Vs[32][64];
    __shared__ float Pt[32][68];
    __shared__ float mrow[64], lrow[64], corr[64], mnew[64];
    __shared__ float red[4][64];

    int tid = threadIdx.x;
    int tx = tid & 15;
    int ty = tid >> 4;
    int bh = blockIdx.y;
    int b = bh >> 4, h = bh & 15;
    int q0 = blockIdx.x << 6;

    const size_t rs = 3 * Dm;
    const float* base = qkv + (size_t)b * Sq * rs + h * Dhd;

    for (int e = tid; e < 64 * 64; e += 256) {
        int r = e >> 6, d = e & 63;
        Qt[d][r] = base[(size_t)(q0 + r) * rs + d];
    }
    if (tid < 64) { mrow[tid] = -1e30f; lrow[tid] = 0.f; }

    float acc[4][4];
#pragma unroll
    for (int i = 0; i < 4; i++)
#pragma unroll
        for (int j = 0; j < 4; j++) acc[i][j] = 0.f;

    int r_ = tid & 63;
    int seg = tid >> 6;

    for (int kt = 0; kt < Sq; kt += 32) {
        __syncthreads();
        for (int e = tid; e < 32 * 64; e += 256) {
            int r = e >> 6, d = e & 63;
            Kt[d][r] = base[(size_t)(kt + r) * rs + Dm + d];
            Vs[r][d] = base[(size_t)(kt + r) * rs + 2 * Dm + d];
        }
        __syncthreads();

        float s[4][2] = {{0.f, 0.f}, {0.f, 0.f}, {0.f, 0.f}, {0.f, 0.f}};
#pragma unroll 8
        for (int d = 0; d < 64; d++) {
            float4 a  = *(const float4*)&Qt[d][ty * 4];
            float2 kb = *(const float2*)&Kt[d][tx * 2];
            s[0][0] += a.x * kb.x; s[0][1] += a.x * kb.y;
            s[1][0] += a.y * kb.x; s[1][1] += a.y * kb.y;
            s[2][0] += a.z * kb.x; s[2][1] += a.z * kb.y;
            s[3][0] += a.w * kb.x; s[3][1] += a.w * kb.y;
        }
#pragma unroll
        for (int i = 0; i < 4; i++)
#pragma unroll
            for (int j = 0; j < 2; j++)
                Pt[tx * 2 + j][ty * 4 + i] = s[i][j] * 0.125f;
        __syncthreads();

        float tm = -1e30f;
#pragma unroll
        for (int kk = seg * 8; kk < seg * 8 + 8; kk++)
            tm = fmaxf(tm, Pt[kk][r_]);
        red[seg][r_] = tm;
        __syncthreads();

        if (tid < 64) {
            float mo = mrow[tid];
            float mn = fmaxf(fmaxf(red[0][tid], red[1][tid]),
                             fmaxf(red[2][tid], red[3][tid]));
            mn = fmaxf(mo, mn);
            mnew[tid] = mn;
            corr[tid] = __expf(mo - mn);
        }
        __syncthreads();

        float mn = mnew[r_];
        float ps = 0.f;
#pragma unroll
        for (int kk = seg * 8; kk < seg * 8 + 8; kk++) {
            float p = __expf(Pt[kk][r_] - mn);
            Pt[kk][r_] = p;
            ps += p;
        }
        red[seg][r_] = ps;
        __syncthreads();

        if (tid < 64) {
            lrow[tid] = lrow[tid] * corr[tid]
                      + red[0][tid] + red[1][tid] + red[2][tid] + red[3][tid];
            mrow[tid] = mnew[tid];
        }

#pragma unroll
        for (int i = 0; i < 4; i++) {
            float f = corr[ty * 4 + i];
#pragma unroll
            for (int j = 0; j < 4; j++) acc[i][j] *= f;
        }

#pragma unroll 8
        for (int kk = 0; kk < 32; kk++) {
            float4 p = *(const float4*)&Pt[kk][ty * 4];
            float4 v = *(const float4*)&Vs[kk][tx * 4];
            acc[0][0] += p.x * v.x; acc[0][1] += p.x * v.y; acc[0][2] += p.x * v.z; acc[0][3] += p.x * v.w;
            acc[1][0] += p.y * v.x; acc[1][1] += p.y * v.y; acc[1][2] += p.y * v.z; acc[1][3] += p.y * v.w;
            acc[2][0] += p.z * v.x; acc[2][1] += p.z * v.y; acc[2][2] += p.z * v.z; acc[2][3] += p.z * v.w;
            acc[3][0] += p.w * v.x; acc[3][1] += p.w * v.y; acc[3][2] += p.w * v.z; acc[3][3] += p.w * v.w;
        }
    }

    __syncthreads();
#pragma unroll
    for (int i = 0; i < 4; i++) {
        float inv = 1.f / lrow[ty * 4 + i];
#pragma unroll
        for (int j = 0; j < 4; j++)
            attn[(size_t)(b * Sq + q0 + ty * 4 + i) * Dm + h * Dhd + tx * 4 + j]
                = acc[i][j] * inv;
    }
}

// ===========================================================================
// Fused residual add + LayerNorm
// ===========================================================================
__device__ __forceinline__ float block_allreduce(float v, float* sred)
{
#pragma unroll
    for (int o = 16; o; o >>= 1) v += __shfl_xor_sync(0xffffffffu, v, o);
    int w = threadIdx.x >> 5;
    if ((threadIdx.x & 31) == 0) sred[w] = v;
    __syncthreads();
    float t = (threadIdx.x < 8) ? sred[threadIdx.x] : 0.f;
    if (threadIdx.x < 32) {
#pragma unroll
        for (int o = 4; o; o >>= 1) t += __shfl_xor_sync(0xffffffffu, t, o);
        if (threadIdx.x == 0) sred[0] = t;
    }
    __syncthreads();
    float r = sred[0];
    __syncthreads();
    return r;
}

__global__ __launch_bounds__(256) void add_ln_kernel(
    const float* __restrict__ x, const float* __restrict__ y,
    const float* __restrict__ g, const float* __restrict__ bta,
    float* __restrict__ out)
{
    __shared__ float sred[8];
    int row = blockIdx.x;
    int tid = threadIdx.x;
    const float* xr = x + (size_t)row * Dm;
    const float* yr = y + (size_t)row * Dm;

    float4 xv = *(const float4*)(xr + tid * 4);
    float4 yv = *(const float4*)(yr + tid * 4);
    float v[4] = {xv.x + yv.x, xv.y + yv.y, xv.z + yv.z, xv.w + yv.w};

    float sum = v[0] + v[1] + v[2] + v[3];
    sum = block_allreduce(sum, sred);
    float mean = sum * (1.f / (float)Dm);

    float sq = 0.f;
#pragma unroll
    for (int i = 0; i < 4; i++) {
        float d = v[i] - mean;
        sq += d * d;
    }
    sq = block_allreduce(sq, sred);
    float inv = rsqrtf(sq * (1.f / (float)Dm) + 1e-5f);

    float4 gv = *(const float4*)(g + tid * 4);
    float4 bv = *(const float4*)(bta + tid * 4);
    float4 o;
    o.x = (v[0] - mean) * inv * gv.x + bv.x;
    o.y = (v[1] - mean) * inv * gv.y + bv.y;
    o.z = (v[2] - mean) * inv * gv.z + bv.z;
    o.w = (v[3] - mean) * inv * gv.w + bv.w;
    *(float4*)(out + (size_t)row * Dm + tid * 4) = o;
}

// ===========================================================================
extern "C" void kernel_launch(void* const* d_in, const int* in_sizes, int n_in,
                              void* d_out, int out_size)
{
    const float* x     = (const float*)d_in[0];
    const float* in_w  = (const float*)d_in[1];
    const float* in_b  = (const float*)d_in[2];
    const float* out_w = (const float*)d_in[3];
    const float* out_b = (const float*)d_in[4];
    const float* w1    = (const float*)d_in[5];
    const float* b1    = (const float*)d_in[6];
    const float* w2    = (const float*)d_in[7];
    const float* b2    = (const float*)d_in[8];
    const float* ln1g  = (const float*)d_in[9];
    const float* ln1b  = (const float*)d_in[10];
    const float* ln2g  = (const float*)d_in[11];
    const float* ln2b  = (const float*)d_in[12];
    float* out = (float*)d_out;

    float *qkv, *attn, *tmp, *hbuf, *ff;
    cudaGetSymbolAddress((void**)&qkv,  g_qkv);
    cudaGetSymbolAddress((void**)&attn, g_attn);
    cudaGetSymbolAddress((void**)&tmp,  g_tmp);
    cudaGetSymbolAddress((void**)&hbuf, g_h);
    cudaGetSymbolAddress((void**)&ff,   g_ff);

    dim3 tb(256);

    rope_table_kernel<<<(Sq * 32 + 255) / 256, tb>>>();
    // QKV projection (mma.sync bf16x3)
    gemm_mma<<<dim3(3072 / 128, Mrows / 128), tb>>>(x, in_w, in_b, qkv,
                                                    Mrows, 3 * Dm, Dm, 0);
    rope_kernel<<<(Mrows * Hh * 32 + 255) / 256, tb>>>(qkv);
    attn_kernel<<<dim3(Sq / 64, Bq * Hh), tb>>>(qkv, attn);
    // Output projection
    gemm_mma<<<dim3(Dm / 128, Mrows / 128), tb>>>(attn, out_w, out_b, tmp,
                                                  Mrows, Dm, Dm, 0);
    add_ln_kernel<<<Mrows, tb>>>(x, tmp, ln1g, ln1b, hbuf);
    // FF1 + ReLU
    gemm_mma<<<dim3(Ff / 128, Mrows / 128), tb>>>(hbuf, w1, b1, ff,
                                                  Mrows, Ff, Dm, 1);
    // FF2
    gemm_mma<<<dim3(Dm / 128, Mrows / 128), tb>>>(ff, w2, b2, tmp,
                                                  Mrows, Dm, Ff, 0);
    add_ln_kernel<<<Mrows, tb>>>(hbuf, tmp, ln2g, ln2b, out);
}

// round 5
// speedup vs baseline: 2.4054x; 1.3671x over previous
#include <cuda_runtime.h>
#include <cuda_bf16.h>
#include <math.h>
#include <stdint.h>

// Problem constants
#define Bq 2
#define Sq 2048
#define Dm 1024
#define Ff 4096
#define Hh 16
#define Dhd 64
#define Mrows 4096  // B*S

// Scratch (device globals: allowed; cudaMalloc is not)
__device__ float g_qkv[(size_t)Mrows * 3 * Dm];
__device__ float g_attn[(size_t)Mrows * Dm];
__device__ float g_tmp[(size_t)Mrows * Dm];
__device__ float g_h[(size_t)Mrows * Dm];
__device__ float g_ff[(size_t)Mrows * Ff];
__device__ float g_cos[Sq * 32];
__device__ float g_sin[Sq * 32];

__device__ __forceinline__ uint32_t smem_u32(const void* p) {
    uint32_t a;
    asm("{ .reg .u64 t; cvta.to.shared.u64 t, %1; cvt.u32.u64 %0, t; }"
        : "=r"(a) : "l"(p));
    return a;
}

// ===========================================================================
// RoPE table kernel (double trig, immune to fast-math MUFU range reduction)
// ===========================================================================
__global__ __launch_bounds__(256) void rope_table_kernel()
{
    int idx = blockIdx.x * 256 + threadIdx.x;
    if (idx >= Sq * 32) return;
    int s = idx >> 5;
    int i = idx & 31;
    double invd = exp(-(double)i * (9.210340371976184 / 32.0));
    float invf = (float)invd;
    float angf = (float)s * invf;
    double a = (double)angf;
    g_cos[idx] = (float)cos(a);
    g_sin[idx] = (float)sin(a);
}

// ===========================================================================
// Shared mma.sync helpers (bf16, m16n8k16, fp32 accum)
// ===========================================================================
__device__ __forceinline__ void ldsm_x4(uint32_t* r, uint32_t addr)
{
    asm volatile("ldmatrix.sync.aligned.m8n8.x4.shared.b16 {%0,%1,%2,%3}, [%4];"
                 : "=r"(r[0]), "=r"(r[1]), "=r"(r[2]), "=r"(r[3]) : "r"(addr));
}
__device__ __forceinline__ void ldsm_x4_t(uint32_t* r, uint32_t addr)
{
    asm volatile("ldmatrix.sync.aligned.m8n8.x4.trans.shared.b16 {%0,%1,%2,%3}, [%4];"
                 : "=r"(r[0]), "=r"(r[1]), "=r"(r[2]), "=r"(r[3]) : "r"(addr));
}
__device__ __forceinline__ void mma_bf16(float* c, const uint32_t* a,
                                         uint32_t b0, uint32_t b1)
{
    asm volatile(
        "mma.sync.aligned.m16n8k16.row.col.f32.bf16.bf16.f32 "
        "{%0,%1,%2,%3}, {%4,%5,%6,%7}, {%8,%9}, {%0,%1,%2,%3};"
        : "+f"(c[0]), "+f"(c[1]), "+f"(c[2]), "+f"(c[3])
        : "r"(a[0]), "r"(a[1]), "r"(a[2]), "r"(a[3]), "r"(b0), "r"(b1));
}
__device__ __forceinline__ uint32_t pack_bf16x2(float lo, float hi)
{
    uint32_t r;
    asm("cvt.rn.bf16x2.f32 %0, %1, %2;" : "=r"(r) : "f"(hi), "f"(lo));
    return r;
}
__device__ __forceinline__ void cvt_hilo(float4 v, uint2& hi, uint2& lo)
{
    __nv_bfloat16 h0 = __float2bfloat16(v.x);
    __nv_bfloat16 h1 = __float2bfloat16(v.y);
    __nv_bfloat16 h2 = __float2bfloat16(v.z);
    __nv_bfloat16 h3 = __float2bfloat16(v.w);
    __nv_bfloat16 l0 = __float2bfloat16(v.x - __bfloat162float(h0));
    __nv_bfloat16 l1 = __float2bfloat16(v.y - __bfloat162float(h1));
    __nv_bfloat16 l2 = __float2bfloat16(v.z - __bfloat162float(h2));
    __nv_bfloat16 l3 = __float2bfloat16(v.w - __bfloat162float(h3));
    __nv_bfloat162 p0, p1, q0, q1;
    p0.x = h0; p0.y = h1; p1.x = h2; p1.y = h3;
    q0.x = l0; q0.y = l1; q1.x = l2; q1.y = l3;
    hi.x = *(unsigned*)&p0; hi.y = *(unsigned*)&p1;
    lo.x = *(unsigned*)&q0; lo.y = *(unsigned*)&q1;
}

// ===========================================================================
// mma.sync bf16x3 GEMM (unchanged from R4)
// ===========================================================================
#define LDAB 40

__global__ __launch_bounds__(256) void gemm_mma(
    const float* __restrict__ A, const float* __restrict__ W,
    const float* __restrict__ bias, float* __restrict__ C,
    int M, int N, int K, int relu)
{
    __shared__ __align__(16) __nv_bfloat16 sAh[128 * LDAB];
    __shared__ __align__(16) __nv_bfloat16 sAl[128 * LDAB];
    __shared__ __align__(16) __nv_bfloat16 sWh[128 * LDAB];
    __shared__ __align__(16) __nv_bfloat16 sWl[128 * LDAB];

    int tid = threadIdx.x;
    int lane = tid & 31, warp = tid >> 5;
    int wm = warp & 1;
    int wn = warp >> 1;
    int row0 = blockIdx.y * 128;
    int col0 = blockIdx.x * 128;

    float acc[4][4][4];
#pragma unroll
    for (int i = 0; i < 4; i++)
#pragma unroll
        for (int j = 0; j < 4; j++)
#pragma unroll
            for (int f = 0; f < 4; f++) acc[i][j][f] = 0.f;

    int frow = lane & 15;
    int fko  = (lane >> 4) << 3;

    uint32_t aAh = smem_u32(sAh), aAl = smem_u32(sAl);
    uint32_t aWh = smem_u32(sWh), aWl = smem_u32(sWl);

    for (int kt = 0; kt < K; kt += 32) {
#pragma unroll
        for (int i = 0; i < 4; i++) {
            int f = tid + i * 256;
            int r = f >> 3, q = f & 7;
            uint2 hi, lo;
            float4 va = *(const float4*)(A + (size_t)(row0 + r) * K + kt + q * 4);
            cvt_hilo(va, hi, lo);
            *(uint2*)(sAh + r * LDAB + q * 4) = hi;
            *(uint2*)(sAl + r * LDAB + q * 4) = lo;
            float4 vb = *(const float4*)(W + (size_t)(col0 + r) * K + kt + q * 4);
            cvt_hilo(vb, hi, lo);
            *(uint2*)(sWh + r * LDAB + q * 4) = hi;
            *(uint2*)(sWl + r * LDAB + q * 4) = lo;
        }
        __syncthreads();

#pragma unroll
        for (int s = 0; s < 2; s++) {
            int ko = s * 16 + fko;
            uint32_t afh[4][4], afl[4][4], bfh[2][4], bfl[2][4];
#pragma unroll
            for (int mt = 0; mt < 4; mt++) {
                int off = ((wm * 64 + mt * 16 + frow) * LDAB + ko) * 2;
                ldsm_x4(afh[mt], aAh + off);
                ldsm_x4(afl[mt], aAl + off);
            }
#pragma unroll
            for (int bt = 0; bt < 2; bt++) {
                int off = ((wn * 32 + bt * 16 + frow) * LDAB + ko) * 2;
                ldsm_x4(bfh[bt], aWh + off);
                ldsm_x4(bfl[bt], aWl + off);
            }
#pragma unroll
            for (int mt = 0; mt < 4; mt++)
#pragma unroll
                for (int bt = 0; bt < 2; bt++)
#pragma unroll
                    for (int h = 0; h < 2; h++) {
                        int nt = bt * 2 + h;
                        mma_bf16(acc[mt][nt], afh[mt], bfh[bt][h], bfh[bt][h + 2]);
                        mma_bf16(acc[mt][nt], afh[mt], bfl[bt][h], bfl[bt][h + 2]);
                        mma_bf16(acc[mt][nt], afl[mt], bfh[bt][h], bfh[bt][h + 2]);
                    }
        }
        __syncthreads();
    }

    int tr = lane >> 2, tc = (lane & 3) * 2;
#pragma unroll
    for (int mt = 0; mt < 4; mt++) {
#pragma unroll
        for (int nt = 0; nt < 4; nt++) {
            int col = col0 + wn * 32 + nt * 8 + tc;
            float2 bv = *(const float2*)(bias + col);
            int r0 = row0 + wm * 64 + mt * 16 + tr;
            float2 o0, o1;
            o0.x = acc[mt][nt][0] + bv.x;
            o0.y = acc[mt][nt][1] + bv.y;
            o1.x = acc[mt][nt][2] + bv.x;
            o1.y = acc[mt][nt][3] + bv.y;
            if (relu) {
                o0.x = fmaxf(o0.x, 0.f); o0.y = fmaxf(o0.y, 0.f);
                o1.x = fmaxf(o1.x, 0.f); o1.y = fmaxf(o1.y, 0.f);
            }
            *(float2*)(C + (size_t)r0 * N + col) = o0;
            *(float2*)(C + (size_t)(r0 + 8) * N + col) = o1;
        }
    }
}

// ===========================================================================
// RoPE apply
// ===========================================================================
__global__ __launch_bounds__(256) void rope_kernel(float* __restrict__ qkv)
{
    int idx = blockIdx.x * 256 + threadIdx.x;
    if (idx >= Mrows * Hh * 32) return;
    int i = idx & 31;
    int t = idx >> 5;
    int h = t & 15;
    int m = t >> 4;
    int s = m & (Sq - 1);

    float c  = g_cos[s * 32 + i];
    float sn = g_sin[s * 32 + i];

    size_t rowbase = (size_t)m * (3 * Dm);
    int col = h * Dhd + 2 * i;

    float qe = qkv[rowbase + col];
    float qo = qkv[rowbase + col + 1];
    qkv[rowbase + col]     = qe * c - qo * sn;
    qkv[rowbase + col + 1] = qe * sn + qo * c;

    float ke = qkv[rowbase + Dm + col];
    float ko = qkv[rowbase + Dm + col + 1];
    qkv[rowbase + Dm + col]     = ke * c - ko * sn;
    qkv[rowbase + Dm + col + 1] = ke * sn + ko * c;
}

// ===========================================================================
// Flash attention via mma.sync bf16x3 (hi/lo split), online softmax in regs.
// CTA = 128 q-rows of one (b,h); 8 warps x 16 q-rows; k-tiles of 64 keys.
// smem rows padded to 72 bf16 (144B = 9*16B: aligned, conflict-free ldmatrix).
// ===========================================================================
#define ATT_LD 72
#define ATT_SMEM ((128 * ATT_LD * 2 + 64 * ATT_LD * 4) * 2)  // 73728 bytes

__global__ __launch_bounds__(256) void attn_mma(
    const float* __restrict__ qkv, float* __restrict__ attn)
{
    extern __shared__ __nv_bfloat16 sm[];
    __nv_bfloat16* sQh = sm;
    __nv_bfloat16* sQl = sQh + 128 * ATT_LD;
    __nv_bfloat16* sKh = sQl + 128 * ATT_LD;
    __nv_bfloat16* sKl = sKh + 64 * ATT_LD;
    __nv_bfloat16* sVh = sKl + 64 * ATT_LD;
    __nv_bfloat16* sVl = sVh + 64 * ATT_LD;

    int tid = threadIdx.x;
    int lane = tid & 31, warp = tid >> 5;
    int bh = blockIdx.y;
    int b = bh >> 4, hh = bh & 15;
    int q0 = blockIdx.x * 128;

    const float* base = qkv + (size_t)b * Sq * 3072 + hh * 64;

    // Stage Q (128 x 64 fp32 -> bf16 hi/lo)
#pragma unroll
    for (int i = 0; i < 8; i++) {
        int f = tid + i * 256;
        int r = f >> 4, q = f & 15;
        float4 v = *(const float4*)(base + (size_t)(q0 + r) * 3072 + q * 4);
        uint2 hi, lo;
        cvt_hilo(v, hi, lo);
        *(uint2*)(sQh + r * ATT_LD + q * 4) = hi;
        *(uint2*)(sQl + r * ATT_LD + q * 4) = lo;
    }
    __syncthreads();

    int frow = lane & 15;
    int fko  = (lane >> 4) << 3;
    uint32_t aQhB = smem_u32(sQh), aQlB = smem_u32(sQl);
    uint32_t aKhB = smem_u32(sKh), aKlB = smem_u32(sKl);
    uint32_t aVhB = smem_u32(sVh), aVlB = smem_u32(sVl);

    // Cache Q a-frags for this warp's 16 rows (constant across k-tiles)
    uint32_t aQh[4][4], aQl[4][4];
#pragma unroll
    for (int c = 0; c < 4; c++) {
        int off = ((warp * 16 + frow) * ATT_LD + c * 16 + fko) * 2;
        ldsm_x4(aQh[c], aQhB + off);
        ldsm_x4(aQl[c], aQlB + off);
    }

    float m0 = -1e30f, m1 = -1e30f, l0 = 0.f, l1 = 0.f;
    float oacc[8][4];
#pragma unroll
    for (int j = 0; j < 8; j++)
#pragma unroll
        for (int f = 0; f < 4; f++) oacc[j][f] = 0.f;

    for (int kt = 0; kt < Sq; kt += 64) {
        __syncthreads();
        // Stage K, V tiles (64 x 64 each)
#pragma unroll
        for (int i = 0; i < 4; i++) {
            int f = tid + i * 256;
            int r = f >> 4, q = f & 15;
            const float* rowp = base + (size_t)(kt + r) * 3072;
            uint2 hi, lo;
            float4 kv = *(const float4*)(rowp + 1024 + q * 4);
            cvt_hilo(kv, hi, lo);
            *(uint2*)(sKh + r * ATT_LD + q * 4) = hi;
            *(uint2*)(sKl + r * ATT_LD + q * 4) = lo;
            float4 vv = *(const float4*)(rowp + 2048 + q * 4);
            cvt_hilo(vv, hi, lo);
            *(uint2*)(sVh + r * ATT_LD + q * 4) = hi;
            *(uint2*)(sVl + r * ATT_LD + q * 4) = lo;
        }
        __syncthreads();

        // ---- S = Q @ K^T (16 x 64 per warp, 3-pass hi/lo) ----
        float sacc[8][4];
#pragma unroll
        for (int j = 0; j < 8; j++)
#pragma unroll
            for (int f = 0; f < 4; f++) sacc[j][f] = 0.f;

#pragma unroll
        for (int kd = 0; kd < 4; kd++) {
#pragma unroll
            for (int bt = 0; bt < 4; bt++) {
                uint32_t kh[4], kl[4];
                int off = ((bt * 16 + frow) * ATT_LD + kd * 16 + fko) * 2;
                ldsm_x4(kh, aKhB + off);
                ldsm_x4(kl, aKlB + off);
#pragma unroll
                for (int h = 0; h < 2; h++) {
                    int nt = bt * 2 + h;
                    mma_bf16(sacc[nt], aQh[kd], kh[h], kh[h + 2]);
                    mma_bf16(sacc[nt], aQh[kd], kl[h], kl[h + 2]);
                    mma_bf16(sacc[nt], aQl[kd], kh[h], kh[h + 2]);
                }
            }
        }

        // ---- online softmax on fragments ----
        float rmax0 = -1e30f, rmax1 = -1e30f;
#pragma unroll
        for (int j = 0; j < 8; j++) {
            rmax0 = fmaxf(rmax0, fmaxf(sacc[j][0], sacc[j][1]));
            rmax1 = fmaxf(rmax1, fmaxf(sacc[j][2], sacc[j][3]));
        }
        rmax0 = fmaxf(rmax0, __shfl_xor_sync(0xffffffffu, rmax0, 1));
        rmax0 = fmaxf(rmax0, __shfl_xor_sync(0xffffffffu, rmax0, 2));
        rmax1 = fmaxf(rmax1, __shfl_xor_sync(0xffffffffu, rmax1, 1));
        rmax1 = fmaxf(rmax1, __shfl_xor_sync(0xffffffffu, rmax1, 2));

        float mn0 = fmaxf(m0, 0.125f * rmax0);
        float mn1 = fmaxf(m1, 0.125f * rmax1);
        float corr0 = __expf(m0 - mn0);
        float corr1 = __expf(m1 - mn1);
        m0 = mn0; m1 = mn1;

        // P = exp(s/8 - m); pack into bf16 hi/lo a-frags; accumulate row sums
        uint32_t pah[4][4], pal[4][4];
        float ps0 = 0.f, ps1 = 0.f;
#pragma unroll
        for (int c = 0; c < 4; c++) {
#pragma unroll
            for (int u = 0; u < 2; u++) {        // ntiles 2c, 2c+1
                int j = 2 * c + u;
                float p0 = __expf(0.125f * sacc[j][0] - mn0);
                float p1 = __expf(0.125f * sacc[j][1] - mn0);
                float p2 = __expf(0.125f * sacc[j][2] - mn1);
                float p3 = __expf(0.125f * sacc[j][3] - mn1);
                ps0 += p0 + p1;
                ps1 += p2 + p3;
                __nv_bfloat16 h0 = __float2bfloat16(p0);
                __nv_bfloat16 h1 = __float2bfloat16(p1);
                __nv_bfloat16 h2 = __float2bfloat16(p2);
                __nv_bfloat16 h3 = __float2bfloat16(p3);
                float l0f = p0 - __bfloat162float(h0);
                float l1f = p1 - __bfloat162float(h1);
                float l2f = p2 - __bfloat162float(h2);
                float l3f = p3 - __bfloat162float(h3);
                __nv_bfloat162 ph01, ph23;
                ph01.x = h0; ph01.y = h1;
                ph23.x = h2; ph23.y = h3;
                pah[c][2 * u + 0] = *(unsigned*)&ph01;
                pah[c][2 * u + 1] = *(unsigned*)&ph23;
                pal[c][2 * u + 0] = pack_bf16x2(l0f, l1f);
                pal[c][2 * u + 1] = pack_bf16x2(l2f, l3f);
            }
        }
        ps0 += __shfl_xor_sync(0xffffffffu, ps0, 1);
        ps0 += __shfl_xor_sync(0xffffffffu, ps0, 2);
        ps1 += __shfl_xor_sync(0xffffffffu, ps1, 1);
        ps1 += __shfl_xor_sync(0xffffffffu, ps1, 2);
        l0 = l0 * corr0 + ps0;
        l1 = l1 * corr1 + ps1;

        // rescale O
#pragma unroll
        for (int j = 0; j < 8; j++) {
            oacc[j][0] *= corr0; oacc[j][1] *= corr0;
            oacc[j][2] *= corr1; oacc[j][3] *= corr1;
        }

        // ---- O += P @ V (V frags via ldmatrix.trans on natural [kk][d]) ----
#pragma unroll
        for (int c = 0; c < 4; c++) {
#pragma unroll
            for (int g = 0; g < 4; g++) {
                uint32_t vh[4], vl[4];
                int off = ((c * 16 + frow) * ATT_LD + g * 16 + fko) * 2;
                ldsm_x4_t(vh, aVhB + off);
                ldsm_x4_t(vl, aVlB + off);
#pragma unroll
                for (int h2 = 0; h2 < 2; h2++) {
                    int j = g * 2 + h2;
                    mma_bf16(oacc[j], pah[c], vh[2 * h2], vh[2 * h2 + 1]);
                    mma_bf16(oacc[j], pah[c], vl[2 * h2], vl[2 * h2 + 1]);
                    mma_bf16(oacc[j], pal[c], vh[2 * h2], vh[2 * h2 + 1]);
                }
            }
        }
    }

    // ---- epilogue ----
    float inv0 = 1.f / l0, inv1 = 1.f / l1;
    int tr = lane >> 2, tc = (lane & 3) * 2;
    int row0 = b * Sq + q0 + warp * 16 + tr;
#pragma unroll
    for (int j = 0; j < 8; j++) {
        int col = hh * 64 + j * 8 + tc;
        float2 o0, o1;
        o0.x = oacc[j][0] * inv0; o0.y = oacc[j][1] * inv0;
        o1.x = oacc[j][2] * inv1; o1.y = oacc[j][3] * inv1;
        *(float2*)(attn + (size_t)row0 * Dm + col) = o0;
        *(float2*)(attn + (size_t)(row0 + 8) * Dm + col) = o1;
    }
}

// ===========================================================================
// Fused residual add + LayerNorm
// ===========================================================================
__device__ __forceinline__ float block_allreduce(float v, float* sred)
{
#pragma unroll
    for (int o = 16; o; o >>= 1) v += __shfl_xor_sync(0xffffffffu, v, o);
    int w = threadIdx.x >> 5;
    if ((threadIdx.x & 31) == 0) sred[w] = v;
    __syncthreads();
    float t = (threadIdx.x < 8) ? sred[threadIdx.x] : 0.f;
    if (threadIdx.x < 32) {
#pragma unroll
        for (int o = 4; o; o >>= 1) t += __shfl_xor_sync(0xffffffffu, t, o);
        if (threadIdx.x == 0) sred[0] = t;
    }
    __syncthreads();
    float r = sred[0];
    __syncthreads();
    return r;
}

__global__ __launch_bounds__(256) void add_ln_kernel(
    const float* __restrict__ x, const float* __restrict__ y,
    const float* __restrict__ g, const float* __restrict__ bta,
    float* __restrict__ out)
{
    __shared__ float sred[8];
    int row = blockIdx.x;
    int tid = threadIdx.x;
    const float* xr = x + (size_t)row * Dm;
    const float* yr = y + (size_t)row * Dm;

    float4 xv = *(const float4*)(xr + tid * 4);
    float4 yv = *(const float4*)(yr + tid * 4);
    float v[4] = {xv.x + yv.x, xv.y + yv.y, xv.z + yv.z, xv.w + yv.w};

    float sum = v[0] + v[1] + v[2] + v[3];
    sum = block_allreduce(sum, sred);
    float mean = sum * (1.f / (float)Dm);

    float sq = 0.f;
#pragma unroll
    for (int i = 0; i < 4; i++) {
        float d = v[i] - mean;
        sq += d * d;
    }
    sq = block_allreduce(sq, sred);
    float inv = rsqrtf(sq * (1.f / (float)Dm) + 1e-5f);

    float4 gv = *(const float4*)(g + tid * 4);
    float4 bv = *(const float4*)(bta + tid * 4);
    float4 o;
    o.x = (v[0] - mean) * inv * gv.x + bv.x;
    o.y = (v[1] - mean) * inv * gv.y + bv.y;
    o.z = (v[2] - mean) * inv * gv.z + bv.z;
    o.w = (v[3] - mean) * inv * gv.w + bv.w;
    *(float4*)(out + (size_t)row * Dm + tid * 4) = o;
}

// ===========================================================================
extern "C" void kernel_launch(void* const* d_in, const int* in_sizes, int n_in,
                              void* d_out, int out_size)
{
    const float* x     = (const float*)d_in[0];
    const float* in_w  = (const float*)d_in[1];
    const float* in_b  = (const float*)d_in[2];
    const float* out_w = (const float*)d_in[3];
    const float* out_b = (const float*)d_in[4];
    const float* w1    = (const float*)d_in[5];
    const float* b1    = (const float*)d_in[6];
    const float* w2    = (const float*)d_in[7];
    const float* b2    = (const float*)d_in[8];
    const float* ln1g  = (const float*)d_in[9];
    const float* ln1b  = (const float*)d_in[10];
    const float* ln2g  = (const float*)d_in[11];
    const float* ln2b  = (const float*)d_in[12];
    float* out = (float*)d_out;

    float *qkv, *attn, *tmp, *hbuf, *ff;
    cudaGetSymbolAddress((void**)&qkv,  g_qkv);
    cudaGetSymbolAddress((void**)&attn, g_attn);
    cudaGetSymbolAddress((void**)&tmp,  g_tmp);
    cudaGetSymbolAddress((void**)&hbuf, g_h);
    cudaGetSymbolAddress((void**)&ff,   g_ff);

    cudaFuncSetAttribute(attn_mma, cudaFuncAttributeMaxDynamicSharedMemorySize,
                         ATT_SMEM);

    dim3 tb(256);

    rope_table_kernel<<<(Sq * 32 + 255) / 256, tb>>>();
    // QKV projection (mma.sync bf16x3)
    gemm_mma<<<dim3(3072 / 128, Mrows / 128), tb>>>(x, in_w, in_b, qkv,
                                                    Mrows, 3 * Dm, Dm, 0);
    rope_kernel<<<(Mrows * Hh * 32 + 255) / 256, tb>>>(qkv);
    // Flash attention (mma.sync bf16x3)
    attn_mma<<<dim3(Sq / 128, Bq * Hh), tb, ATT_SMEM>>>(qkv, attn);
    // Output projection
    gemm_mma<<<dim3(Dm / 128, Mrows / 128), tb>>>(attn, out_w, out_b, tmp,
                                                  Mrows, Dm, Dm, 0);
    add_ln_kernel<<<Mrows, tb>>>(x, tmp, ln1g, ln1b, hbuf);
    // FF1 + ReLU
    gemm_mma<<<dim3(Ff / 128, Mrows / 128), tb>>>(hbuf, w1, b1, ff,
                                                  Mrows, Ff, Dm, 1);
    // FF2
    gemm_mma<<<dim3(Dm / 128, Mrows / 128), tb>>>(ff, w2, b2, tmp,
                                                  Mrows, Dm, Ff, 0);
    add_ln_kernel<<<Mrows, tb>>>(hbuf, tmp, ln2g, ln2b, out);
}

// round 6
// speedup vs baseline: 2.5526x; 1.0612x over previous
#include <cuda_runtime.h>
#include <cuda_bf16.h>
#include <math.h>
#include <stdint.h>

// Problem constants
#define Bq 2
#define Sq 2048
#define Dm 1024
#define Ff 4096
#define Hh 16
#define Dhd 64
#define Mrows 4096  // B*S

// ---------------------------------------------------------------------------
// Scratch (device globals)
// ---------------------------------------------------------------------------
__device__ float g_qkv[(size_t)Mrows * 3 * Dm];
__device__ float g_tmp[(size_t)Mrows * Dm];
__device__ float g_h[(size_t)Mrows * Dm];
__device__ float g_cos[Sq * 32];
__device__ float g_sin[Sq * 32];

__device__ __nv_bfloat16 g_xh[(size_t)Mrows * Dm], g_xl[(size_t)Mrows * Dm];
__device__ __nv_bfloat16 g_wbh[12582912], g_wbl[12582912];
// weight offsets: in_proj 0 (3145728), out_w 3145728, w1 4194304, w2 8388608
#define OFF_INW 0
#define OFF_OUTW 3145728
#define OFF_W1 4194304
#define OFF_W2 8388608
__device__ __nv_bfloat16 g_qh[(size_t)Bq * Hh * Sq * 64], g_ql[(size_t)Bq * Hh * Sq * 64];
__device__ __nv_bfloat16 g_kh[(size_t)Bq * Hh * Sq * 64], g_kl[(size_t)Bq * Hh * Sq * 64];
__device__ __nv_bfloat16 g_vh[(size_t)Bq * Hh * Sq * 64], g_vl[(size_t)Bq * Hh * Sq * 64];
__device__ __nv_bfloat16 g_ath[(size_t)Mrows * Dm], g_atl[(size_t)Mrows * Dm];
__device__ __nv_bfloat16 g_hh[(size_t)Mrows * Dm], g_hl[(size_t)Mrows * Dm];
__device__ __nv_bfloat16 g_ffh[(size_t)Mrows * Ff], g_ffl[(size_t)Mrows * Ff];

__device__ __forceinline__ uint32_t smem_u32(const void* p) {
    uint32_t a;
    asm("{ .reg .u64 t; cvta.to.shared.u64 t, %1; cvt.u32.u64 %0, t; }"
        : "=r"(a) : "l"(p));
    return a;
}
__device__ __forceinline__ void cp16(uint32_t dst, const void* src) {
    asm volatile("cp.async.cg.shared.global [%0], [%1], 16;"
                 :: "r"(dst), "l"(src));
}
#define CP_COMMIT() asm volatile("cp.async.commit_group;" ::: "memory")
#define CP_WAIT1()  asm volatile("cp.async.wait_group 1;" ::: "memory")
#define CP_WAIT0()  asm volatile("cp.async.wait_group 0;" ::: "memory")

__device__ __forceinline__ void ldsm_x4(uint32_t* r, uint32_t addr)
{
    asm volatile("ldmatrix.sync.aligned.m8n8.x4.shared.b16 {%0,%1,%2,%3}, [%4];"
                 : "=r"(r[0]), "=r"(r[1]), "=r"(r[2]), "=r"(r[3]) : "r"(addr));
}
__device__ __forceinline__ void ldsm_x4_t(uint32_t* r, uint32_t addr)
{
    asm volatile("ldmatrix.sync.aligned.m8n8.x4.trans.shared.b16 {%0,%1,%2,%3}, [%4];"
                 : "=r"(r[0]), "=r"(r[1]), "=r"(r[2]), "=r"(r[3]) : "r"(addr));
}
__device__ __forceinline__ void mma_bf16(float* c, const uint32_t* a,
                                         uint32_t b0, uint32_t b1)
{
    asm volatile(
        "mma.sync.aligned.m16n8k16.row.col.f32.bf16.bf16.f32 "
        "{%0,%1,%2,%3}, {%4,%5,%6,%7}, {%8,%9}, {%0,%1,%2,%3};"
        : "+f"(c[0]), "+f"(c[1]), "+f"(c[2]), "+f"(c[3])
        : "r"(a[0]), "r"(a[1]), "r"(a[2]), "r"(a[3]), "r"(b0), "r"(b1));
}
__device__ __forceinline__ uint32_t pack_bf16x2(float lo, float hi)
{
    uint32_t r;
    asm("cvt.rn.bf16x2.f32 %0, %1, %2;" : "=r"(r) : "f"(hi), "f"(lo));
    return r;
}
__device__ __forceinline__ void split8(const float* v, uint2& hi, uint2& lo)
{
    // 8 floats -> 8 bf16 hi (uint2... actually 4x bf16x2 = 2 uint2)
    __nv_bfloat16 h[8];
#pragma unroll
    for (int i = 0; i < 8; i++) h[i] = __float2bfloat16(v[i]);
    uint32_t* hp = (uint32_t*)&hi;
    hp[0] = ((uint32_t*)h)[0];  // not used; replaced below
    (void)hp;
    // pack properly
    uint32_t w0, w1, w2, w3;
    __nv_bfloat162 t;
    t.x = h[0]; t.y = h[1]; w0 = *(uint32_t*)&t;
    t.x = h[2]; t.y = h[3]; w1 = *(uint32_t*)&t;
    t.x = h[4]; t.y = h[5]; w2 = *(uint32_t*)&t;
    t.x = h[6]; t.y = h[7]; w3 = *(uint32_t*)&t;
    hi.x = w0; hi.y = w1;
    lo.x = w2; lo.y = w3;   // NOTE: caller treats hi={e0..3}, lo={e4..7} of HI part
}

// ===========================================================================
// RoPE table kernel
// ===========================================================================
__global__ __launch_bounds__(256) void rope_table_kernel()
{
    int idx = blockIdx.x * 256 + threadIdx.x;
    if (idx >= Sq * 32) return;
    int s = idx >> 5;
    int i = idx & 31;
    double invd = exp(-(double)i * (9.210340371976184 / 32.0));
    float invf = (float)invd;
    float angf = (float)s * invf;
    double a = (double)angf;
    g_cos[idx] = (float)cos(a);
    g_sin[idx] = (float)sin(a);
}

// ===========================================================================
// Generic fp32 -> bf16 hi/lo converter (4 elems/thread)
// ===========================================================================
__global__ __launch_bounds__(256) void cvt_kernel(
    const float* __restrict__ src, __nv_bfloat16* __restrict__ dh,
    __nv_bfloat16* __restrict__ dl, int n4)
{
    int idx = blockIdx.x * 256 + threadIdx.x;
    if (idx >= n4) return;
    float4 v = *(const float4*)(src + (size_t)idx * 4);
    __nv_bfloat16 h0 = __float2bfloat16(v.x);
    __nv_bfloat16 h1 = __float2bfloat16(v.y);
    __nv_bfloat16 h2 = __float2bfloat16(v.z);
    __nv_bfloat16 h3 = __float2bfloat16(v.w);
    uint32_t lo01 = pack_bf16x2(v.x - __bfloat162float(h0), v.y - __bfloat162float(h1));
    uint32_t lo23 = pack_bf16x2(v.z - __bfloat162float(h2), v.w - __bfloat162float(h3));
    __nv_bfloat162 a, b;
    a.x = h0; a.y = h1; b.x = h2; b.y = h3;
    uint2 hv; hv.x = *(uint32_t*)&a; hv.y = *(uint32_t*)&b;
    uint2 lv; lv.x = lo01; lv.y = lo23;
    *(uint2*)(dh + (size_t)idx * 4) = hv;
    *(uint2*)(dl + (size_t)idx * 4) = lv;
}

// ===========================================================================
// RoPE + split: qkv fp32 -> head-major bf16 hi/lo Q,K,V arrays.
// One thread = 8 consecutive elems (4 rope pairs) of one (m,h) row.
// ===========================================================================
__global__ __launch_bounds__(256) void rope_bf_kernel(const float* __restrict__ qkv)
{
    int idx = blockIdx.x * 256 + threadIdx.x;  // total Mrows*Hh*8 = 524288
    if (idx >= Mrows * Hh * 8) return;
    int e0 = (idx & 7) * 8;
    int h  = (idx >> 3) & 15;
    int m  = idx >> 7;
    int s  = m & (Sq - 1);
    int b  = m >> 11;
    int bh = b * Hh + h;
    int i0 = e0 >> 1;

    const float* rp = qkv + (size_t)m * 3072 + h * 64 + e0;
    float q[8], k[8], v[8];
    *(float4*)(q)     = *(const float4*)(rp);
    *(float4*)(q + 4) = *(const float4*)(rp + 4);
    *(float4*)(k)     = *(const float4*)(rp + 1024);
    *(float4*)(k + 4) = *(const float4*)(rp + 1028);
    *(float4*)(v)     = *(const float4*)(rp + 2048);
    *(float4*)(v + 4) = *(const float4*)(rp + 2052);

    float qr[8], kr[8];
#pragma unroll
    for (int p = 0; p < 4; p++) {
        float c  = g_cos[s * 32 + i0 + p];
        float sn = g_sin[s * 32 + i0 + p];
        qr[2 * p]     = q[2 * p] * c - q[2 * p + 1] * sn;
        qr[2 * p + 1] = q[2 * p] * sn + q[2 * p + 1] * c;
        kr[2 * p]     = k[2 * p] * c - k[2 * p + 1] * sn;
        kr[2 * p + 1] = k[2 * p] * sn + k[2 * p + 1] * c;
    }

    size_t d = ((size_t)bh * Sq + s) * 64 + e0;
    // q
    {
        __nv_bfloat16 hb[8]; uint2 hv, lv;
#pragma unroll
        for (int i = 0; i < 8; i++) hb[i] = __float2bfloat16(qr[i]);
        __nv_bfloat162 t0, t1, t2, t3;
        t0.x = hb[0]; t0.y = hb[1]; t1.x = hb[2]; t1.y = hb[3];
        t2.x = hb[4]; t2.y = hb[5]; t3.x = hb[6]; t3.y = hb[7];
        hv.x = *(uint32_t*)&t0; hv.y = *(uint32_t*)&t1;
        uint2 hv2; hv2.x = *(uint32_t*)&t2; hv2.y = *(uint32_t*)&t3;
        lv.x = pack_bf16x2(qr[0] - __bfloat162float(hb[0]), qr[1] - __bfloat162float(hb[1]));
        lv.y = pack_bf16x2(qr[2] - __bfloat162float(hb[2]), qr[3] - __bfloat162float(hb[3]));
        uint2 lv2;
        lv2.x = pack_bf16x2(qr[4] - __bfloat162float(hb[4]), qr[5] - __bfloat162float(hb[5]));
        lv2.y = pack_bf16x2(qr[6] - __bfloat162float(hb[6]), qr[7] - __bfloat162float(hb[7]));
        *(uint2*)(g_qh + d) = hv; *(uint2*)(g_qh + d + 4) = hv2;
        *(uint2*)(g_ql + d) = lv; *(uint2*)(g_ql + d + 4) = lv2;
    }
    // k
    {
        __nv_bfloat16 hb[8];
#pragma unroll
        for (int i = 0; i < 8; i++) hb[i] = __float2bfloat16(kr[i]);
        __nv_bfloat162 t0, t1, t2, t3;
        t0.x = hb[0]; t0.y = hb[1]; t1.x = hb[2]; t1.y = hb[3];
        t2.x = hb[4]; t2.y = hb[5]; t3.x = hb[6]; t3.y = hb[7];
        uint2 hv, hv2, lv, lv2;
        hv.x = *(uint32_t*)&t0; hv.y = *(uint32_t*)&t1;
        hv2.x = *(uint32_t*)&t2; hv2.y = *(uint32_t*)&t3;
        lv.x = pack_bf16x2(kr[0] - __bfloat162float(hb[0]), kr[1] - __bfloat162float(hb[1]));
        lv.y = pack_bf16x2(kr[2] - __bfloat162float(hb[2]), kr[3] - __bfloat162float(hb[3]));
        lv2.x = pack_bf16x2(kr[4] - __bfloat162float(hb[4]), kr[5] - __bfloat162float(hb[5]));
        lv2.y = pack_bf16x2(kr[6] - __bfloat162float(hb[6]), kr[7] - __bfloat162float(hb[7]));
        *(uint2*)(g_kh + d) = hv; *(uint2*)(g_kh + d + 4) = hv2;
        *(uint2*)(g_kl + d) = lv; *(uint2*)(g_kl + d + 4) = lv2;
    }
    // v (no rotation)
    {
        __nv_bfloat16 hb[8];
#pragma unroll
        for (int i = 0; i < 8; i++) hb[i] = __float2bfloat16(v[i]);
        __nv_bfloat162 t0, t1, t2, t3;
        t0.x = hb[0]; t0.y = hb[1]; t1.x = hb[2]; t1.y = hb[3];
        t2.x = hb[4]; t2.y = hb[5]; t3.x = hb[6]; t3.y = hb[7];
        uint2 hv, hv2, lv, lv2;
        hv.x = *(uint32_t*)&t0; hv.y = *(uint32_t*)&t1;
        hv2.x = *(uint32_t*)&t2; hv2.y = *(uint32_t*)&t3;
        lv.x = pack_bf16x2(v[0] - __bfloat162float(hb[0]), v[1] - __bfloat162float(hb[1]));
        lv.y = pack_bf16x2(v[2] - __bfloat162float(hb[2]), v[3] - __bfloat162float(hb[3]));
        lv2.x = pack_bf16x2(v[4] - __bfloat162float(hb[4]), v[5] - __bfloat162float(hb[5]));
        lv2.y = pack_bf16x2(v[6] - __bfloat162float(hb[6]), v[7] - __bfloat162float(hb[7]));
        *(uint2*)(g_vh + d) = hv; *(uint2*)(g_vh + d + 4) = hv2;
        *(uint2*)(g_vl + d) = lv; *(uint2*)(g_vl + d + 4) = lv2;
    }
}

// ===========================================================================
// bf16x3 GEMM with cp.async double buffering.
// A (Ah,Al) [M,K] bf16; W (Wh,Wl) [N,K] bf16. mode 0: fp32 out; 1: relu+bf16 hi/lo.
// CTA 128x128, BK=32, 8 warps. pitch 40 bf16 (80B: 16B-aligned, ldsm conflict-free).
// smem: 2 stages x 4 arrays x 128x40x2B = 81920 bytes.
// ===========================================================================
#define GPITCH 80          // bytes per row
#define GARR 10240         // bytes per array (128*80)
#define GSTG 40960         // bytes per stage

__global__ __launch_bounds__(256) void gemm_bf(
    const __nv_bfloat16* __restrict__ Ah, const __nv_bfloat16* __restrict__ Al,
    const __nv_bfloat16* __restrict__ Wh, const __nv_bfloat16* __restrict__ Wl,
    const float* __restrict__ bias, float* __restrict__ Cf,
    __nv_bfloat16* __restrict__ Ch, __nv_bfloat16* __restrict__ Cl,
    int N, int K, int mode)
{
    extern __shared__ char dsm[];
    uint32_t sb = smem_u32(dsm);

    int tid = threadIdx.x;
    int lane = tid & 31, warp = tid >> 5;
    int wm = warp & 1;
    int wn = warp >> 1;
    int row0 = blockIdx.y * 128;
    int col0 = blockIdx.x * 128;

    float acc[4][4][4];
#pragma unroll
    for (int i = 0; i < 4; i++)
#pragma unroll
        for (int j = 0; j < 4; j++)
#pragma unroll
            for (int f = 0; f < 4; f++) acc[i][j][f] = 0.f;

    int frow = lane & 15;
    int fko  = (lane >> 4) << 3;

    // staging: 2048 chunks of 16B per stage, 8 per thread
    int sf[8], sa[8], sr[8], sq[8];
#pragma unroll
    for (int i = 0; i < 8; i++) {
        int f = tid + i * 256;
        sf[i] = f; sa[i] = f >> 9;
        int rem = f & 511;
        sr[i] = rem >> 2; sq[i] = rem & 3;
    }

    int nk = K >> 5;

    // prefetch stage 0
#pragma unroll
    for (int i = 0; i < 8; i++) {
        const __nv_bfloat16* s;
        if (sa[i] == 0)      s = Ah + (size_t)(row0 + sr[i]) * K;
        else if (sa[i] == 1) s = Al + (size_t)(row0 + sr[i]) * K;
        else if (sa[i] == 2) s = Wh + (size_t)(col0 + sr[i]) * K;
        else                 s = Wl + (size_t)(col0 + sr[i]) * K;
        cp16(sb + sa[i] * GARR + sr[i] * GPITCH + sq[i] * 16, s + sq[i] * 8);
    }
    CP_COMMIT();

    for (int t = 0; t < nk; t++) {
        int buf = t & 1;
        if (t + 1 < nk) {
            int kt = (t + 1) * 32;
            uint32_t stg = sb + (buf ^ 1) * GSTG;
#pragma unroll
            for (int i = 0; i < 8; i++) {
                const __nv_bfloat16* s;
                if (sa[i] == 0)      s = Ah + (size_t)(row0 + sr[i]) * K;
                else if (sa[i] == 1) s = Al + (size_t)(row0 + sr[i]) * K;
                else if (sa[i] == 2) s = Wh + (size_t)(col0 + sr[i]) * K;
                else                 s = Wl + (size_t)(col0 + sr[i]) * K;
                cp16(stg + sa[i] * GARR + sr[i] * GPITCH + sq[i] * 16,
                     s + kt + sq[i] * 8);
            }
            CP_COMMIT();
            CP_WAIT1();
        } else {
            CP_WAIT0();
        }
        __syncthreads();

        uint32_t aAh = sb + buf * GSTG;
        uint32_t aAl = aAh + GARR;
        uint32_t aWh = aAl + GARR;
        uint32_t aWl = aWh + GARR;

#pragma unroll
        for (int s = 0; s < 2; s++) {
            int ko = s * 16 + fko;
            uint32_t afh[4][4], afl[4][4], bfh[2][4], bfl[2][4];
#pragma unroll
            for (int mt = 0; mt < 4; mt++) {
                int off = (wm * 64 + mt * 16 + frow) * GPITCH + ko * 2;
                ldsm_x4(afh[mt], aAh + off);
                ldsm_x4(afl[mt], aAl + off);
            }
#pragma unroll
            for (int bt = 0; bt < 2; bt++) {
                int off = (wn * 32 + bt * 16 + frow) * GPITCH + ko * 2;
                ldsm_x4(bfh[bt], aWh + off);
                ldsm_x4(bfl[bt], aWl + off);
            }
#pragma unroll
            for (int mt = 0; mt < 4; mt++)
#pragma unroll
                for (int bt = 0; bt < 2; bt++)
#pragma unroll
                    for (int h = 0; h < 2; h++) {
                        int nt = bt * 2 + h;
                        mma_bf16(acc[mt][nt], afh[mt], bfh[bt][h], bfh[bt][h + 2]);
                        mma_bf16(acc[mt][nt], afh[mt], bfl[bt][h], bfl[bt][h + 2]);
                        mma_bf16(acc[mt][nt], afl[mt], bfh[bt][h], bfh[bt][h + 2]);
                    }
        }
        __syncthreads();
    }

    int tr = lane >> 2, tc = (lane & 3) * 2;
#pragma unroll
    for (int mt = 0; mt < 4; mt++) {
#pragma unroll
        for (int nt = 0; nt < 4; nt++) {
            int col = col0 + wn * 32 + nt * 8 + tc;
            float2 bv = *(const float2*)(bias + col);
            int r0 = row0 + wm * 64 + mt * 16 + tr;
            float o[4];
            o[0] = acc[mt][nt][0] + bv.x;
            o[1] = acc[mt][nt][1] + bv.y;
            o[2] = acc[mt][nt][2] + bv.x;
            o[3] = acc[mt][nt][3] + bv.y;
            if (mode == 0) {
                *(float2*)(Cf + (size_t)r0 * N + col) = make_float2(o[0], o[1]);
                *(float2*)(Cf + (size_t)(r0 + 8) * N + col) = make_float2(o[2], o[3]);
            } else {
#pragma unroll
                for (int i = 0; i < 4; i++) o[i] = fmaxf(o[i], 0.f);
                __nv_bfloat16 h0 = __float2bfloat16(o[0]);
                __nv_bfloat16 h1 = __float2bfloat16(o[1]);
                __nv_bfloat16 h2 = __float2bfloat16(o[2]);
                __nv_bfloat16 h3 = __float2bfloat16(o[3]);
                __nv_bfloat162 a, b;
                a.x = h0; a.y = h1; b.x = h2; b.y = h3;
                *(__nv_bfloat162*)(Ch + (size_t)r0 * N + col) = a;
                *(__nv_bfloat162*)(Ch + (size_t)(r0 + 8) * N + col) = b;
                uint32_t l01 = pack_bf16x2(o[0] - __bfloat162float(h0),
                                           o[1] - __bfloat162float(h1));
                uint32_t l23 = pack_bf16x2(o[2] - __bfloat162float(h2),
                                           o[3] - __bfloat162float(h3));
                *(uint32_t*)(Cl + (size_t)r0 * N + col) = l01;
                *(uint32_t*)(Cl + (size_t)(r0 + 8) * N + col) = l23;
            }
        }
    }
}

// ===========================================================================
// Flash attention via mma.sync bf16x3 with cp.async pipelined K/V.
// Inputs: head-major bf16 hi/lo Q,K,V [bh][s][64]. Outputs bf16 hi/lo attn.
// pitch 72 bf16 = 144B (9x16B aligned, ldsm conflict-free).
// smem: Q 2x128x144 = 36864; KV 2 stages x 4 x 64x144 = 73728; total 110592.
// ===========================================================================
#define APITCH 144
#define AQH 0
#define AQL 18432
#define AKV0 36864
#define AARR 9216
#define ASTG 36864
#define ATT_SMEM 110592

__global__ __launch_bounds__(256) void attn_mma(
    const __nv_bfloat16* __restrict__ Qh, const __nv_bfloat16* __restrict__ Ql,
    const __nv_bfloat16* __restrict__ Kh, const __nv_bfloat16* __restrict__ Kl,
    const __nv_bfloat16* __restrict__ Vh, const __nv_bfloat16* __restrict__ Vl,
    __nv_bfloat16* __restrict__ ath, __nv_bfloat16* __restrict__ atl)
{
    extern __shared__ char dsm[];
    uint32_t sb = smem_u32(dsm);

    int tid = threadIdx.x;
    int lane = tid & 31, warp = tid >> 5;
    int bh = blockIdx.y;
    int b = bh >> 4, hh = bh & 15;
    int q0 = blockIdx.x * 128;

    size_t hbase = (size_t)bh * Sq * 64;

    // stage Q (2048 chunks, 8/thread)
#pragma unroll
    for (int i = 0; i < 8; i++) {
        int f = tid + i * 256;
        int a = f >> 10, rem = f & 1023, r = rem >> 3, q = rem & 7;
        const __nv_bfloat16* s = (a ? Ql : Qh) + hbase + (size_t)(q0 + r) * 64 + q * 8;
        cp16(sb + (a ? AQL : AQH) + r * APITCH + q * 16, s);
    }
    // stage KV tile 0
#pragma unroll
    for (int i = 0; i < 8; i++) {
        int f = tid + i * 256;
        int a = f >> 9, rem = f & 511, r = rem >> 3, q = rem & 7;
        const __nv_bfloat16* s;
        if (a == 0)      s = Kh;
        else if (a == 1) s = Kl;
        else if (a == 2) s = Vh;
        else             s = Vl;
        cp16(sb + AKV0 + a * AARR + r * APITCH + q * 16,
             s + hbase + (size_t)r * 64 + q * 8);
    }
    CP_COMMIT();

    int frow = lane & 15;
    int fko  = (lane >> 4) << 3;

    uint32_t aQh[4][4], aQl[4][4];
    float m0 = -1e30f, m1 = -1e30f, l0 = 0.f, l1 = 0.f;
    float oacc[8][4];
#pragma unroll
    for (int j = 0; j < 8; j++)
#pragma unroll
        for (int f = 0; f < 4; f++) oacc[j][f] = 0.f;

    const int NT = Sq / 64;
    for (int t = 0; t < NT; t++) {
        int buf = t & 1;
        if (t + 1 < NT) {
            int kt = (t + 1) * 64;
            uint32_t stg = sb + AKV0 + (buf ^ 1) * ASTG;
#pragma unroll
            for (int i = 0; i < 8; i++) {
                int f = tid + i * 256;
                int a = f >> 9, rem = f & 511, r = rem >> 3, q = rem & 7;
                const __nv_bfloat16* s;
                if (a == 0)      s = Kh;
                else if (a == 1) s = Kl;
                else if (a == 2) s = Vh;
                else             s = Vl;
                cp16(stg + a * AARR + r * APITCH + q * 16,
                     s + hbase + (size_t)(kt + r) * 64 + q * 8);
            }
            CP_COMMIT();
            CP_WAIT1();
        } else {
            CP_WAIT0();
        }
        __syncthreads();

        if (t == 0) {
#pragma unroll
            for (int c = 0; c < 4; c++) {
                int off = (warp * 16 + frow) * APITCH + (c * 16 + fko) * 2;
                ldsm_x4(aQh[c], sb + AQH + off);
                ldsm_x4(aQl[c], sb + AQL + off);
            }
        }

        uint32_t aKhB = sb + AKV0 + buf * ASTG;
        uint32_t aKlB = aKhB + AARR;
        uint32_t aVhB = aKlB + AARR;
        uint32_t aVlB = aVhB + AARR;

        // ---- S = Q @ K^T ----
        float sacc[8][4];
#pragma unroll
        for (int j = 0; j < 8; j++)
#pragma unroll
            for (int f = 0; f < 4; f++) sacc[j][f] = 0.f;

#pragma unroll
        for (int kd = 0; kd < 4; kd++) {
#pragma unroll
            for (int bt = 0; bt < 4; bt++) {
                uint32_t kh[4], kl[4];
                int off = (bt * 16 + frow) * APITCH + (kd * 16 + fko) * 2;
                ldsm_x4(kh, aKhB + off);
                ldsm_x4(kl, aKlB + off);
#pragma unroll
                for (int h = 0; h < 2; h++) {
                    int nt = bt * 2 + h;
                    mma_bf16(sacc[nt], aQh[kd], kh[h], kh[h + 2]);
                    mma_bf16(sacc[nt], aQh[kd], kl[h], kl[h + 2]);
                    mma_bf16(sacc[nt], aQl[kd], kh[h], kh[h + 2]);
                }
            }
        }

        // ---- online softmax ----
        float rmax0 = -1e30f, rmax1 = -1e30f;
#pragma unroll
        for (int j = 0; j < 8; j++) {
            rmax0 = fmaxf(rmax0, fmaxf(sacc[j][0], sacc[j][1]));
            rmax1 = fmaxf(rmax1, fmaxf(sacc[j][2], sacc[j][3]));
        }
        rmax0 = fmaxf(rmax0, __shfl_xor_sync(0xffffffffu, rmax0, 1));
        rmax0 = fmaxf(rmax0, __shfl_xor_sync(0xffffffffu, rmax0, 2));
        rmax1 = fmaxf(rmax1, __shfl_xor_sync(0xffffffffu, rmax1, 1));
        rmax1 = fmaxf(rmax1, __shfl_xor_sync(0xffffffffu, rmax1, 2));

        float mn0 = fmaxf(m0, 0.125f * rmax0);
        float mn1 = fmaxf(m1, 0.125f * rmax1);
        float corr0 = __expf(m0 - mn0);
        float corr1 = __expf(m1 - mn1);
        m0 = mn0; m1 = mn1;

        uint32_t pah[4][4], pal[4][4];
        float ps0 = 0.f, ps1 = 0.f;
#pragma unroll
        for (int c = 0; c < 4; c++) {
#pragma unroll
            for (int u = 0; u < 2; u++) {
                int j = 2 * c + u;
                float p0 = __expf(0.125f * sacc[j][0] - mn0);
                float p1 = __expf(0.125f * sacc[j][1] - mn0);
                float p2 = __expf(0.125f * sacc[j][2] - mn1);
                float p3 = __expf(0.125f * sacc[j][3] - mn1);
                ps0 += p0 + p1;
                ps1 += p2 + p3;
                __nv_bfloat16 h0 = __float2bfloat16(p0);
                __nv_bfloat16 h1 = __float2bfloat16(p1);
                __nv_bfloat16 h2 = __float2bfloat16(p2);
                __nv_bfloat16 h3 = __float2bfloat16(p3);
                __nv_bfloat162 ph01, ph23;
                ph01.x = h0; ph01.y = h1;
                ph23.x = h2; ph23.y = h3;
                pah[c][2 * u + 0] = *(unsigned*)&ph01;
                pah[c][2 * u + 1] = *(unsigned*)&ph23;
                pal[c][2 * u + 0] = pack_bf16x2(p0 - __bfloat162float(h0),
                                                p1 - __bfloat162float(h1));
                pal[c][2 * u + 1] = pack_bf16x2(p2 - __bfloat162float(h2),
                                                p3 - __bfloat162float(h3));
            }
        }
        ps0 += __shfl_xor_sync(0xffffffffu, ps0, 1);
        ps0 += __shfl_xor_sync(0xffffffffu, ps0, 2);
        ps1 += __shfl_xor_sync(0xffffffffu, ps1, 1);
        ps1 += __shfl_xor_sync(0xffffffffu, ps1, 2);
        l0 = l0 * corr0 + ps0;
        l1 = l1 * corr1 + ps1;

#pragma unroll
        for (int j = 0; j < 8; j++) {
            oacc[j][0] *= corr0; oacc[j][1] *= corr0;
            oacc[j][2] *= corr1; oacc[j][3] *= corr1;
        }

        // ---- O += P @ V ----
#pragma unroll
        for (int c = 0; c < 4; c++) {
#pragma unroll
            for (int g = 0; g < 4; g++) {
                uint32_t vh[4], vl[4];
                int off = (c * 16 + frow) * APITCH + (g * 16 + fko) * 2;
                ldsm_x4_t(vh, aVhB + off);
                ldsm_x4_t(vl, aVlB + off);
#pragma unroll
                for (int h2 = 0; h2 < 2; h2++) {
                    int j = g * 2 + h2;
                    mma_bf16(oacc[j], pah[c], vh[2 * h2], vh[2 * h2 + 1]);
                    mma_bf16(oacc[j], pah[c], vl[2 * h2], vl[2 * h2 + 1]);
                    mma_bf16(oacc[j], pal[c], vh[2 * h2], vh[2 * h2 + 1]);
                }
            }
        }
        __syncthreads();
    }

    // ---- epilogue: write bf16 hi/lo attn [B*S][Dm] ----
    float inv0 = 1.f / l0, inv1 = 1.f / l1;
    int tr = lane >> 2, tc = (lane & 3) * 2;
    int row0 = b * Sq + q0 + warp * 16 + tr;
#pragma unroll
    for (int j = 0; j < 8; j++) {
        int col = hh * 64 + j * 8 + tc;
        float o0 = oacc[j][0] * inv0, o1 = oacc[j][1] * inv0;
        float o2 = oacc[j][2] * inv1, o3 = oacc[j][3] * inv1;
        __nv_bfloat16 h0 = __float2bfloat16(o0);
        __nv_bfloat16 h1 = __float2bfloat16(o1);
        __nv_bfloat16 h2 = __float2bfloat16(o2);
        __nv_bfloat16 h3 = __float2bfloat16(o3);
        __nv_bfloat162 a0, a1;
        a0.x = h0; a0.y = h1; a1.x = h2; a1.y = h3;
        *(__nv_bfloat162*)(ath + (size_t)row0 * Dm + col) = a0;
        *(__nv_bfloat162*)(ath + (size_t)(row0 + 8) * Dm + col) = a1;
        *(uint32_t*)(atl + (size_t)row0 * Dm + col) =
            pack_bf16x2(o0 - __bfloat162float(h0), o1 - __bfloat162float(h1));
        *(uint32_t*)(atl + (size_t)(row0 + 8) * Dm + col) =
            pack_bf16x2(o2 - __bfloat162float(h2), o3 - __bfloat162float(h3));
    }
}

// ===========================================================================
// Fused residual add + LayerNorm (+ optional bf16 hi/lo output)
// ===========================================================================
__device__ __forceinline__ float block_allreduce(float v, float* sred)
{
#pragma unroll
    for (int o = 16; o; o >>= 1) v += __shfl_xor_sync(0xffffffffu, v, o);
    int w = threadIdx.x >> 5;
    if ((threadIdx.x & 31) == 0) sred[w] = v;
    __syncthreads();
    float t = (threadIdx.x < 8) ? sred[threadIdx.x] : 0.f;
    if (threadIdx.x < 32) {
#pragma unroll
        for (int o = 4; o; o >>= 1) t += __shfl_xor_sync(0xffffffffu, t, o);
        if (threadIdx.x == 0) sred[0] = t;
    }
    __syncthreads();
    float r = sred[0];
    __syncthreads();
    return r;
}

__global__ __launch_bounds__(256) void add_ln_kernel(
    const float* __restrict__ x, const float* __restrict__ y,
    const float* __restrict__ g, const float* __restrict__ bta,
    float* __restrict__ out, __nv_bfloat16* __restrict__ oh,
    __nv_bfloat16* __restrict__ ol)
{
    __shared__ float sred[8];
    int row = blockIdx.x;
    int tid = threadIdx.x;
    const float* xr = x + (size_t)row * Dm;
    const float* yr = y + (size_t)row * Dm;

    float4 xv = *(const float4*)(xr + tid * 4);
    float4 yv = *(const float4*)(yr + tid * 4);
    float v[4] = {xv.x + yv.x, xv.y + yv.y, xv.z + yv.z, xv.w + yv.w};

    float sum = v[0] + v[1] + v[2] + v[3];
    sum = block_allreduce(sum, sred);
    float mean = sum * (1.f / (float)Dm);

    float sq = 0.f;
#pragma unroll
    for (int i = 0; i < 4; i++) {
        float d = v[i] - mean;
        sq += d * d;
    }
    sq = block_allreduce(sq, sred);
    float inv = rsqrtf(sq * (1.f / (float)Dm) + 1e-5f);

    float4 gv = *(const float4*)(g + tid * 4);
    float4 bv = *(const float4*)(bta + tid * 4);
    float o[4];
    o[0] = (v[0] - mean) * inv * gv.x + bv.x;
    o[1] = (v[1] - mean) * inv * gv.y + bv.y;
    o[2] = (v[2] - mean) * inv * gv.z + bv.z;
    o[3] = (v[3] - mean) * inv * gv.w + bv.w;
    *(float4*)(out + (size_t)row * Dm + tid * 4) =
        make_float4(o[0], o[1], o[2], o[3]);

    if (oh) {
        __nv_bfloat16 h0 = __float2bfloat16(o[0]);
        __nv_bfloat16 h1 = __float2bfloat16(o[1]);
        __nv_bfloat16 h2 = __float2bfloat16(o[2]);
        __nv_bfloat16 h3 = __float2bfloat16(o[3]);
        __nv_bfloat162 a, b;
        a.x = h0; a.y = h1; b.x = h2; b.y = h3;
        uint2 hv; hv.x = *(uint32_t*)&a; hv.y = *(uint32_t*)&b;
        uint2 lv;
        lv.x = pack_bf16x2(o[0] - __bfloat162float(h0), o[1] - __bfloat162float(h1));
        lv.y = pack_bf16x2(o[2] - __bfloat162float(h2), o[3] - __bfloat162float(h3));
        *(uint2*)(oh + (size_t)row * Dm + tid * 4) = hv;
        *(uint2*)(ol + (size_t)row * Dm + tid * 4) = lv;
    }
}

// ===========================================================================
extern "C" void kernel_launch(void* const* d_in, const int* in_sizes, int n_in,
                              void* d_out, int out_size)
{
    const float* x     = (const float*)d_in[0];
    const float* in_w  = (const float*)d_in[1];
    const float* in_b  = (const float*)d_in[2];
    const float* out_w = (const float*)d_in[3];
    const float* out_b = (const float*)d_in[4];
    const float* w1    = (const float*)d_in[5];
    const float* b1    = (const float*)d_in[6];
    const float* w2    = (const float*)d_in[7];
    const float* b2    = (const float*)d_in[8];
    const float* ln1g  = (const float*)d_in[9];
    const float* ln1b  = (const float*)d_in[10];
    const float* ln2g  = (const float*)d_in[11];
    const float* ln2b  = (const float*)d_in[12];
    float* out = (float*)d_out;

    float *qkv, *tmp, *hbuf;
    __nv_bfloat16 *xh, *xl, *wbh, *wbl, *qh, *ql, *kh, *kl, *vh, *vl;
    __nv_bfloat16 *ath, *atl, *hh, *hl, *ffh, *ffl;
    cudaGetSymbolAddress((void**)&qkv, g_qkv);
    cudaGetSymbolAddress((void**)&tmp, g_tmp);
    cudaGetSymbolAddress((void**)&hbuf, g_h);
    cudaGetSymbolAddress((void**)&xh, g_xh);
    cudaGetSymbolAddress((void**)&xl, g_xl);
    cudaGetSymbolAddress((void**)&wbh, g_wbh);
    cudaGetSymbolAddress((void**)&wbl, g_wbl);
    cudaGetSymbolAddress((void**)&qh, g_qh);
    cudaGetSymbolAddress((void**)&ql, g_ql);
    cudaGetSymbolAddress((void**)&kh, g_kh);
    cudaGetSymbolAddress((void**)&kl, g_kl);
    cudaGetSymbolAddress((void**)&vh, g_vh);
    cudaGetSymbolAddress((void**)&vl, g_vl);
    cudaGetSymbolAddress((void**)&ath, g_ath);
    cudaGetSymbolAddress((void**)&atl, g_atl);
    cudaGetSymbolAddress((void**)&hh, g_hh);
    cudaGetSymbolAddress((void**)&hl, g_hl);
    cudaGetSymbolAddress((void**)&ffh, g_ffh);
    cudaGetSymbolAddress((void**)&ffl, g_ffl);

    cudaFuncSetAttribute(gemm_bf, cudaFuncAttributeMaxDynamicSharedMemorySize,
                         2 * GSTG);
    cudaFuncSetAttribute(attn_mma, cudaFuncAttributeMaxDynamicSharedMemorySize,
                         ATT_SMEM);

    dim3 tb(256);

    rope_table_kernel<<<(Sq * 32 + 255) / 256, tb>>>();
    // conversions (x + 4 weights)
    cvt_kernel<<<(Mrows * Dm / 4 + 255) / 256, tb>>>(x, xh, xl, Mrows * Dm / 4);
    cvt_kernel<<<(3 * Dm * Dm / 4 + 255) / 256, tb>>>(in_w, wbh + OFF_INW, wbl + OFF_INW, 3 * Dm * Dm / 4);
    cvt_kernel<<<(Dm * Dm / 4 + 255) / 256, tb>>>(out_w, wbh + OFF_OUTW, wbl + OFF_OUTW, Dm * Dm / 4);
    cvt_kernel<<<(Ff * Dm / 4 + 255) / 256, tb>>>(w1, wbh + OFF_W1, wbl + OFF_W1, Ff * Dm / 4);
    cvt_kernel<<<(Dm * Ff / 4 + 255) / 256, tb>>>(w2, wbh + OFF_W2, wbl + OFF_W2, Dm * Ff / 4);

    // QKV projection -> fp32
    gemm_bf<<<dim3(3072 / 128, Mrows / 128), tb, 2 * GSTG>>>(
        xh, xl, wbh + OFF_INW, wbl + OFF_INW, in_b, qkv, nullptr, nullptr,
        3 * Dm, Dm, 0);
    // RoPE + head-major bf16 split
    rope_bf_kernel<<<(Mrows * Hh * 8 + 255) / 256, tb>>>(qkv);
    // Attention -> bf16 hi/lo
    attn_mma<<<dim3(Sq / 128, Bq * Hh), tb, ATT_SMEM>>>(
        qh, ql, kh, kl, vh, vl, ath, atl);
    // Output projection -> fp32
    gemm_bf<<<dim3(Dm / 128, Mrows / 128), tb, 2 * GSTG>>>(
        ath, atl, wbh + OFF_OUTW, wbl + OFF_OUTW, out_b, tmp, nullptr, nullptr,
        Dm, Dm, 0);
    // LN1 -> fp32 h + bf16 hi/lo
    add_ln_kernel<<<Mrows, tb>>>(x, tmp, ln1g, ln1b, hbuf, hh, hl);
    // FF1 + ReLU -> bf16 hi/lo
    gemm_bf<<<dim3(Ff / 128, Mrows / 128), tb, 2 * GSTG>>>(
        hh, hl, wbh + OFF_W1, wbl + OFF_W1, b1, nullptr, ffh, ffl,
        Ff, Dm, 1);
    // FF2 -> fp32
    gemm_bf<<<dim3(Dm / 128, Mrows / 128), tb, 2 * GSTG>>>(
        ffh, ffl, wbh + OFF_W2, wbl + OFF_W2, b2, tmp, nullptr, nullptr,
        Dm, Ff, 0);
    // LN2 -> out
    add_ln_kernel<<<Mrows, tb>>>(hbuf, tmp, ln2g, ln2b, out, nullptr, nullptr);
}

// round 7
// speedup vs baseline: 3.1532x; 1.2353x over previous
#include <cuda_runtime.h>
#include <cuda_bf16.h>
#include <cuda_fp16.h>
#include <math.h>
#include <stdint.h>

// Problem constants
#define Bq 2
#define Sq 2048
#define Dm 1024
#define Ff 4096
#define Hh 16
#define Dhd 64
#define Mrows 4096  // B*S

// ---------------------------------------------------------------------------
// Scratch (device globals)
// ---------------------------------------------------------------------------
__device__ float g_qkv[(size_t)Mrows * 3 * Dm];
__device__ float g_tmp[(size_t)Mrows * Dm];
__device__ float g_h[(size_t)Mrows * Dm];
__device__ float g_cos[Sq * 32];
__device__ float g_sin[Sq * 32];

__device__ __half g_xh[(size_t)Mrows * Dm], g_xl[(size_t)Mrows * Dm];
__device__ __half g_wb[12582912];
// weight offsets: in_proj 0 (3145728), out_w 3145728, w1 4194304, w2 8388608
#define OFF_INW 0
#define OFF_OUTW 3145728
#define OFF_W1 4194304
#define OFF_W2 8388608
__device__ __nv_bfloat16 g_qh[(size_t)Bq * Hh * Sq * 64], g_ql[(size_t)Bq * Hh * Sq * 64];
__device__ __nv_bfloat16 g_kh[(size_t)Bq * Hh * Sq * 64], g_kl[(size_t)Bq * Hh * Sq * 64];
__device__ __nv_bfloat16 g_vh[(size_t)Bq * Hh * Sq * 64], g_vl[(size_t)Bq * Hh * Sq * 64];
__device__ __half g_ath[(size_t)Mrows * Dm], g_atl[(size_t)Mrows * Dm];
__device__ __half g_hh[(size_t)Mrows * Dm], g_hl[(size_t)Mrows * Dm];
__device__ __half g_ffh[(size_t)Mrows * Ff], g_ffl[(size_t)Mrows * Ff];

__device__ __forceinline__ uint32_t smem_u32(const void* p) {
    uint32_t a;
    asm("{ .reg .u64 t; cvta.to.shared.u64 t, %1; cvt.u32.u64 %0, t; }"
        : "=r"(a) : "l"(p));
    return a;
}
__device__ __forceinline__ void cp16(uint32_t dst, const void* src) {
    asm volatile("cp.async.cg.shared.global [%0], [%1], 16;"
                 :: "r"(dst), "l"(src));
}
#define CP_COMMIT() asm volatile("cp.async.commit_group;" ::: "memory")
#define CP_WAIT1()  asm volatile("cp.async.wait_group 1;" ::: "memory")
#define CP_WAIT0()  asm volatile("cp.async.wait_group 0;" ::: "memory")

__device__ __forceinline__ void ldsm_x4(uint32_t* r, uint32_t addr)
{
    asm volatile("ldmatrix.sync.aligned.m8n8.x4.shared.b16 {%0,%1,%2,%3}, [%4];"
                 : "=r"(r[0]), "=r"(r[1]), "=r"(r[2]), "=r"(r[3]) : "r"(addr));
}
__device__ __forceinline__ void ldsm_x4_t(uint32_t* r, uint32_t addr)
{
    asm volatile("ldmatrix.sync.aligned.m8n8.x4.trans.shared.b16 {%0,%1,%2,%3}, [%4];"
                 : "=r"(r[0]), "=r"(r[1]), "=r"(r[2]), "=r"(r[3]) : "r"(addr));
}
__device__ __forceinline__ void mma_bf16(float* c, const uint32_t* a,
                                         uint32_t b0, uint32_t b1)
{
    asm volatile(
        "mma.sync.aligned.m16n8k16.row.col.f32.bf16.bf16.f32 "
        "{%0,%1,%2,%3}, {%4,%5,%6,%7}, {%8,%9}, {%0,%1,%2,%3};"
        : "+f"(c[0]), "+f"(c[1]), "+f"(c[2]), "+f"(c[3])
        : "r"(a[0]), "r"(a[1]), "r"(a[2]), "r"(a[3]), "r"(b0), "r"(b1));
}
__device__ __forceinline__ void mma_f16(float* c, const uint32_t* a,
                                        uint32_t b0, uint32_t b1)
{
    asm volatile(
        "mma.sync.aligned.m16n8k16.row.col.f32.f16.f16.f32 "
        "{%0,%1,%2,%3}, {%4,%5,%6,%7}, {%8,%9}, {%0,%1,%2,%3};"
        : "+f"(c[0]), "+f"(c[1]), "+f"(c[2]), "+f"(c[3])
        : "r"(a[0]), "r"(a[1]), "r"(a[2]), "r"(a[3]), "r"(b0), "r"(b1));
}
__device__ __forceinline__ uint32_t pack_bf16x2(float lo, float hi)
{
    uint32_t r;
    asm("cvt.rn.bf16x2.f32 %0, %1, %2;" : "=r"(r) : "f"(hi), "f"(lo));
    return r;
}
__device__ __forceinline__ uint32_t pack_f16x2(float lo, float hi)
{
    uint32_t r;
    asm("cvt.rn.f16x2.f32 %0, %1, %2;" : "=r"(r) : "f"(hi), "f"(lo));
    return r;
}
// split 4 fp32 into fp16 hi (uint2) and fp16 lo (uint2)
__device__ __forceinline__ void split_f16x4(const float* o, uint2& hv, uint2& lv)
{
    __half h0 = __float2half_rn(o[0]);
    __half h1 = __float2half_rn(o[1]);
    __half h2 = __float2half_rn(o[2]);
    __half h3 = __float2half_rn(o[3]);
    __half2 a, b;
    a.x = h0; a.y = h1; b.x = h2; b.y = h3;
    hv.x = *(uint32_t*)&a; hv.y = *(uint32_t*)&b;
    lv.x = pack_f16x2(o[0] - __half2float(h0), o[1] - __half2float(h1));
    lv.y = pack_f16x2(o[2] - __half2float(h2), o[3] - __half2float(h3));
}

// ===========================================================================
// RoPE table kernel
// ===========================================================================
__global__ __launch_bounds__(256) void rope_table_kernel()
{
    int idx = blockIdx.x * 256 + threadIdx.x;
    if (idx >= Sq * 32) return;
    int s = idx >> 5;
    int i = idx & 31;
    double invd = exp(-(double)i * (9.210340371976184 / 32.0));
    float invf = (float)invd;
    float angf = (float)s * invf;
    double a = (double)angf;
    g_cos[idx] = (float)cos(a);
    g_sin[idx] = (float)sin(a);
}

// ===========================================================================
// Converters
// ===========================================================================
__global__ __launch_bounds__(256) void cvt_pair_f16(
    const float* __restrict__ src, __half* __restrict__ dh,
    __half* __restrict__ dl, int n4)
{
    int idx = blockIdx.x * 256 + threadIdx.x;
    if (idx >= n4) return;
    float4 v = *(const float4*)(src + (size_t)idx * 4);
    float o[4] = {v.x, v.y, v.z, v.w};
    uint2 hv, lv;
    split_f16x4(o, hv, lv);
    *(uint2*)(dh + (size_t)idx * 4) = hv;
    *(uint2*)(dl + (size_t)idx * 4) = lv;
}

__global__ __launch_bounds__(256) void cvt_f16(
    const float* __restrict__ src, __half* __restrict__ d, int n4)
{
    int idx = blockIdx.x * 256 + threadIdx.x;
    if (idx >= n4) return;
    float4 v = *(const float4*)(src + (size_t)idx * 4);
    uint2 hv;
    hv.x = pack_f16x2(v.x, v.y);
    hv.y = pack_f16x2(v.z, v.w);
    *(uint2*)(d + (size_t)idx * 4) = hv;
}

// ===========================================================================
// RoPE + split: qkv fp32 -> head-major bf16 hi/lo Q,K,V arrays.
// ===========================================================================
__global__ __launch_bounds__(256) void rope_bf_kernel(const float* __restrict__ qkv)
{
    int idx = blockIdx.x * 256 + threadIdx.x;
    if (idx >= Mrows * Hh * 8) return;
    int e0 = (idx & 7) * 8;
    int h  = (idx >> 3) & 15;
    int m  = idx >> 7;
    int s  = m & (Sq - 1);
    int b  = m >> 11;
    int bh = b * Hh + h;
    int i0 = e0 >> 1;

    const float* rp = qkv + (size_t)m * 3072 + h * 64 + e0;
    float q[8], k[8], v[8];
    *(float4*)(q)     = *(const float4*)(rp);
    *(float4*)(q + 4) = *(const float4*)(rp + 4);
    *(float4*)(k)     = *(const float4*)(rp + 1024);
    *(float4*)(k + 4) = *(const float4*)(rp + 1028);
    *(float4*)(v)     = *(const float4*)(rp + 2048);
    *(float4*)(v + 4) = *(const float4*)(rp + 2052);

    float qr[8], kr[8];
#pragma unroll
    for (int p = 0; p < 4; p++) {
        float c  = g_cos[s * 32 + i0 + p];
        float sn = g_sin[s * 32 + i0 + p];
        qr[2 * p]     = q[2 * p] * c - q[2 * p + 1] * sn;
        qr[2 * p + 1] = q[2 * p] * sn + q[2 * p + 1] * c;
        kr[2 * p]     = k[2 * p] * c - k[2 * p + 1] * sn;
        kr[2 * p + 1] = k[2 * p] * sn + k[2 * p + 1] * c;
    }

    size_t d = ((size_t)bh * Sq + s) * 64 + e0;
#pragma unroll
    for (int grp = 0; grp < 3; grp++) {
        const float* src = (grp == 0) ? qr : (grp == 1) ? kr : v;
        __nv_bfloat16* dsth = (grp == 0) ? g_qh : (grp == 1) ? g_kh : g_vh;
        __nv_bfloat16* dstl = (grp == 0) ? g_ql : (grp == 1) ? g_kl : g_vl;
        __nv_bfloat16 hb[8];
#pragma unroll
        for (int i = 0; i < 8; i++) hb[i] = __float2bfloat16(src[i]);
        __nv_bfloat162 t0, t1, t2, t3;
        t0.x = hb[0]; t0.y = hb[1]; t1.x = hb[2]; t1.y = hb[3];
        t2.x = hb[4]; t2.y = hb[5]; t3.x = hb[6]; t3.y = hb[7];
        uint2 hv, hv2, lv, lv2;
        hv.x = *(uint32_t*)&t0; hv.y = *(uint32_t*)&t1;
        hv2.x = *(uint32_t*)&t2; hv2.y = *(uint32_t*)&t3;
        lv.x = pack_bf16x2(src[0] - __bfloat162float(hb[0]), src[1] - __bfloat162float(hb[1]));
        lv.y = pack_bf16x2(src[2] - __bfloat162float(hb[2]), src[3] - __bfloat162float(hb[3]));
        lv2.x = pack_bf16x2(src[4] - __bfloat162float(hb[4]), src[5] - __bfloat162float(hb[5]));
        lv2.y = pack_bf16x2(src[6] - __bfloat162float(hb[6]), src[7] - __bfloat162float(hb[7]));
        *(uint2*)(dsth + d) = hv; *(uint2*)(dsth + d + 4) = hv2;
        *(uint2*)(dstl + d) = lv; *(uint2*)(dstl + d + 4) = lv2;
    }
}

// ===========================================================================
// fp16 2-pass GEMM: C = (Ah+Al) @ W^T + bias.  A hi/lo fp16, W single fp16.
// CTA 128x128, BK=32, 8 warps. pitch 80B. cp.async double buffered.
// smem: 2 stages x 3 arrays x 10240B = 61440 bytes.
// mode 0: fp32 out; mode 1: relu + fp16 hi/lo out.
// ===========================================================================
#define GPITCH 80
#define GARR 10240
#define GSTG 30720

__global__ __launch_bounds__(256) void gemm_f16(
    const __half* __restrict__ Ah, const __half* __restrict__ Al,
    const __half* __restrict__ W, const float* __restrict__ bias,
    float* __restrict__ Cf, __half* __restrict__ Ch, __half* __restrict__ Cl,
    int N, int K, int mode)
{
    extern __shared__ char dsm[];
    uint32_t sb = smem_u32(dsm);

    int tid = threadIdx.x;
    int lane = tid & 31, warp = tid >> 5;
    int wm = warp & 1;
    int wn = warp >> 1;
    int row0 = blockIdx.y * 128;
    int col0 = blockIdx.x * 128;

    float acc[4][4][4];
#pragma unroll
    for (int i = 0; i < 4; i++)
#pragma unroll
        for (int j = 0; j < 4; j++)
#pragma unroll
            for (int f = 0; f < 4; f++) acc[i][j][f] = 0.f;

    int frow = lane & 15;
    int fko  = (lane >> 4) << 3;

    // staging: 1536 16B-chunks per stage, 6 per thread
    int sa[6], sr[6], sq[6];
#pragma unroll
    for (int i = 0; i < 6; i++) {
        int f = tid + i * 256;
        sa[i] = f >> 9;
        int rem = f & 511;
        sr[i] = rem >> 2; sq[i] = rem & 3;
    }

    int nk = K >> 5;

#pragma unroll
    for (int i = 0; i < 6; i++) {
        const __half* s;
        if (sa[i] == 0)      s = Ah + (size_t)(row0 + sr[i]) * K;
        else if (sa[i] == 1) s = Al + (size_t)(row0 + sr[i]) * K;
        else                 s = W + (size_t)(col0 + sr[i]) * K;
        cp16(sb + sa[i] * GARR + sr[i] * GPITCH + sq[i] * 16, s + sq[i] * 8);
    }
    CP_COMMIT();

    for (int t = 0; t < nk; t++) {
        int buf = t & 1;
        if (t + 1 < nk) {
            int kt = (t + 1) * 32;
            uint32_t stg = sb + (buf ^ 1) * GSTG;
#pragma unroll
            for (int i = 0; i < 6; i++) {
                const __half* s;
                if (sa[i] == 0)      s = Ah + (size_t)(row0 + sr[i]) * K;
                else if (sa[i] == 1) s = Al + (size_t)(row0 + sr[i]) * K;
                else                 s = W + (size_t)(col0 + sr[i]) * K;
                cp16(stg + sa[i] * GARR + sr[i] * GPITCH + sq[i] * 16,
                     s + kt + sq[i] * 8);
            }
            CP_COMMIT();
            CP_WAIT1();
        } else {
            CP_WAIT0();
        }
        __syncthreads();

        uint32_t aAh = sb + buf * GSTG;
        uint32_t aAl = aAh + GARR;
        uint32_t aW  = aAl + GARR;

#pragma unroll
        for (int s = 0; s < 2; s++) {
            int ko = s * 16 + fko;
            uint32_t afh[4][4], afl[4][4], bf[2][4];
#pragma unroll
            for (int mt = 0; mt < 4; mt++) {
                int off = (wm * 64 + mt * 16 + frow) * GPITCH + ko * 2;
                ldsm_x4(afh[mt], aAh + off);
                ldsm_x4(afl[mt], aAl + off);
            }
#pragma unroll
            for (int bt = 0; bt < 2; bt++) {
                int off = (wn * 32 + bt * 16 + frow) * GPITCH + ko * 2;
                ldsm_x4(bf[bt], aW + off);
            }
#pragma unroll
            for (int mt = 0; mt < 4; mt++)
#pragma unroll
                for (int bt = 0; bt < 2; bt++)
#pragma unroll
                    for (int h = 0; h < 2; h++) {
                        int nt = bt * 2 + h;
                        mma_f16(acc[mt][nt], afh[mt], bf[bt][h], bf[bt][h + 2]);
                        mma_f16(acc[mt][nt], afl[mt], bf[bt][h], bf[bt][h + 2]);
                    }
        }
        __syncthreads();
    }

    int tr = lane >> 2, tc = (lane & 3) * 2;
#pragma unroll
    for (int mt = 0; mt < 4; mt++) {
#pragma unroll
        for (int nt = 0; nt < 4; nt++) {
            int col = col0 + wn * 32 + nt * 8 + tc;
            float2 bv = *(const float2*)(bias + col);
            int r0 = row0 + wm * 64 + mt * 16 + tr;
            float o[4];
            o[0] = acc[mt][nt][0] + bv.x;
            o[1] = acc[mt][nt][1] + bv.y;
            o[2] = acc[mt][nt][2] + bv.x;
            o[3] = acc[mt][nt][3] + bv.y;
            if (mode == 0) {
                *(float2*)(Cf + (size_t)r0 * N + col) = make_float2(o[0], o[1]);
                *(float2*)(Cf + (size_t)(r0 + 8) * N + col) = make_float2(o[2], o[3]);
            } else {
#pragma unroll
                for (int i = 0; i < 4; i++) o[i] = fmaxf(o[i], 0.f);
                __half h0 = __float2half_rn(o[0]);
                __half h1 = __float2half_rn(o[1]);
                __half h2 = __float2half_rn(o[2]);
                __half h3 = __float2half_rn(o[3]);
                __half2 a, b;
                a.x = h0; a.y = h1; b.x = h2; b.y = h3;
                *(__half2*)(Ch + (size_t)r0 * N + col) = a;
                *(__half2*)(Ch + (size_t)(r0 + 8) * N + col) = b;
                *(uint32_t*)(Cl + (size_t)r0 * N + col) =
                    pack_f16x2(o[0] - __half2float(h0), o[1] - __half2float(h1));
                *(uint32_t*)(Cl + (size_t)(r0 + 8) * N + col) =
                    pack_f16x2(o[2] - __half2float(h2), o[3] - __half2float(h3));
            }
        }
    }
}

// ===========================================================================
// Flash attention via mma.sync bf16x3 with cp.async pipelined K/V.
// Inputs bf16 hi/lo head-major; outputs fp16 hi/lo attn [B*S][Dm].
// ===========================================================================
#define APITCH 144
#define AQH 0
#define AQL 18432
#define AKV0 36864
#define AARR 9216
#define ASTG 36864
#define ATT_SMEM 110592

__global__ __launch_bounds__(256) void attn_mma(
    const __nv_bfloat16* __restrict__ Qh, const __nv_bfloat16* __restrict__ Ql,
    const __nv_bfloat16* __restrict__ Kh, const __nv_bfloat16* __restrict__ Kl,
    const __nv_bfloat16* __restrict__ Vh, const __nv_bfloat16* __restrict__ Vl,
    __half* __restrict__ ath, __half* __restrict__ atl)
{
    extern __shared__ char dsm[];
    uint32_t sb = smem_u32(dsm);

    int tid = threadIdx.x;
    int lane = tid & 31, warp = tid >> 5;
    int bh = blockIdx.y;
    int b = bh >> 4, hh = bh & 15;
    int q0 = blockIdx.x * 128;

    size_t hbase = (size_t)bh * Sq * 64;

#pragma unroll
    for (int i = 0; i < 8; i++) {
        int f = tid + i * 256;
        int a = f >> 10, rem = f & 1023, r = rem >> 3, q = rem & 7;
        const __nv_bfloat16* s = (a ? Ql : Qh) + hbase + (size_t)(q0 + r) * 64 + q * 8;
        cp16(sb + (a ? AQL : AQH) + r * APITCH + q * 16, s);
    }
#pragma unroll
    for (int i = 0; i < 8; i++) {
        int f = tid + i * 256;
        int a = f >> 9, rem = f & 511, r = rem >> 3, q = rem & 7;
        const __nv_bfloat16* s;
        if (a == 0)      s = Kh;
        else if (a == 1) s = Kl;
        else if (a == 2) s = Vh;
        else             s = Vl;
        cp16(sb + AKV0 + a * AARR + r * APITCH + q * 16,
             s + hbase + (size_t)r * 64 + q * 8);
    }
    CP_COMMIT();

    int frow = lane & 15;
    int fko  = (lane >> 4) << 3;

    uint32_t aQh[4][4], aQl[4][4];
    float m0 = -1e30f, m1 = -1e30f, l0 = 0.f, l1 = 0.f;
    float oacc[8][4];
#pragma unroll
    for (int j = 0; j < 8; j++)
#pragma unroll
        for (int f = 0; f < 4; f++) oacc[j][f] = 0.f;

    const int NT = Sq / 64;
    for (int t = 0; t < NT; t++) {
        int buf = t & 1;
        if (t + 1 < NT) {
            int kt = (t + 1) * 64;
            uint32_t stg = sb + AKV0 + (buf ^ 1) * ASTG;
#pragma unroll
            for (int i = 0; i < 8; i++) {
                int f = tid + i * 256;
                int a = f >> 9, rem = f & 511, r = rem >> 3, q = rem & 7;
                const __nv_bfloat16* s;
                if (a == 0)      s = Kh;
                else if (a == 1) s = Kl;
                else if (a == 2) s = Vh;
                else             s = Vl;
                cp16(stg + a * AARR + r * APITCH + q * 16,
                     s + hbase + (size_t)(kt + r) * 64 + q * 8);
            }
            CP_COMMIT();
            CP_WAIT1();
        } else {
            CP_WAIT0();
        }
        __syncthreads();

        if (t == 0) {
#pragma unroll
            for (int c = 0; c < 4; c++) {
                int off = (warp * 16 + frow) * APITCH + (c * 16 + fko) * 2;
                ldsm_x4(aQh[c], sb + AQH + off);
                ldsm_x4(aQl[c], sb + AQL + off);
            }
        }

        uint32_t aKhB = sb + AKV0 + buf * ASTG;
        uint32_t aKlB = aKhB + AARR;
        uint32_t aVhB = aKlB + AARR;
        uint32_t aVlB = aVhB + AARR;

        float sacc[8][4];
#pragma unroll
        for (int j = 0; j < 8; j++)
#pragma unroll
            for (int f = 0; f < 4; f++) sacc[j][f] = 0.f;

#pragma unroll
        for (int kd = 0; kd < 4; kd++) {
#pragma unroll
            for (int bt = 0; bt < 4; bt++) {
                uint32_t kh[4], kl[4];
                int off = (bt * 16 + frow) * APITCH + (kd * 16 + fko) * 2;
                ldsm_x4(kh, aKhB + off);
                ldsm_x4(kl, aKlB + off);
#pragma unroll
                for (int h = 0; h < 2; h++) {
                    int nt = bt * 2 + h;
                    mma_bf16(sacc[nt], aQh[kd], kh[h], kh[h + 2]);
                    mma_bf16(sacc[nt], aQh[kd], kl[h], kl[h + 2]);
                    mma_bf16(sacc[nt], aQl[kd], kh[h], kh[h + 2]);
                }
            }
        }

        float rmax0 = -1e30f, rmax1 = -1e30f;
#pragma unroll
        for (int j = 0; j < 8; j++) {
            rmax0 = fmaxf(rmax0, fmaxf(sacc[j][0], sacc[j][1]));
            rmax1 = fmaxf(rmax1, fmaxf(sacc[j][2], sacc[j][3]));
        }
        rmax0 = fmaxf(rmax0, __shfl_xor_sync(0xffffffffu, rmax0, 1));
        rmax0 = fmaxf(rmax0, __shfl_xor_sync(0xffffffffu, rmax0, 2));
        rmax1 = fmaxf(rmax1, __shfl_xor_sync(0xffffffffu, rmax1, 1));
        rmax1 = fmaxf(rmax1, __shfl_xor_sync(0xffffffffu, rmax1, 2));

        float mn0 = fmaxf(m0, 0.125f * rmax0);
        float mn1 = fmaxf(m1, 0.125f * rmax1);
        float corr0 = __expf(m0 - mn0);
        float corr1 = __expf(m1 - mn1);
        m0 = mn0; m1 = mn1;

        uint32_t pah[4][4], pal[4][4];
        float ps0 = 0.f, ps1 = 0.f;
#pragma unroll
        for (int c = 0; c < 4; c++) {
#pragma unroll
            for (int u = 0; u < 2; u++) {
                int j = 2 * c + u;
                float p0 = __expf(0.125f * sacc[j][0] - mn0);
                float p1 = __expf(0.125f * sacc[j][1] - mn0);
                float p2 = __expf(0.125f * sacc[j][2] - mn1);
                float p3 = __expf(0.125f * sacc[j][3] - mn1);
                ps0 += p0 + p1;
                ps1 += p2 + p3;
                __nv_bfloat16 h0 = __float2bfloat16(p0);
                __nv_bfloat16 h1 = __float2bfloat16(p1);
                __nv_bfloat16 h2 = __float2bfloat16(p2);
                __nv_bfloat16 h3 = __float2bfloat16(p3);
                __nv_bfloat162 ph01, ph23;
                ph01.x = h0; ph01.y = h1;
                ph23.x = h2; ph23.y = h3;
                pah[c][2 * u + 0] = *(unsigned*)&ph01;
                pah[c][2 * u + 1] = *(unsigned*)&ph23;
                pal[c][2 * u + 0] = pack_bf16x2(p0 - __bfloat162float(h0),
                                                p1 - __bfloat162float(h1));
                pal[c][2 * u + 1] = pack_bf16x2(p2 - __bfloat162float(h2),
                                                p3 - __bfloat162float(h3));
            }
        }
        ps0 += __shfl_xor_sync(0xffffffffu, ps0, 1);
        ps0 += __shfl_xor_sync(0xffffffffu, ps0, 2);
        ps1 += __shfl_xor_sync(0xffffffffu, ps1, 1);
        ps1 += __shfl_xor_sync(0xffffffffu, ps1, 2);
        l0 = l0 * corr0 + ps0;
        l1 = l1 * corr1 + ps1;

#pragma unroll
        for (int j = 0; j < 8; j++) {
            oacc[j][0] *= corr0; oacc[j][1] *= corr0;
            oacc[j][2] *= corr1; oacc[j][3] *= corr1;
        }

#pragma unroll
        for (int c = 0; c < 4; c++) {
#pragma unroll
            for (int g = 0; g < 4; g++) {
                uint32_t vh[4], vl[4];
                int off = (c * 16 + frow) * APITCH + (g * 16 + fko) * 2;
                ldsm_x4_t(vh, aVhB + off);
                ldsm_x4_t(vl, aVlB + off);
#pragma unroll
                for (int h2 = 0; h2 < 2; h2++) {
                    int j = g * 2 + h2;
                    mma_bf16(oacc[j], pah[c], vh[2 * h2], vh[2 * h2 + 1]);
                    mma_bf16(oacc[j], pah[c], vl[2 * h2], vl[2 * h2 + 1]);
                    mma_bf16(oacc[j], pal[c], vh[2 * h2], vh[2 * h2 + 1]);
                }
            }
        }
        __syncthreads();
    }

    // epilogue: fp16 hi/lo
    float inv0 = 1.f / l0, inv1 = 1.f / l1;
    int tr = lane >> 2, tc = (lane & 3) * 2;
    int row0 = b * Sq + q0 + warp * 16 + tr;
#pragma unroll
    for (int j = 0; j < 8; j++) {
        int col = hh * 64 + j * 8 + tc;
        float o0 = oacc[j][0] * inv0, o1 = oacc[j][1] * inv0;
        float o2 = oacc[j][2] * inv1, o3 = oacc[j][3] * inv1;
        __half h0 = __float2half_rn(o0);
        __half h1 = __float2half_rn(o1);
        __half h2 = __float2half_rn(o2);
        __half h3 = __float2half_rn(o3);
        __half2 a0, a1;
        a0.x = h0; a0.y = h1; a1.x = h2; a1.y = h3;
        *(__half2*)(ath + (size_t)row0 * Dm + col) = a0;
        *(__half2*)(ath + (size_t)(row0 + 8) * Dm + col) = a1;
        *(uint32_t*)(atl + (size_t)row0 * Dm + col) =
            pack_f16x2(o0 - __half2float(h0), o1 - __half2float(h1));
        *(uint32_t*)(atl + (size_t)(row0 + 8) * Dm + col) =
            pack_f16x2(o2 - __half2float(h2), o3 - __half2float(h3));
    }
}

// ===========================================================================
// Fused residual add + LayerNorm (+ optional fp16 hi/lo output)
// ===========================================================================
__device__ __forceinline__ float block_allreduce(float v, float* sred)
{
#pragma unroll
    for (int o = 16; o; o >>= 1) v += __shfl_xor_sync(0xffffffffu, v, o);
    int w = threadIdx.x >> 5;
    if ((threadIdx.x & 31) == 0) sred[w] = v;
    __syncthreads();
    float t = (threadIdx.x < 8) ? sred[threadIdx.x] : 0.f;
    if (threadIdx.x < 32) {
#pragma unroll
        for (int o = 4; o; o >>= 1) t += __shfl_xor_sync(0xffffffffu, t, o);
        if (threadIdx.x == 0) sred[0] = t;
    }
    __syncthreads();
    float r = sred[0];
    __syncthreads();
    return r;
}

__global__ __launch_bounds__(256) void add_ln_kernel(
    const float* __restrict__ x, const float* __restrict__ y,
    const float* __restrict__ g, const float* __restrict__ bta,
    float* __restrict__ out, __half* __restrict__ oh,
    __half* __restrict__ ol)
{
    __shared__ float sred[8];
    int row = blockIdx.x;
    int tid = threadIdx.x;
    const float* xr = x + (size_t)row * Dm;
    const float* yr = y + (size_t)row * Dm;

    float4 xv = *(const float4*)(xr + tid * 4);
    float4 yv = *(const float4*)(yr + tid * 4);
    float v[4] = {xv.x + yv.x, xv.y + yv.y, xv.z + yv.z, xv.w + yv.w};

    float sum = v[0] + v[1] + v[2] + v[3];
    sum = block_allreduce(sum, sred);
    float mean = sum * (1.f / (float)Dm);

    float sq = 0.f;
#pragma unroll
    for (int i = 0; i < 4; i++) {
        float d = v[i] - mean;
        sq += d * d;
    }
    sq = block_allreduce(sq, sred);
    float inv = rsqrtf(sq * (1.f / (float)Dm) + 1e-5f);

    float4 gv = *(const float4*)(g + tid * 4);
    float4 bv = *(const float4*)(bta + tid * 4);
    float o[4];
    o[0] = (v[0] - mean) * inv * gv.x + bv.x;
    o[1] = (v[1] - mean) * inv * gv.y + bv.y;
    o[2] = (v[2] - mean) * inv * gv.z + bv.z;
    o[3] = (v[3] - mean) * inv * gv.w + bv.w;
    *(float4*)(out + (size_t)row * Dm + tid * 4) =
        make_float4(o[0], o[1], o[2], o[3]);

    if (oh) {
        uint2 hv, lv;
        split_f16x4(o, hv, lv);
        *(uint2*)(oh + (size_t)row * Dm + tid * 4) = hv;
        *(uint2*)(ol + (size_t)row * Dm + tid * 4) = lv;
    }
}

// ===========================================================================
extern "C" void kernel_launch(void* const* d_in, const int* in_sizes, int n_in,
                              void* d_out, int out_size)
{
    const float* x     = (const float*)d_in[0];
    const float* in_w  = (const float*)d_in[1];
    const float* in_b  = (const float*)d_in[2];
    const float* out_w = (const float*)d_in[3];
    const float* out_b = (const float*)d_in[4];
    const float* w1    = (const float*)d_in[5];
    const float* b1    = (const float*)d_in[6];
    const float* w2    = (const float*)d_in[7];
    const float* b2    = (const float*)d_in[8];
    const float* ln1g  = (const float*)d_in[9];
    const float* ln1b  = (const float*)d_in[10];
    const float* ln2g  = (const float*)d_in[11];
    const float* ln2b  = (const float*)d_in[12];
    float* out = (float*)d_out;

    float *qkv, *tmp, *hbuf;
    __half *xh, *xl, *wb, *ath, *atl, *hh, *hl, *ffh, *ffl;
    __nv_bfloat16 *qh, *ql, *kh, *kl, *vh, *vl;
    cudaGetSymbolAddress((void**)&qkv, g_qkv);
    cudaGetSymbolAddress((void**)&tmp, g_tmp);
    cudaGetSymbolAddress((void**)&hbuf, g_h);
    cudaGetSymbolAddress((void**)&xh, g_xh);
    cudaGetSymbolAddress((void**)&xl, g_xl);
    cudaGetSymbolAddress((void**)&wb, g_wb);
    cudaGetSymbolAddress((void**)&qh, g_qh);
    cudaGetSymbolAddress((void**)&ql, g_ql);
    cudaGetSymbolAddress((void**)&kh, g_kh);
    cudaGetSymbolAddress((void**)&kl, g_kl);
    cudaGetSymbolAddress((void**)&vh, g_vh);
    cudaGetSymbolAddress((void**)&vl, g_vl);
    cudaGetSymbolAddress((void**)&ath, g_ath);
    cudaGetSymbolAddress((void**)&atl, g_atl);
    cudaGetSymbolAddress((void**)&hh, g_hh);
    cudaGetSymbolAddress((void**)&hl, g_hl);
    cudaGetSymbolAddress((void**)&ffh, g_ffh);
    cudaGetSymbolAddress((void**)&ffl, g_ffl);

    cudaFuncSetAttribute(gemm_f16, cudaFuncAttributeMaxDynamicSharedMemorySize,
                         2 * GSTG);
    cudaFuncSetAttribute(attn_mma, cudaFuncAttributeMaxDynamicSharedMemorySize,
                         ATT_SMEM);

    dim3 tb(256);

    rope_table_kernel<<<(Sq * 32 + 255) / 256, tb>>>();
    cvt_pair_f16<<<(Mrows * Dm / 4 + 255) / 256, tb>>>(x, xh, xl, Mrows * Dm / 4);
    cvt_f16<<<(3 * Dm * Dm / 4 + 255) / 256, tb>>>(in_w, wb + OFF_INW, 3 * Dm * Dm / 4);
    cvt_f16<<<(Dm * Dm / 4 + 255) / 256, tb>>>(out_w, wb + OFF_OUTW, Dm * Dm / 4);
    cvt_f16<<<(Ff * Dm / 4 + 255) / 256, tb>>>(w1, wb + OFF_W1, Ff * Dm / 4);
    cvt_f16<<<(Dm * Ff / 4 + 255) / 256, tb>>>(w2, wb + OFF_W2, Dm * Ff / 4);

    // QKV projection -> fp32
    gemm_f16<<<dim3(3072 / 128, Mrows / 128), tb, 2 * GSTG>>>(
        xh, xl, wb + OFF_INW, in_b, qkv, nullptr, nullptr, 3 * Dm, Dm, 0);
    // RoPE + head-major bf16 split
    rope_bf_kernel<<<(Mrows * Hh * 8 + 255) / 256, tb>>>(qkv);
    // Attention -> fp16 hi/lo
    attn_mma<<<dim3(Sq / 128, Bq * Hh), tb, ATT_SMEM>>>(
        qh, ql, kh, kl, vh, vl, ath, atl);
    // Output projection -> fp32
    gemm_f16<<<dim3(Dm / 128, Mrows / 128), tb, 2 * GSTG>>>(
        ath, atl, wb + OFF_OUTW, out_b, tmp, nullptr, nullptr, Dm, Dm, 0);
    // LN1 -> fp32 h + fp16 hi/lo
    add_ln_kernel<<<Mrows, tb>>>(x, tmp, ln1g, ln1b, hbuf, hh, hl);
    // FF1 + ReLU -> fp16 hi/lo
    gemm_f16<<<dim3(Ff / 128, Mrows / 128), tb, 2 * GSTG>>>(
        hh, hl, wb + OFF_W1, b1, nullptr, ffh, ffl, Ff, Dm, 1);
    // FF2 -> fp32
    gemm_f16<<<dim3(Dm / 128, Mrows / 128), tb, 2 * GSTG>>>(
        ffh, ffl, wb + OFF_W2, b2, tmp, nullptr, nullptr, Dm, Ff, 0);
    // LN2 -> out
    add_ln_kernel<<<Mrows, tb>>>(hbuf, tmp, ln2g, ln2b, out, nullptr, nullptr);
}

// round 8
// speedup vs baseline: 3.7489x; 1.1889x over previous
#include <cuda_runtime.h>
#include <cuda_bf16.h>
#include <cuda_fp16.h>
#include <math.h>
#include <stdint.h>

// Problem constants
#define Bq 2
#define Sq 2048
#define Dm 1024
#define Ff 4096
#define Hh 16
#define Dhd 64
#define Mrows 4096  // B*S

// ---------------------------------------------------------------------------
// Scratch (device globals)
// ---------------------------------------------------------------------------
__device__ float g_qkv[(size_t)Mrows * 3 * Dm];
__device__ float g_tmp[(size_t)Mrows * Dm];
__device__ float g_h[(size_t)Mrows * Dm];
__device__ float g_cos[Sq * 32];
__device__ float g_sin[Sq * 32];

__device__ __half g_xh[(size_t)Mrows * Dm], g_xl[(size_t)Mrows * Dm];
__device__ __half g_wb[12582912];
#define OFF_INW 0
#define OFF_OUTW 3145728
#define OFF_W1 4194304
#define OFF_W2 8388608
__device__ __half g_qhh[(size_t)Bq * Hh * Sq * 64], g_qll[(size_t)Bq * Hh * Sq * 64];
__device__ __half g_kk[(size_t)Bq * Hh * Sq * 64];
__device__ __half g_vv[(size_t)Bq * Hh * Sq * 64];
__device__ __half g_ath[(size_t)Mrows * Dm], g_atl[(size_t)Mrows * Dm];
__device__ __half g_hh[(size_t)Mrows * Dm], g_hl[(size_t)Mrows * Dm];
__device__ __half g_ffh[(size_t)Mrows * Ff], g_ffl[(size_t)Mrows * Ff];

__device__ __forceinline__ uint32_t smem_u32(const void* p) {
    uint32_t a;
    asm("{ .reg .u64 t; cvta.to.shared.u64 t, %1; cvt.u32.u64 %0, t; }"
        : "=r"(a) : "l"(p));
    return a;
}
__device__ __forceinline__ void cp16(uint32_t dst, const void* src) {
    asm volatile("cp.async.cg.shared.global [%0], [%1], 16;"
                 :: "r"(dst), "l"(src));
}
#define CP_COMMIT() asm volatile("cp.async.commit_group;" ::: "memory")
#define CP_WAIT1()  asm volatile("cp.async.wait_group 1;" ::: "memory")
#define CP_WAIT0()  asm volatile("cp.async.wait_group 0;" ::: "memory")

__device__ __forceinline__ void ldsm_x4(uint32_t* r, uint32_t addr)
{
    asm volatile("ldmatrix.sync.aligned.m8n8.x4.shared.b16 {%0,%1,%2,%3}, [%4];"
                 : "=r"(r[0]), "=r"(r[1]), "=r"(r[2]), "=r"(r[3]) : "r"(addr));
}
__device__ __forceinline__ void ldsm_x4_t(uint32_t* r, uint32_t addr)
{
    asm volatile("ldmatrix.sync.aligned.m8n8.x4.trans.shared.b16 {%0,%1,%2,%3}, [%4];"
                 : "=r"(r[0]), "=r"(r[1]), "=r"(r[2]), "=r"(r[3]) : "r"(addr));
}
__device__ __forceinline__ void mma_f16(float* c, const uint32_t* a,
                                        uint32_t b0, uint32_t b1)
{
    asm volatile(
        "mma.sync.aligned.m16n8k16.row.col.f32.f16.f16.f32 "
        "{%0,%1,%2,%3}, {%4,%5,%6,%7}, {%8,%9}, {%0,%1,%2,%3};"
        : "+f"(c[0]), "+f"(c[1]), "+f"(c[2]), "+f"(c[3])
        : "r"(a[0]), "r"(a[1]), "r"(a[2]), "r"(a[3]), "r"(b0), "r"(b1));
}
__device__ __forceinline__ uint32_t pack_f16x2(float lo, float hi)
{
    uint32_t r;
    asm("cvt.rn.f16x2.f32 %0, %1, %2;" : "=r"(r) : "f"(hi), "f"(lo));
    return r;
}
__device__ __forceinline__ void split_f16x4(const float* o, uint2& hv, uint2& lv)
{
    __half h0 = __float2half_rn(o[0]);
    __half h1 = __float2half_rn(o[1]);
    __half h2 = __float2half_rn(o[2]);
    __half h3 = __float2half_rn(o[3]);
    __half2 a, b;
    a.x = h0; a.y = h1; b.x = h2; b.y = h3;
    hv.x = *(uint32_t*)&a; hv.y = *(uint32_t*)&b;
    lv.x = pack_f16x2(o[0] - __half2float(h0), o[1] - __half2float(h1));
    lv.y = pack_f16x2(o[2] - __half2float(h2), o[3] - __half2float(h3));
}

// ===========================================================================
// RoPE table kernel
// ===========================================================================
__global__ __launch_bounds__(256) void rope_table_kernel()
{
    int idx = blockIdx.x * 256 + threadIdx.x;
    if (idx >= Sq * 32) return;
    int s = idx >> 5;
    int i = idx & 31;
    double invd = exp(-(double)i * (9.210340371976184 / 32.0));
    float invf = (float)invd;
    float angf = (float)s * invf;
    double a = (double)angf;
    g_cos[idx] = (float)cos(a);
    g_sin[idx] = (float)sin(a);
}

// ===========================================================================
// Converters
// ===========================================================================
__global__ __launch_bounds__(256) void cvt_pair_f16(
    const float* __restrict__ src, __half* __restrict__ dh,
    __half* __restrict__ dl, int n4)
{
    int idx = blockIdx.x * 256 + threadIdx.x;
    if (idx >= n4) return;
    float4 v = *(const float4*)(src + (size_t)idx * 4);
    float o[4] = {v.x, v.y, v.z, v.w};
    uint2 hv, lv;
    split_f16x4(o, hv, lv);
    *(uint2*)(dh + (size_t)idx * 4) = hv;
    *(uint2*)(dl + (size_t)idx * 4) = lv;
}

__global__ __launch_bounds__(256) void cvt_f16(
    const float* __restrict__ src, __half* __restrict__ d, int n4)
{
    int idx = blockIdx.x * 256 + threadIdx.x;
    if (idx >= n4) return;
    float4 v = *(const float4*)(src + (size_t)idx * 4);
    uint2 hv;
    hv.x = pack_f16x2(v.x, v.y);
    hv.y = pack_f16x2(v.z, v.w);
    *(uint2*)(d + (size_t)idx * 4) = hv;
}

// ===========================================================================
// RoPE + split: qkv fp32 -> head-major fp16: Q hi/lo, K single, V single.
// ===========================================================================
__global__ __launch_bounds__(256) void rope_bf_kernel(const float* __restrict__ qkv)
{
    int idx = blockIdx.x * 256 + threadIdx.x;
    if (idx >= Mrows * Hh * 8) return;
    int e0 = (idx & 7) * 8;
    int h  = (idx >> 3) & 15;
    int m  = idx >> 7;
    int s  = m & (Sq - 1);
    int b  = m >> 11;
    int bh = b * Hh + h;
    int i0 = e0 >> 1;

    const float* rp = qkv + (size_t)m * 3072 + h * 64 + e0;
    float q[8], k[8], v[8];
    *(float4*)(q)     = *(const float4*)(rp);
    *(float4*)(q + 4) = *(const float4*)(rp + 4);
    *(float4*)(k)     = *(const float4*)(rp + 1024);
    *(float4*)(k + 4) = *(const float4*)(rp + 1028);
    *(float4*)(v)     = *(const float4*)(rp + 2048);
    *(float4*)(v + 4) = *(const float4*)(rp + 2052);

    float qr[8], kr[8];
#pragma unroll
    for (int p = 0; p < 4; p++) {
        float c  = g_cos[s * 32 + i0 + p];
        float sn = g_sin[s * 32 + i0 + p];
        qr[2 * p]     = q[2 * p] * c - q[2 * p + 1] * sn;
        qr[2 * p + 1] = q[2 * p] * sn + q[2 * p + 1] * c;
        kr[2 * p]     = k[2 * p] * c - k[2 * p + 1] * sn;
        kr[2 * p + 1] = k[2 * p] * sn + k[2 * p + 1] * c;
    }

    size_t d = ((size_t)bh * Sq + s) * 64 + e0;
    // Q: fp16 hi/lo
    {
        uint2 hv, lv, hv2, lv2;
        split_f16x4(qr, hv, lv);
        split_f16x4(qr + 4, hv2, lv2);
        *(uint2*)(g_qhh + d) = hv;  *(uint2*)(g_qhh + d + 4) = hv2;
        *(uint2*)(g_qll + d) = lv;  *(uint2*)(g_qll + d + 4) = lv2;
    }
    // K: single fp16
    {
        uint2 a;
        a.x = pack_f16x2(kr[0], kr[1]); a.y = pack_f16x2(kr[2], kr[3]);
        uint2 b2;
        b2.x = pack_f16x2(kr[4], kr[5]); b2.y = pack_f16x2(kr[6], kr[7]);
        *(uint2*)(g_kk + d) = a; *(uint2*)(g_kk + d + 4) = b2;
    }
    // V: single fp16
    {
        uint2 a;
        a.x = pack_f16x2(v[0], v[1]); a.y = pack_f16x2(v[2], v[3]);
        uint2 b2;
        b2.x = pack_f16x2(v[4], v[5]); b2.y = pack_f16x2(v[6], v[7]);
        *(uint2*)(g_vv + d) = a; *(uint2*)(g_vv + d + 4) = b2;
    }
}

// ===========================================================================
// fp16 2-pass GEMM (unchanged from R7)
// ===========================================================================
#define GPITCH 80
#define GARR 10240
#define GSTG 30720

__global__ __launch_bounds__(256) void gemm_f16(
    const __half* __restrict__ Ah, const __half* __restrict__ Al,
    const __half* __restrict__ W, const float* __restrict__ bias,
    float* __restrict__ Cf, __half* __restrict__ Ch, __half* __restrict__ Cl,
    int N, int K, int mode)
{
    extern __shared__ char dsm[];
    uint32_t sb = smem_u32(dsm);

    int tid = threadIdx.x;
    int lane = tid & 31, warp = tid >> 5;
    int wm = warp & 1;
    int wn = warp >> 1;
    int row0 = blockIdx.y * 128;
    int col0 = blockIdx.x * 128;

    float acc[4][4][4];
#pragma unroll
    for (int i = 0; i < 4; i++)
#pragma unroll
        for (int j = 0; j < 4; j++)
#pragma unroll
            for (int f = 0; f < 4; f++) acc[i][j][f] = 0.f;

    int frow = lane & 15;
    int fko  = (lane >> 4) << 3;

    int sa[6], sr[6], sq[6];
#pragma unroll
    for (int i = 0; i < 6; i++) {
        int f = tid + i * 256;
        sa[i] = f >> 9;
        int rem = f & 511;
        sr[i] = rem >> 2; sq[i] = rem & 3;
    }

    int nk = K >> 5;

#pragma unroll
    for (int i = 0; i < 6; i++) {
        const __half* s;
        if (sa[i] == 0)      s = Ah + (size_t)(row0 + sr[i]) * K;
        else if (sa[i] == 1) s = Al + (size_t)(row0 + sr[i]) * K;
        else                 s = W + (size_t)(col0 + sr[i]) * K;
        cp16(sb + sa[i] * GARR + sr[i] * GPITCH + sq[i] * 16, s + sq[i] * 8);
    }
    CP_COMMIT();

    for (int t = 0; t < nk; t++) {
        int buf = t & 1;
        if (t + 1 < nk) {
            int kt = (t + 1) * 32;
            uint32_t stg = sb + (buf ^ 1) * GSTG;
#pragma unroll
            for (int i = 0; i < 6; i++) {
                const __half* s;
                if (sa[i] == 0)      s = Ah + (size_t)(row0 + sr[i]) * K;
                else if (sa[i] == 1) s = Al + (size_t)(row0 + sr[i]) * K;
                else                 s = W + (size_t)(col0 + sr[i]) * K;
                cp16(stg + sa[i] * GARR + sr[i] * GPITCH + sq[i] * 16,
                     s + kt + sq[i] * 8);
            }
            CP_COMMIT();
            CP_WAIT1();
        } else {
            CP_WAIT0();
        }
        __syncthreads();

        uint32_t aAh = sb + buf * GSTG;
        uint32_t aAl = aAh + GARR;
        uint32_t aW  = aAl + GARR;

#pragma unroll
        for (int s = 0; s < 2; s++) {
            int ko = s * 16 + fko;
            uint32_t afh[4][4], afl[4][4], bf[2][4];
#pragma unroll
            for (int mt = 0; mt < 4; mt++) {
                int off = (wm * 64 + mt * 16 + frow) * GPITCH + ko * 2;
                ldsm_x4(afh[mt], aAh + off);
                ldsm_x4(afl[mt], aAl + off);
            }
#pragma unroll
            for (int bt = 0; bt < 2; bt++) {
                int off = (wn * 32 + bt * 16 + frow) * GPITCH + ko * 2;
                ldsm_x4(bf[bt], aW + off);
            }
#pragma unroll
            for (int mt = 0; mt < 4; mt++)
#pragma unroll
                for (int bt = 0; bt < 2; bt++)
#pragma unroll
                    for (int h = 0; h < 2; h++) {
                        int nt = bt * 2 + h;
                        mma_f16(acc[mt][nt], afh[mt], bf[bt][h], bf[bt][h + 2]);
                        mma_f16(acc[mt][nt], afl[mt], bf[bt][h], bf[bt][h + 2]);
                    }
        }
        __syncthreads();
    }

    int tr = lane >> 2, tc = (lane & 3) * 2;
#pragma unroll
    for (int mt = 0; mt < 4; mt++) {
#pragma unroll
        for (int nt = 0; nt < 4; nt++) {
            int col = col0 + wn * 32 + nt * 8 + tc;
            float2 bv = *(const float2*)(bias + col);
            int r0 = row0 + wm * 64 + mt * 16 + tr;
            float o[4];
            o[0] = acc[mt][nt][0] + bv.x;
            o[1] = acc[mt][nt][1] + bv.y;
            o[2] = acc[mt][nt][2] + bv.x;
            o[3] = acc[mt][nt][3] + bv.y;
            if (mode == 0) {
                *(float2*)(Cf + (size_t)r0 * N + col) = make_float2(o[0], o[1]);
                *(float2*)(Cf + (size_t)(r0 + 8) * N + col) = make_float2(o[2], o[3]);
            } else {
#pragma unroll
                for (int i = 0; i < 4; i++) o[i] = fmaxf(o[i], 0.f);
                __half h0 = __float2half_rn(o[0]);
                __half h1 = __float2half_rn(o[1]);
                __half h2 = __float2half_rn(o[2]);
                __half h3 = __float2half_rn(o[3]);
                __half2 a, b;
                a.x = h0; a.y = h1; b.x = h2; b.y = h3;
                *(__half2*)(Ch + (size_t)r0 * N + col) = a;
                *(__half2*)(Ch + (size_t)(r0 + 8) * N + col) = b;
                *(uint32_t*)(Cl + (size_t)r0 * N + col) =
                    pack_f16x2(o[0] - __half2float(h0), o[1] - __half2float(h1));
                *(uint32_t*)(Cl + (size_t)(r0 + 8) * N + col) =
                    pack_f16x2(o[2] - __half2float(h2), o[3] - __half2float(h3));
            }
        }
    }
}

// ===========================================================================
// Flash attention, fp16: S = (Qh+Ql)@K^T (2 passes), O = P@V (1 pass).
// smem: Qh,Ql 128x144B each; K,V 64x144B x 2 stages. Total 73728 bytes.
// ===========================================================================
#define APITCH 144
#define AQH 0
#define AQL 18432
#define AKV0 36864
#define AARR 9216
#define ASTG 18432
#define ATT_SMEM 73728

__global__ __launch_bounds__(256) void attn_mma(
    const __half* __restrict__ Qh, const __half* __restrict__ Ql,
    const __half* __restrict__ Kk, const __half* __restrict__ Vv,
    __half* __restrict__ ath, __half* __restrict__ atl)
{
    extern __shared__ char dsm[];
    uint32_t sb = smem_u32(dsm);

    int tid = threadIdx.x;
    int lane = tid & 31, warp = tid >> 5;
    int bh = blockIdx.y;
    int b = bh >> 4, hh = bh & 15;
    int q0 = blockIdx.x * 128;

    size_t hbase = (size_t)bh * Sq * 64;

    // stage Q (2 arrays x 128 rows x 8 chunks = 2048; 8/thread)
#pragma unroll
    for (int i = 0; i < 8; i++) {
        int f = tid + i * 256;
        int a = f >> 10, rem = f & 1023, r = rem >> 3, q = rem & 7;
        const __half* s = (a ? Ql : Qh) + hbase + (size_t)(q0 + r) * 64 + q * 8;
        cp16(sb + (a ? AQL : AQH) + r * APITCH + q * 16, s);
    }
    // stage K,V tile 0 (2 arrays x 64 x 8 = 1024 chunks; 4/thread)
#pragma unroll
    for (int i = 0; i < 4; i++) {
        int f = tid + i * 256;
        int a = f >> 9, rem = f & 511, r = rem >> 3, q = rem & 7;
        const __half* s = (a ? Vv : Kk) + hbase + (size_t)r * 64 + q * 8;
        cp16(sb + AKV0 + a * AARR + r * APITCH + q * 16, s);
    }
    CP_COMMIT();

    int frow = lane & 15;
    int fko  = (lane >> 4) << 3;

    uint32_t aQh[4][4], aQl[4][4];
    float m0 = -1e30f, m1 = -1e30f, l0 = 0.f, l1 = 0.f;
    float oacc[8][4];
#pragma unroll
    for (int j = 0; j < 8; j++)
#pragma unroll
        for (int f = 0; f < 4; f++) oacc[j][f] = 0.f;

    const int NT = Sq / 64;
    for (int t = 0; t < NT; t++) {
        int buf = t & 1;
        if (t + 1 < NT) {
            int kt = (t + 1) * 64;
            uint32_t stg = sb + AKV0 + (buf ^ 1) * ASTG + AARR * 0;
            // note: stage layout = [stage][K then V]; stride between stages = 2*AARR
            stg = sb + AKV0 + (buf ^ 1) * (2 * AARR);
#pragma unroll
            for (int i = 0; i < 4; i++) {
                int f = tid + i * 256;
                int a = f >> 9, rem = f & 511, r = rem >> 3, q = rem & 7;
                const __half* s = (a ? Vv : Kk) + hbase + (size_t)(kt + r) * 64 + q * 8;
                cp16(stg + a * AARR + r * APITCH + q * 16, s);
            }
            CP_COMMIT();
            CP_WAIT1();
        } else {
            CP_WAIT0();
        }
        __syncthreads();

        if (t == 0) {
#pragma unroll
            for (int c = 0; c < 4; c++) {
                int off = (warp * 16 + frow) * APITCH + (c * 16 + fko) * 2;
                ldsm_x4(aQh[c], sb + AQH + off);
                ldsm_x4(aQl[c], sb + AQL + off);
            }
        }

        uint32_t aKB = sb + AKV0 + buf * (2 * AARR);
        uint32_t aVB = aKB + AARR;

        // ---- S = Q @ K^T (2 passes) ----
        float sacc[8][4];
#pragma unroll
        for (int j = 0; j < 8; j++)
#pragma unroll
            for (int f = 0; f < 4; f++) sacc[j][f] = 0.f;

#pragma unroll
        for (int kd = 0; kd < 4; kd++) {
#pragma unroll
            for (int bt = 0; bt < 4; bt++) {
                uint32_t kf[4];
                int off = (bt * 16 + frow) * APITCH + (kd * 16 + fko) * 2;
                ldsm_x4(kf, aKB + off);
#pragma unroll
                for (int h = 0; h < 2; h++) {
                    int nt = bt * 2 + h;
                    mma_f16(sacc[nt], aQh[kd], kf[h], kf[h + 2]);
                    mma_f16(sacc[nt], aQl[kd], kf[h], kf[h + 2]);
                }
            }
        }

        // ---- online softmax ----
        float rmax0 = -1e30f, rmax1 = -1e30f;
#pragma unroll
        for (int j = 0; j < 8; j++) {
            rmax0 = fmaxf(rmax0, fmaxf(sacc[j][0], sacc[j][1]));
            rmax1 = fmaxf(rmax1, fmaxf(sacc[j][2], sacc[j][3]));
        }
        rmax0 = fmaxf(rmax0, __shfl_xor_sync(0xffffffffu, rmax0, 1));
        rmax0 = fmaxf(rmax0, __shfl_xor_sync(0xffffffffu, rmax0, 2));
        rmax1 = fmaxf(rmax1, __shfl_xor_sync(0xffffffffu, rmax1, 1));
        rmax1 = fmaxf(rmax1, __shfl_xor_sync(0xffffffffu, rmax1, 2));

        float mn0 = fmaxf(m0, 0.125f * rmax0);
        float mn1 = fmaxf(m1, 0.125f * rmax1);
        float corr0 = __expf(m0 - mn0);
        float corr1 = __expf(m1 - mn1);
        m0 = mn0; m1 = mn1;

        // P = exp(s/8 - m), packed single fp16 a-frags
        uint32_t pah[4][4];
        float ps0 = 0.f, ps1 = 0.f;
#pragma unroll
        for (int c = 0; c < 4; c++) {
#pragma unroll
            for (int u = 0; u < 2; u++) {
                int j = 2 * c + u;
                float p0 = __expf(0.125f * sacc[j][0] - mn0);
                float p1 = __expf(0.125f * sacc[j][1] - mn0);
                float p2 = __expf(0.125f * sacc[j][2] - mn1);
                float p3 = __expf(0.125f * sacc[j][3] - mn1);
                ps0 += p0 + p1;
                ps1 += p2 + p3;
                pah[c][2 * u + 0] = pack_f16x2(p0, p1);
                pah[c][2 * u + 1] = pack_f16x2(p2, p3);
            }
        }
        ps0 += __shfl_xor_sync(0xffffffffu, ps0, 1);
        ps0 += __shfl_xor_sync(0xffffffffu, ps0, 2);
        ps1 += __shfl_xor_sync(0xffffffffu, ps1, 1);
        ps1 += __shfl_xor_sync(0xffffffffu, ps1, 2);
        l0 = l0 * corr0 + ps0;
        l1 = l1 * corr1 + ps1;

#pragma unroll
        for (int j = 0; j < 8; j++) {
            oacc[j][0] *= corr0; oacc[j][1] *= corr0;
            oacc[j][2] *= corr1; oacc[j][3] *= corr1;
        }

        // ---- O += P @ V (1 pass) ----
#pragma unroll
        for (int c = 0; c < 4; c++) {
#pragma unroll
            for (int g = 0; g < 4; g++) {
                uint32_t vf[4];
                int off = (c * 16 + frow) * APITCH + (g * 16 + fko) * 2;
                ldsm_x4_t(vf, aVB + off);
#pragma unroll
                for (int h2 = 0; h2 < 2; h2++) {
                    int j = g * 2 + h2;
                    mma_f16(oacc[j], pah[c], vf[2 * h2], vf[2 * h2 + 1]);
                }
            }
        }
        __syncthreads();
    }

    // epilogue: fp16 hi/lo
    float inv0 = 1.f / l0, inv1 = 1.f / l1;
    int tr = lane >> 2, tc = (lane & 3) * 2;
    int row0 = b * Sq + q0 + warp * 16 + tr;
#pragma unroll
    for (int j = 0; j < 8; j++) {
        int col = hh * 64 + j * 8 + tc;
        float o0 = oacc[j][0] * inv0, o1 = oacc[j][1] * inv0;
        float o2 = oacc[j][2] * inv1, o3 = oacc[j][3] * inv1;
        __half h0 = __float2half_rn(o0);
        __half h1 = __float2half_rn(o1);
        __half h2 = __float2half_rn(o2);
        __half h3 = __float2half_rn(o3);
        __half2 a0, a1;
        a0.x = h0; a0.y = h1; a1.x = h2; a1.y = h3;
        *(__half2*)(ath + (size_t)row0 * Dm + col) = a0;
        *(__half2*)(ath + (size_t)(row0 + 8) * Dm + col) = a1;
        *(uint32_t*)(atl + (size_t)row0 * Dm + col) =
            pack_f16x2(o0 - __half2float(h0), o1 - __half2float(h1));
        *(uint32_t*)(atl + (size_t)(row0 + 8) * Dm + col) =
            pack_f16x2(o2 - __half2float(h2), o3 - __half2float(h3));
    }
}

// ===========================================================================
// Fused residual add + LayerNorm (+ optional fp16 hi/lo output)
// ===========================================================================
__device__ __forceinline__ float block_allreduce(float v, float* sred)
{
#pragma unroll
    for (int o = 16; o; o >>= 1) v += __shfl_xor_sync(0xffffffffu, v, o);
    int w = threadIdx.x >> 5;
    if ((threadIdx.x & 31) == 0) sred[w] = v;
    __syncthreads();
    float t = (threadIdx.x < 8) ? sred[threadIdx.x] : 0.f;
    if (threadIdx.x < 32) {
#pragma unroll
        for (int o = 4; o; o >>= 1) t += __shfl_xor_sync(0xffffffffu, t, o);
        if (threadIdx.x == 0) sred[0] = t;
    }
    __syncthreads();
    float r = sred[0];
    __syncthreads();
    return r;
}

__global__ __launch_bounds__(256) void add_ln_kernel(
    const float* __restrict__ x, const float* __restrict__ y,
    const float* __restrict__ g, const float* __restrict__ bta,
    float* __restrict__ out, __half* __restrict__ oh,
    __half* __restrict__ ol)
{
    __shared__ float sred[8];
    int row = blockIdx.x;
    int tid = threadIdx.x;
    const float* xr = x + (size_t)row * Dm;
    const float* yr = y + (size_t)row * Dm;

    float4 xv = *(const float4*)(xr + tid * 4);
    float4 yv = *(const float4*)(yr + tid * 4);
    float v[4] = {xv.x + yv.x, xv.y + yv.y, xv.z + yv.z, xv.w + yv.w};

    float sum = v[0] + v[1] + v[2] + v[3];
    sum = block_allreduce(sum, sred);
    float mean = sum * (1.f / (float)Dm);

    float sq = 0.f;
#pragma unroll
    for (int i = 0; i < 4; i++) {
        float d = v[i] - mean;
        sq += d * d;
    }
    sq = block_allreduce(sq, sred);
    float inv = rsqrtf(sq * (1.f / (float)Dm) + 1e-5f);

    float4 gv = *(const float4*)(g + tid * 4);
    float4 bv = *(const float4*)(bta + tid * 4);
    float o[4];
    o[0] = (v[0] - mean) * inv * gv.x + bv.x;
    o[1] = (v[1] - mean) * inv * gv.y + bv.y;
    o[2] = (v[2] - mean) * inv * gv.z + bv.z;
    o[3] = (v[3] - mean) * inv * gv.w + bv.w;
    *(float4*)(out + (size_t)row * Dm + tid * 4) =
        make_float4(o[0], o[1], o[2], o[3]);

    if (oh) {
        uint2 hv, lv;
        split_f16x4(o, hv, lv);
        *(uint2*)(oh + (size_t)row * Dm + tid * 4) = hv;
        *(uint2*)(ol + (size_t)row * Dm + tid * 4) = lv;
    }
}

// ===========================================================================
extern "C" void kernel_launch(void* const* d_in, const int* in_sizes, int n_in,
                              void* d_out, int out_size)
{
    const float* x     = (const float*)d_in[0];
    const float* in_w  = (const float*)d_in[1];
    const float* in_b  = (const float*)d_in[2];
    const float* out_w = (const float*)d_in[3];
    const float* out_b = (const float*)d_in[4];
    const float* w1    = (const float*)d_in[5];
    const float* b1    = (const float*)d_in[6];
    const float* w2    = (const float*)d_in[7];
    const float* b2    = (const float*)d_in[8];
    const float* ln1g  = (const float*)d_in[9];
    const float* ln1b  = (const float*)d_in[10];
    const float* ln2g  = (const float*)d_in[11];
    const float* ln2b  = (const float*)d_in[12];
    float* out = (float*)d_out;

    float *qkv, *tmp, *hbuf;
    __half *xh, *xl, *wb, *ath, *atl, *hh, *hl, *ffh, *ffl;
    __half *qhh, *qll, *kk, *vv;
    cudaGetSymbolAddress((void**)&qkv, g_qkv);
    cudaGetSymbolAddress((void**)&tmp, g_tmp);
    cudaGetSymbolAddress((void**)&hbuf, g_h);
    cudaGetSymbolAddress((void**)&xh, g_xh);
    cudaGetSymbolAddress((void**)&xl, g_xl);
    cudaGetSymbolAddress((void**)&wb, g_wb);
    cudaGetSymbolAddress((void**)&qhh, g_qhh);
    cudaGetSymbolAddress((void**)&qll, g_qll);
    cudaGetSymbolAddress((void**)&kk, g_kk);
    cudaGetSymbolAddress((void**)&vv, g_vv);
    cudaGetSymbolAddress((void**)&ath, g_ath);
    cudaGetSymbolAddress((void**)&atl, g_atl);
    cudaGetSymbolAddress((void**)&hh, g_hh);
    cudaGetSymbolAddress((void**)&hl, g_hl);
    cudaGetSymbolAddress((void**)&ffh, g_ffh);
    cudaGetSymbolAddress((void**)&ffl, g_ffl);

    cudaFuncSetAttribute(gemm_f16, cudaFuncAttributeMaxDynamicSharedMemorySize,
                         2 * GSTG);
    cudaFuncSetAttribute(attn_mma, cudaFuncAttributeMaxDynamicSharedMemorySize,
                         ATT_SMEM);

    dim3 tb(256);

    rope_table_kernel<<<(Sq * 32 + 255) / 256, tb>>>();
    cvt_pair_f16<<<(Mrows * Dm / 4 + 255) / 256, tb>>>(x, xh, xl, Mrows * Dm / 4);
    cvt_f16<<<(3 * Dm * Dm / 4 + 255) / 256, tb>>>(in_w, wb + OFF_INW, 3 * Dm * Dm / 4);
    cvt_f16<<<(Dm * Dm / 4 + 255) / 256, tb>>>(out_w, wb + OFF_OUTW, Dm * Dm / 4);
    cvt_f16<<<(Ff * Dm / 4 + 255) / 256, tb>>>(w1, wb + OFF_W1, Ff * Dm / 4);
    cvt_f16<<<(Dm * Ff / 4 + 255) / 256, tb>>>(w2, wb + OFF_W2, Dm * Ff / 4);

    // QKV projection -> fp32
    gemm_f16<<<dim3(3072 / 128, Mrows / 128), tb, 2 * GSTG>>>(
        xh, xl, wb + OFF_INW, in_b, qkv, nullptr, nullptr, 3 * Dm, Dm, 0);
    // RoPE + head-major fp16 split
    rope_bf_kernel<<<(Mrows * Hh * 8 + 255) / 256, tb>>>(qkv);
    // Attention -> fp16 hi/lo
    attn_mma<<<dim3(Sq / 128, Bq * Hh), tb, ATT_SMEM>>>(
        qhh, qll, kk, vv, ath, atl);
    // Output projection -> fp32
    gemm_f16<<<dim3(Dm / 128, Mrows / 128), tb, 2 * GSTG>>>(
        ath, atl, wb + OFF_OUTW, out_b, tmp, nullptr, nullptr, Dm, Dm, 0);
    // LN1 -> fp32 h + fp16 hi/lo
    add_ln_kernel<<<Mrows, tb>>>(x, tmp, ln1g, ln1b, hbuf, hh, hl);
    // FF1 + ReLU -> fp16 hi/lo
    gemm_f16<<<dim3(Ff / 128, Mrows / 128), tb, 2 * GSTG>>>(
        hh, hl, wb + OFF_W1, b1, nullptr, ffh, ffl, Ff, Dm, 1);
    // FF2 -> fp32
    gemm_f16<<<dim3(Dm / 128, Mrows / 128), tb, 2 * GSTG>>>(
        ffh, ffl, wb + OFF_W2, b2, tmp, nullptr, nullptr, Dm, Ff, 0);
    // LN2 -> out
    add_ln_kernel<<<Mrows, tb>>>(hbuf, tmp, ln2g, ln2b, out, nullptr, nullptr);
}

// round 9
// speedup vs baseline: 5.9891x; 1.5976x over previous
#include <cuda_runtime.h>
#include <cuda_fp16.h>
#include <math.h>
#include <stdint.h>

// Problem constants
#define Bq 2
#define Sq 2048
#define Dm 1024
#define Ff 4096
#define Hh 16
#define Dhd 64
#define Mrows 4096  // B*S

// ---------------------------------------------------------------------------
// Scratch (device globals)
// ---------------------------------------------------------------------------
__device__ float g_qkv[(size_t)Mrows * 3 * Dm];
__device__ float g_tmp[(size_t)Mrows * Dm];
__device__ float g_h[(size_t)Mrows * Dm];
__device__ float g_cos[Sq * 32];
__device__ float g_sin[Sq * 32];

__device__ __half g_xf[(size_t)Mrows * Dm];
__device__ __half g_wb[12582912];
#define OFF_INW 0
#define OFF_OUTW 3145728
#define OFF_W1 4194304
#define OFF_W2 8388608
__device__ __half g_qq[(size_t)Bq * Hh * Sq * 64];
__device__ __half g_kk[(size_t)Bq * Hh * Sq * 64];
__device__ __half g_vv[(size_t)Bq * Hh * Sq * 64];
__device__ __half g_at[(size_t)Mrows * Dm];
__device__ __half g_hf[(size_t)Mrows * Dm];
__device__ __half g_ff[(size_t)Mrows * Ff];

__device__ __forceinline__ uint32_t smem_u32(const void* p) {
    uint32_t a;
    asm("{ .reg .u64 t; cvta.to.shared.u64 t, %1; cvt.u32.u64 %0, t; }"
        : "=r"(a) : "l"(p));
    return a;
}
__device__ __forceinline__ void cp16(uint32_t dst, const void* src) {
    asm volatile("cp.async.cg.shared.global [%0], [%1], 16;"
                 :: "r"(dst), "l"(src));
}
#define CP_COMMIT() asm volatile("cp.async.commit_group;" ::: "memory")
#define CP_WAIT1()  asm volatile("cp.async.wait_group 1;" ::: "memory")
#define CP_WAIT0()  asm volatile("cp.async.wait_group 0;" ::: "memory")

__device__ __forceinline__ void ldsm_x4(uint32_t* r, uint32_t addr)
{
    asm volatile("ldmatrix.sync.aligned.m8n8.x4.shared.b16 {%0,%1,%2,%3}, [%4];"
                 : "=r"(r[0]), "=r"(r[1]), "=r"(r[2]), "=r"(r[3]) : "r"(addr));
}
__device__ __forceinline__ void ldsm_x4_t(uint32_t* r, uint32_t addr)
{
    asm volatile("ldmatrix.sync.aligned.m8n8.x4.trans.shared.b16 {%0,%1,%2,%3}, [%4];"
                 : "=r"(r[0]), "=r"(r[1]), "=r"(r[2]), "=r"(r[3]) : "r"(addr));
}
__device__ __forceinline__ void mma_f16(float* c, const uint32_t* a,
                                        uint32_t b0, uint32_t b1)
{
    asm volatile(
        "mma.sync.aligned.m16n8k16.row.col.f32.f16.f16.f32 "
        "{%0,%1,%2,%3}, {%4,%5,%6,%7}, {%8,%9}, {%0,%1,%2,%3};"
        : "+f"(c[0]), "+f"(c[1]), "+f"(c[2]), "+f"(c[3])
        : "r"(a[0]), "r"(a[1]), "r"(a[2]), "r"(a[3]), "r"(b0), "r"(b1));
}
__device__ __forceinline__ uint32_t pack_f16x2(float lo, float hi)
{
    uint32_t r;
    asm("cvt.rn.f16x2.f32 %0, %1, %2;" : "=r"(r) : "f"(hi), "f"(lo));
    return r;
}

// ===========================================================================
// RoPE table kernel
// ===========================================================================
__global__ __launch_bounds__(256) void rope_table_kernel()
{
    int idx = blockIdx.x * 256 + threadIdx.x;
    if (idx >= Sq * 32) return;
    int s = idx >> 5;
    int i = idx & 31;
    double invd = exp(-(double)i * (9.210340371976184 / 32.0));
    float invf = (float)invd;
    float angf = (float)s * invf;
    double a = (double)angf;
    g_cos[idx] = (float)cos(a);
    g_sin[idx] = (float)sin(a);
}

// ===========================================================================
// fp32 -> fp16 converter (4 elems/thread)
// ===========================================================================
__global__ __launch_bounds__(256) void cvt_f16(
    const float* __restrict__ src, __half* __restrict__ d, int n4)
{
    int idx = blockIdx.x * 256 + threadIdx.x;
    if (idx >= n4) return;
    float4 v = *(const float4*)(src + (size_t)idx * 4);
    uint2 hv;
    hv.x = pack_f16x2(v.x, v.y);
    hv.y = pack_f16x2(v.z, v.w);
    *(uint2*)(d + (size_t)idx * 4) = hv;
}

// ===========================================================================
// RoPE + split: qkv fp32 -> head-major single fp16 Q, K, V.
// ===========================================================================
__global__ __launch_bounds__(256) void rope_f16_kernel(const float* __restrict__ qkv)
{
    int idx = blockIdx.x * 256 + threadIdx.x;
    if (idx >= Mrows * Hh * 8) return;
    int e0 = (idx & 7) * 8;
    int h  = (idx >> 3) & 15;
    int m  = idx >> 7;
    int s  = m & (Sq - 1);
    int b  = m >> 11;
    int bh = b * Hh + h;
    int i0 = e0 >> 1;

    const float* rp = qkv + (size_t)m * 3072 + h * 64 + e0;
    float q[8], k[8], v[8];
    *(float4*)(q)     = *(const float4*)(rp);
    *(float4*)(q + 4) = *(const float4*)(rp + 4);
    *(float4*)(k)     = *(const float4*)(rp + 1024);
    *(float4*)(k + 4) = *(const float4*)(rp + 1028);
    *(float4*)(v)     = *(const float4*)(rp + 2048);
    *(float4*)(v + 4) = *(const float4*)(rp + 2052);

    float qr[8], kr[8];
#pragma unroll
    for (int p = 0; p < 4; p++) {
        float c  = g_cos[s * 32 + i0 + p];
        float sn = g_sin[s * 32 + i0 + p];
        qr[2 * p]     = q[2 * p] * c - q[2 * p + 1] * sn;
        qr[2 * p + 1] = q[2 * p] * sn + q[2 * p + 1] * c;
        kr[2 * p]     = k[2 * p] * c - k[2 * p + 1] * sn;
        kr[2 * p + 1] = k[2 * p] * sn + k[2 * p + 1] * c;
    }

    size_t d = ((size_t)bh * Sq + s) * 64 + e0;
    uint2 a0, a1;
    a0.x = pack_f16x2(qr[0], qr[1]); a0.y = pack_f16x2(qr[2], qr[3]);
    a1.x = pack_f16x2(qr[4], qr[5]); a1.y = pack_f16x2(qr[6], qr[7]);
    *(uint2*)(g_qq + d) = a0; *(uint2*)(g_qq + d + 4) = a1;
    a0.x = pack_f16x2(kr[0], kr[1]); a0.y = pack_f16x2(kr[2], kr[3]);
    a1.x = pack_f16x2(kr[4], kr[5]); a1.y = pack_f16x2(kr[6], kr[7]);
    *(uint2*)(g_kk + d) = a0; *(uint2*)(g_kk + d + 4) = a1;
    a0.x = pack_f16x2(v[0], v[1]); a0.y = pack_f16x2(v[2], v[3]);
    a1.x = pack_f16x2(v[4], v[5]); a1.y = pack_f16x2(v[6], v[7]);
    *(uint2*)(g_vv + d) = a0; *(uint2*)(g_vv + d + 4) = a1;
}

// ===========================================================================
// Pure fp16 1-pass GEMM: C = A @ W^T + bias, fp32 accum.
// CTA 128x128, BK=32, 8 warps. pitch 80B, cp.async double buffered.
// smem: 2 stages x 2 arrays x 10240B = 40960 bytes.
// mode 0: fp32 out; mode 1: relu + fp16 out.
// ===========================================================================
#define GPITCH 80
#define GARR 10240
#define GSTG 20480

__global__ __launch_bounds__(256) void gemm_f16(
    const __half* __restrict__ A, const __half* __restrict__ W,
    const float* __restrict__ bias, float* __restrict__ Cf,
    __half* __restrict__ Ch, int N, int K, int mode)
{
    extern __shared__ char dsm[];
    uint32_t sb = smem_u32(dsm);

    int tid = threadIdx.x;
    int lane = tid & 31, warp = tid >> 5;
    int wm = warp & 1;
    int wn = warp >> 1;
    int row0 = blockIdx.y * 128;
    int col0 = blockIdx.x * 128;

    float acc[4][4][4];
#pragma unroll
    for (int i = 0; i < 4; i++)
#pragma unroll
        for (int j = 0; j < 4; j++)
#pragma unroll
            for (int f = 0; f < 4; f++) acc[i][j][f] = 0.f;

    int frow = lane & 15;
    int fko  = (lane >> 4) << 3;

    // staging: 1024 16B-chunks per stage, 4 per thread
    int sa[4], sr[4], sq[4];
#pragma unroll
    for (int i = 0; i < 4; i++) {
        int f = tid + i * 256;
        sa[i] = f >> 9;
        int rem = f & 511;
        sr[i] = rem >> 2; sq[i] = rem & 3;
    }

    int nk = K >> 5;

#pragma unroll
    for (int i = 0; i < 4; i++) {
        const __half* s = sa[i] ? (W + (size_t)(col0 + sr[i]) * K)
                                : (A + (size_t)(row0 + sr[i]) * K);
        cp16(sb + sa[i] * GARR + sr[i] * GPITCH + sq[i] * 16, s + sq[i] * 8);
    }
    CP_COMMIT();

    for (int t = 0; t < nk; t++) {
        int buf = t & 1;
        if (t + 1 < nk) {
            int kt = (t + 1) * 32;
            uint32_t stg = sb + (buf ^ 1) * GSTG;
#pragma unroll
            for (int i = 0; i < 4; i++) {
                const __half* s = sa[i] ? (W + (size_t)(col0 + sr[i]) * K)
                                        : (A + (size_t)(row0 + sr[i]) * K);
                cp16(stg + sa[i] * GARR + sr[i] * GPITCH + sq[i] * 16,
                     s + kt + sq[i] * 8);
            }
            CP_COMMIT();
            CP_WAIT1();
        } else {
            CP_WAIT0();
        }
        __syncthreads();

        uint32_t aA = sb + buf * GSTG;
        uint32_t aW = aA + GARR;

#pragma unroll
        for (int s = 0; s < 2; s++) {
            int ko = s * 16 + fko;
            uint32_t af[4][4], bf[2][4];
#pragma unroll
            for (int mt = 0; mt < 4; mt++) {
                int off = (wm * 64 + mt * 16 + frow) * GPITCH + ko * 2;
                ldsm_x4(af[mt], aA + off);
            }
#pragma unroll
            for (int bt = 0; bt < 2; bt++) {
                int off = (wn * 32 + bt * 16 + frow) * GPITCH + ko * 2;
                ldsm_x4(bf[bt], aW + off);
            }
#pragma unroll
            for (int mt = 0; mt < 4; mt++)
#pragma unroll
                for (int bt = 0; bt < 2; bt++)
#pragma unroll
                    for (int h = 0; h < 2; h++) {
                        int nt = bt * 2 + h;
                        mma_f16(acc[mt][nt], af[mt], bf[bt][h], bf[bt][h + 2]);
                    }
        }
        __syncthreads();
    }

    int tr = lane >> 2, tc = (lane & 3) * 2;
#pragma unroll
    for (int mt = 0; mt < 4; mt++) {
#pragma unroll
        for (int nt = 0; nt < 4; nt++) {
            int col = col0 + wn * 32 + nt * 8 + tc;
            float2 bv = *(const float2*)(bias + col);
            int r0 = row0 + wm * 64 + mt * 16 + tr;
            float o[4];
            o[0] = acc[mt][nt][0] + bv.x;
            o[1] = acc[mt][nt][1] + bv.y;
            o[2] = acc[mt][nt][2] + bv.x;
            o[3] = acc[mt][nt][3] + bv.y;
            if (mode == 0) {
                *(float2*)(Cf + (size_t)r0 * N + col) = make_float2(o[0], o[1]);
                *(float2*)(Cf + (size_t)(r0 + 8) * N + col) = make_float2(o[2], o[3]);
            } else {
#pragma unroll
                for (int i = 0; i < 4; i++) o[i] = fmaxf(o[i], 0.f);
                *(uint32_t*)(Ch + (size_t)r0 * N + col) = pack_f16x2(o[0], o[1]);
                *(uint32_t*)(Ch + (size_t)(r0 + 8) * N + col) = pack_f16x2(o[2], o[3]);
            }
        }
    }
}

// ===========================================================================
// Flash attention, pure fp16: S = Q@K^T (1 pass), O = P@V (1 pass).
// smem: Q 128x144B; K,V 64x144B x 2 stages. Total 55296 bytes.
// ===========================================================================
#define APITCH 144
#define AQ0 0
#define AKV0 18432
#define AARR 9216
#define ATT_SMEM 55296

__global__ __launch_bounds__(256) void attn_mma(
    const __half* __restrict__ Qq, const __half* __restrict__ Kk,
    const __half* __restrict__ Vv, __half* __restrict__ at)
{
    extern __shared__ char dsm[];
    uint32_t sb = smem_u32(dsm);

    int tid = threadIdx.x;
    int lane = tid & 31, warp = tid >> 5;
    int bh = blockIdx.y;
    int b = bh >> 4, hh = bh & 15;
    int q0 = blockIdx.x * 128;

    size_t hbase = (size_t)bh * Sq * 64;

    // stage Q (128 rows x 8 chunks = 1024; 4/thread)
#pragma unroll
    for (int i = 0; i < 4; i++) {
        int f = tid + i * 256;
        int r = f >> 3, q = f & 7;
        cp16(sb + AQ0 + r * APITCH + q * 16,
             Qq + hbase + (size_t)(q0 + r) * 64 + q * 8);
    }
    // stage K,V tile 0 (2 arrays x 64 x 8 = 1024; 4/thread)
#pragma unroll
    for (int i = 0; i < 4; i++) {
        int f = tid + i * 256;
        int a = f >> 9, rem = f & 511, r = rem >> 3, q = rem & 7;
        const __half* s = (a ? Vv : Kk) + hbase + (size_t)r * 64 + q * 8;
        cp16(sb + AKV0 + a * AARR + r * APITCH + q * 16, s);
    }
    CP_COMMIT();

    int frow = lane & 15;
    int fko  = (lane >> 4) << 3;

    uint32_t aQ[4][4];
    float m0 = -1e30f, m1 = -1e30f, l0 = 0.f, l1 = 0.f;
    float oacc[8][4];
#pragma unroll
    for (int j = 0; j < 8; j++)
#pragma unroll
        for (int f = 0; f < 4; f++) oacc[j][f] = 0.f;

    const int NT = Sq / 64;
    for (int t = 0; t < NT; t++) {
        int buf = t & 1;
        if (t + 1 < NT) {
            int kt = (t + 1) * 64;
            uint32_t stg = sb + AKV0 + (buf ^ 1) * (2 * AARR);
#pragma unroll
            for (int i = 0; i < 4; i++) {
                int f = tid + i * 256;
                int a = f >> 9, rem = f & 511, r = rem >> 3, q = rem & 7;
                const __half* s = (a ? Vv : Kk) + hbase + (size_t)(kt + r) * 64 + q * 8;
                cp16(stg + a * AARR + r * APITCH + q * 16, s);
            }
            CP_COMMIT();
            CP_WAIT1();
        } else {
            CP_WAIT0();
        }
        __syncthreads();

        if (t == 0) {
#pragma unroll
            for (int c = 0; c < 4; c++) {
                int off = (warp * 16 + frow) * APITCH + (c * 16 + fko) * 2;
                ldsm_x4(aQ[c], sb + AQ0 + off);
            }
        }

        uint32_t aKB = sb + AKV0 + buf * (2 * AARR);
        uint32_t aVB = aKB + AARR;

        // ---- S = Q @ K^T (1 pass) ----
        float sacc[8][4];
#pragma unroll
        for (int j = 0; j < 8; j++)
#pragma unroll
            for (int f = 0; f < 4; f++) sacc[j][f] = 0.f;

#pragma unroll
        for (int kd = 0; kd < 4; kd++) {
#pragma unroll
            for (int bt = 0; bt < 4; bt++) {
                uint32_t kf[4];
                int off = (bt * 16 + frow) * APITCH + (kd * 16 + fko) * 2;
                ldsm_x4(kf, aKB + off);
#pragma unroll
                for (int h = 0; h < 2; h++) {
                    int nt = bt * 2 + h;
                    mma_f16(sacc[nt], aQ[kd], kf[h], kf[h + 2]);
                }
            }
        }

        // ---- online softmax ----
        float rmax0 = -1e30f, rmax1 = -1e30f;
#pragma unroll
        for (int j = 0; j < 8; j++) {
            rmax0 = fmaxf(rmax0, fmaxf(sacc[j][0], sacc[j][1]));
            rmax1 = fmaxf(rmax1, fmaxf(sacc[j][2], sacc[j][3]));
        }
        rmax0 = fmaxf(rmax0, __shfl_xor_sync(0xffffffffu, rmax0, 1));
        rmax0 = fmaxf(rmax0, __shfl_xor_sync(0xffffffffu, rmax0, 2));
        rmax1 = fmaxf(rmax1, __shfl_xor_sync(0xffffffffu, rmax1, 1));
        rmax1 = fmaxf(rmax1, __shfl_xor_sync(0xffffffffu, rmax1, 2));

        float mn0 = fmaxf(m0, 0.125f * rmax0);
        float mn1 = fmaxf(m1, 0.125f * rmax1);
        float corr0 = __expf(m0 - mn0);
        float corr1 = __expf(m1 - mn1);
        m0 = mn0; m1 = mn1;

        uint32_t pah[4][4];
        float ps0 = 0.f, ps1 = 0.f;
#pragma unroll
        for (int c = 0; c < 4; c++) {
#pragma unroll
            for (int u = 0; u < 2; u++) {
                int j = 2 * c + u;
                float p0 = __expf(0.125f * sacc[j][0] - mn0);
                float p1 = __expf(0.125f * sacc[j][1] - mn0);
                float p2 = __expf(0.125f * sacc[j][2] - mn1);
                float p3 = __expf(0.125f * sacc[j][3] - mn1);
                ps0 += p0 + p1;
                ps1 += p2 + p3;
                pah[c][2 * u + 0] = pack_f16x2(p0, p1);
                pah[c][2 * u + 1] = pack_f16x2(p2, p3);
            }
        }
        ps0 += __shfl_xor_sync(0xffffffffu, ps0, 1);
        ps0 += __shfl_xor_sync(0xffffffffu, ps0, 2);
        ps1 += __shfl_xor_sync(0xffffffffu, ps1, 1);
        ps1 += __shfl_xor_sync(0xffffffffu, ps1, 2);
        l0 = l0 * corr0 + ps0;
        l1 = l1 * corr1 + ps1;

#pragma unroll
        for (int j = 0; j < 8; j++) {
            oacc[j][0] *= corr0; oacc[j][1] *= corr0;
            oacc[j][2] *= corr1; oacc[j][3] *= corr1;
        }

        // ---- O += P @ V (1 pass) ----
#pragma unroll
        for (int c = 0; c < 4; c++) {
#pragma unroll
            for (int g = 0; g < 4; g++) {
                uint32_t vf[4];
                int off = (c * 16 + frow) * APITCH + (g * 16 + fko) * 2;
                ldsm_x4_t(vf, aVB + off);
#pragma unroll
                for (int h2 = 0; h2 < 2; h2++) {
                    int j = g * 2 + h2;
                    mma_f16(oacc[j], pah[c], vf[2 * h2], vf[2 * h2 + 1]);
                }
            }
        }
        __syncthreads();
    }

    // epilogue: single fp16
    float inv0 = 1.f / l0, inv1 = 1.f / l1;
    int tr = lane >> 2, tc = (lane & 3) * 2;
    int row0 = b * Sq + q0 + warp * 16 + tr;
#pragma unroll
    for (int j = 0; j < 8; j++) {
        int col = hh * 64 + j * 8 + tc;
        *(uint32_t*)(at + (size_t)row0 * Dm + col) =
            pack_f16x2(oacc[j][0] * inv0, oacc[j][1] * inv0);
        *(uint32_t*)(at + (size_t)(row0 + 8) * Dm + col) =
            pack_f16x2(oacc[j][2] * inv1, oacc[j][3] * inv1);
    }
}

// ===========================================================================
// Fused residual add + LayerNorm (+ optional fp16 output)
// ===========================================================================
__device__ __forceinline__ float block_allreduce(float v, float* sred)
{
#pragma unroll
    for (int o = 16; o; o >>= 1) v += __shfl_xor_sync(0xffffffffu, v, o);
    int w = threadIdx.x >> 5;
    if ((threadIdx.x & 31) == 0) sred[w] = v;
    __syncthreads();
    float t = (threadIdx.x < 8) ? sred[threadIdx.x] : 0.f;
    if (threadIdx.x < 32) {
#pragma unroll
        for (int o = 4; o; o >>= 1) t += __shfl_xor_sync(0xffffffffu, t, o);
        if (threadIdx.x == 0) sred[0] = t;
    }
    __syncthreads();
    float r = sred[0];
    __syncthreads();
    return r;
}

__global__ __launch_bounds__(256) void add_ln_kernel(
    const float* __restrict__ x, const float* __restrict__ y,
    const float* __restrict__ g, const float* __restrict__ bta,
    float* __restrict__ out, __half* __restrict__ oh)
{
    __shared__ float sred[8];
    int row = blockIdx.x;
    int tid = threadIdx.x;
    const float* xr = x + (size_t)row * Dm;
    const float* yr = y + (size_t)row * Dm;

    float4 xv = *(const float4*)(xr + tid * 4);
    float4 yv = *(const float4*)(yr + tid * 4);
    float v[4] = {xv.x + yv.x, xv.y + yv.y, xv.z + yv.z, xv.w + yv.w};

    float sum = v[0] + v[1] + v[2] + v[3];
    sum = block_allreduce(sum, sred);
    float mean = sum * (1.f / (float)Dm);

    float sq = 0.f;
#pragma unroll
    for (int i = 0; i < 4; i++) {
        float d = v[i] - mean;
        sq += d * d;
    }
    sq = block_allreduce(sq, sred);
    float inv = rsqrtf(sq * (1.f / (float)Dm) + 1e-5f);

    float4 gv = *(const float4*)(g + tid * 4);
    float4 bv = *(const float4*)(bta + tid * 4);
    float o[4];
    o[0] = (v[0] - mean) * inv * gv.x + bv.x;
    o[1] = (v[1] - mean) * inv * gv.y + bv.y;
    o[2] = (v[2] - mean) * inv * gv.z + bv.z;
    o[3] = (v[3] - mean) * inv * gv.w + bv.w;
    *(float4*)(out + (size_t)row * Dm + tid * 4) =
        make_float4(o[0], o[1], o[2], o[3]);

    if (oh) {
        uint2 hv;
        hv.x = pack_f16x2(o[0], o[1]);
        hv.y = pack_f16x2(o[2], o[3]);
        *(uint2*)(oh + (size_t)row * Dm + tid * 4) = hv;
    }
}

// ===========================================================================
extern "C" void kernel_launch(void* const* d_in, const int* in_sizes, int n_in,
                              void* d_out, int out_size)
{
    const float* x     = (const float*)d_in[0];
    const float* in_w  = (const float*)d_in[1];
    const float* in_b  = (const float*)d_in[2];
    const float* out_w = (const float*)d_in[3];
    const float* out_b = (const float*)d_in[4];
    const float* w1    = (const float*)d_in[5];
    const float* b1    = (const float*)d_in[6];
    const float* w2    = (const float*)d_in[7];
    const float* b2    = (const float*)d_in[8];
    const float* ln1g  = (const float*)d_in[9];
    const float* ln1b  = (const float*)d_in[10];
    const float* ln2g  = (const float*)d_in[11];
    const float* ln2b  = (const float*)d_in[12];
    float* out = (float*)d_out;

    float *qkv, *tmp, *hbuf;
    __half *xf, *wb, *qq, *kk, *vv, *at, *hf, *ff;
    cudaGetSymbolAddress((void**)&qkv, g_qkv);
    cudaGetSymbolAddress((void**)&tmp, g_tmp);
    cudaGetSymbolAddress((void**)&hbuf, g_h);
    cudaGetSymbolAddress((void**)&xf, g_xf);
    cudaGetSymbolAddress((void**)&wb, g_wb);
    cudaGetSymbolAddress((void**)&qq, g_qq);
    cudaGetSymbolAddress((void**)&kk, g_kk);
    cudaGetSymbolAddress((void**)&vv, g_vv);
    cudaGetSymbolAddress((void**)&at, g_at);
    cudaGetSymbolAddress((void**)&hf, g_hf);
    cudaGetSymbolAddress((void**)&ff, g_ff);

    cudaFuncSetAttribute(gemm_f16, cudaFuncAttributeMaxDynamicSharedMemorySize,
                         2 * GSTG);
    cudaFuncSetAttribute(attn_mma, cudaFuncAttributeMaxDynamicSharedMemorySize,
                         ATT_SMEM);

    dim3 tb(256);

    rope_table_kernel<<<(Sq * 32 + 255) / 256, tb>>>();
    cvt_f16<<<(Mrows * Dm / 4 + 255) / 256, tb>>>(x, xf, Mrows * Dm / 4);
    cvt_f16<<<(3 * Dm * Dm / 4 + 255) / 256, tb>>>(in_w, wb + OFF_INW, 3 * Dm * Dm / 4);
    cvt_f16<<<(Dm * Dm / 4 + 255) / 256, tb>>>(out_w, wb + OFF_OUTW, Dm * Dm / 4);
    cvt_f16<<<(Ff * Dm / 4 + 255) / 256, tb>>>(w1, wb + OFF_W1, Ff * Dm / 4);
    cvt_f16<<<(Dm * Ff / 4 + 255) / 256, tb>>>(w2, wb + OFF_W2, Dm * Ff / 4);

    // QKV projection -> fp32
    gemm_f16<<<dim3(3072 / 128, Mrows / 128), tb, 2 * GSTG>>>(
        xf, wb + OFF_INW, in_b, qkv, nullptr, 3 * Dm, Dm, 0);
    // RoPE + head-major fp16
    rope_f16_kernel<<<(Mrows * Hh * 8 + 255) / 256, tb>>>(qkv);
    // Attention -> fp16
    attn_mma<<<dim3(Sq / 128, Bq * Hh), tb, ATT_SMEM>>>(qq, kk, vv, at);
    // Output projection -> fp32
    gemm_f16<<<dim3(Dm / 128, Mrows / 128), tb, 2 * GSTG>>>(
        at, wb + OFF_OUTW, out_b, tmp, nullptr, Dm, Dm, 0);
    // LN1 -> fp32 h + fp16
    add_ln_kernel<<<Mrows, tb>>>(x, tmp, ln1g, ln1b, hbuf, hf);
    // FF1 + ReLU -> fp16
    gemm_f16<<<dim3(Ff / 128, Mrows / 128), tb, 2 * GSTG>>>(
        hf, wb + OFF_W1, b1, nullptr, ff, Ff, Dm, 1);
    // FF2 -> fp32
    gemm_f16<<<dim3(Dm / 128, Mrows / 128), tb, 2 * GSTG>>>(
        ff, wb + OFF_W2, b2, tmp, nullptr, Dm, Ff, 0);
    // LN2 -> out
    add_ln_kernel<<<Mrows, tb>>>(hbuf, tmp, ln2g, ln2b, out, nullptr);
}

// round 10
// speedup vs baseline: 6.0882x; 1.0165x over previous
#include <cuda_runtime.h>
#include <cuda_fp16.h>
#include <math.h>
#include <stdint.h>

// Problem constants
#define Bq 2
#define Sq 2048
#define Dm 1024
#define Ff 4096
#define Hh 16
#define Dhd 64
#define Mrows 4096  // B*S

// ---------------------------------------------------------------------------
// Scratch (device globals)
// ---------------------------------------------------------------------------
__device__ float g_tmp[(size_t)Mrows * Dm];
__device__ float g_h[(size_t)Mrows * Dm];
__device__ float g_cos[Sq * 32];
__device__ float g_sin[Sq * 32];

__device__ __half g_xf[(size_t)Mrows * Dm];
__device__ __half g_wb[12582912];
#define OFF_INW 0
#define OFF_OUTW 3145728
#define OFF_W1 4194304
#define OFF_W2 8388608
__device__ __half g_qq[(size_t)Bq * Hh * Sq * 64];
__device__ __half g_kk[(size_t)Bq * Hh * Sq * 64];
__device__ __half g_vv[(size_t)Bq * Hh * Sq * 64];
__device__ __half g_at[(size_t)Mrows * Dm];
__device__ __half g_hf[(size_t)Mrows * Dm];
__device__ __half g_ff[(size_t)Mrows * Ff];

__device__ __forceinline__ uint32_t smem_u32(const void* p) {
    uint32_t a;
    asm("{ .reg .u64 t; cvta.to.shared.u64 t, %1; cvt.u32.u64 %0, t; }"
        : "=r"(a) : "l"(p));
    return a;
}
__device__ __forceinline__ void cp16(uint32_t dst, const void* src) {
    asm volatile("cp.async.cg.shared.global [%0], [%1], 16;"
                 :: "r"(dst), "l"(src));
}
#define CP_COMMIT() asm volatile("cp.async.commit_group;" ::: "memory")
#define CP_WAIT1()  asm volatile("cp.async.wait_group 1;" ::: "memory")
#define CP_WAIT0()  asm volatile("cp.async.wait_group 0;" ::: "memory")

__device__ __forceinline__ void ldsm_x4(uint32_t* r, uint32_t addr)
{
    asm volatile("ldmatrix.sync.aligned.m8n8.x4.shared.b16 {%0,%1,%2,%3}, [%4];"
                 : "=r"(r[0]), "=r"(r[1]), "=r"(r[2]), "=r"(r[3]) : "r"(addr));
}
__device__ __forceinline__ void ldsm_x4_t(uint32_t* r, uint32_t addr)
{
    asm volatile("ldmatrix.sync.aligned.m8n8.x4.trans.shared.b16 {%0,%1,%2,%3}, [%4];"
                 : "=r"(r[0]), "=r"(r[1]), "=r"(r[2]), "=r"(r[3]) : "r"(addr));
}
__device__ __forceinline__ void mma_f16(float* c, const uint32_t* a,
                                        uint32_t b0, uint32_t b1)
{
    asm volatile(
        "mma.sync.aligned.m16n8k16.row.col.f32.f16.f16.f32 "
        "{%0,%1,%2,%3}, {%4,%5,%6,%7}, {%8,%9}, {%0,%1,%2,%3};"
        : "+f"(c[0]), "+f"(c[1]), "+f"(c[2]), "+f"(c[3])
        : "r"(a[0]), "r"(a[1]), "r"(a[2]), "r"(a[3]), "r"(b0), "r"(b1));
}
__device__ __forceinline__ uint32_t pack_f16x2(float lo, float hi)
{
    uint32_t r;
    asm("cvt.rn.f16x2.f32 %0, %1, %2;" : "=r"(r) : "f"(hi), "f"(lo));
    return r;
}

// ===========================================================================
// RoPE table kernel
// ===========================================================================
__global__ __launch_bounds__(256) void rope_table_kernel()
{
    int idx = blockIdx.x * 256 + threadIdx.x;
    if (idx >= Sq * 32) return;
    int s = idx >> 5;
    int i = idx & 31;
    double invd = exp(-(double)i * (9.210340371976184 / 32.0));
    float invf = (float)invd;
    float angf = (float)s * invf;
    double a = (double)angf;
    g_cos[idx] = (float)cos(a);
    g_sin[idx] = (float)sin(a);
}

// ===========================================================================
// Fused fp32 -> fp16 converter: x + 4 weight matrices in one launch.
// Segment boundaries in float4 units.
// ===========================================================================
#define SEG_X   1048576               // x: 4M elems
#define SEG_INW (SEG_X + 786432)      // in_w: 3M
#define SEG_OUW (SEG_INW + 262144)    // out_w: 1M
#define SEG_W1  (SEG_OUW + 1048576)   // w1: 4M
#define SEG_W2  (SEG_W1 + 1048576)    // w2: 4M -> total 4194304

__global__ __launch_bounds__(256) void cvt_all(
    const float* __restrict__ x, const float* __restrict__ in_w,
    const float* __restrict__ out_w, const float* __restrict__ w1,
    const float* __restrict__ w2)
{
    int idx = blockIdx.x * 256 + threadIdx.x;
    if (idx >= SEG_W2) return;
    const float* src;
    __half* dst;
    int base;
    if (idx < SEG_X)        { src = x;     dst = g_xf;            base = 0; }
    else if (idx < SEG_INW) { src = in_w;  dst = g_wb + OFF_INW;  base = SEG_X; }
    else if (idx < SEG_OUW) { src = out_w; dst = g_wb + OFF_OUTW; base = SEG_INW; }
    else if (idx < SEG_W1)  { src = w1;    dst = g_wb + OFF_W1;   base = SEG_OUW; }
    else                    { src = w2;    dst = g_wb + OFF_W2;   base = SEG_W1; }
    int off = idx - base;
    float4 v = *(const float4*)(src + (size_t)off * 4);
    uint2 hv;
    hv.x = pack_f16x2(v.x, v.y);
    hv.y = pack_f16x2(v.z, v.w);
    *(uint2*)(dst + (size_t)off * 4) = hv;
}

// ===========================================================================
// Pure fp16 1-pass GEMM: C = A @ W^T + bias, fp32 accum.
// CTA 128x128, BK=32, 8 warps. pitch 80B, cp.async double buffered.
// mode 0: fp32 out. mode 1: relu + fp16 out.
// mode 2: QKV epilogue — apply RoPE (q,k) in fp32 regs, write head-major fp16
//         Q/K/V. Thread column pairs (even,odd) coincide with RoPE pairs.
// ===========================================================================
#define GPITCH 80
#define GARR 10240
#define GSTG 20480

__global__ __launch_bounds__(256) void gemm_f16(
    const __half* __restrict__ A, const __half* __restrict__ W,
    const float* __restrict__ bias, float* __restrict__ Cf,
    __half* __restrict__ Ch, __half* __restrict__ Qd,
    __half* __restrict__ Kd, __half* __restrict__ Vd,
    int N, int K, int mode)
{
    extern __shared__ char dsm[];
    uint32_t sb = smem_u32(dsm);

    int tid = threadIdx.x;
    int lane = tid & 31, warp = tid >> 5;
    int wm = warp & 1;
    int wn = warp >> 1;
    int row0 = blockIdx.y * 128;
    int col0 = blockIdx.x * 128;

    float acc[4][4][4];
#pragma unroll
    for (int i = 0; i < 4; i++)
#pragma unroll
        for (int j = 0; j < 4; j++)
#pragma unroll
            for (int f = 0; f < 4; f++) acc[i][j][f] = 0.f;

    int frow = lane & 15;
    int fko  = (lane >> 4) << 3;

    int sa[4], sr[4], sq[4];
#pragma unroll
    for (int i = 0; i < 4; i++) {
        int f = tid + i * 256;
        sa[i] = f >> 9;
        int rem = f & 511;
        sr[i] = rem >> 2; sq[i] = rem & 3;
    }

    int nk = K >> 5;

#pragma unroll
    for (int i = 0; i < 4; i++) {
        const __half* s = sa[i] ? (W + (size_t)(col0 + sr[i]) * K)
                                : (A + (size_t)(row0 + sr[i]) * K);
        cp16(sb + sa[i] * GARR + sr[i] * GPITCH + sq[i] * 16, s + sq[i] * 8);
    }
    CP_COMMIT();

    for (int t = 0; t < nk; t++) {
        int buf = t & 1;
        if (t + 1 < nk) {
            int kt = (t + 1) * 32;
            uint32_t stg = sb + (buf ^ 1) * GSTG;
#pragma unroll
            for (int i = 0; i < 4; i++) {
                const __half* s = sa[i] ? (W + (size_t)(col0 + sr[i]) * K)
                                        : (A + (size_t)(row0 + sr[i]) * K);
                cp16(stg + sa[i] * GARR + sr[i] * GPITCH + sq[i] * 16,
                     s + kt + sq[i] * 8);
            }
            CP_COMMIT();
            CP_WAIT1();
        } else {
            CP_WAIT0();
        }
        __syncthreads();

        uint32_t aA = sb + buf * GSTG;
        uint32_t aW = aA + GARR;

#pragma unroll
        for (int s = 0; s < 2; s++) {
            int ko = s * 16 + fko;
            uint32_t af[4][4], bf[2][4];
#pragma unroll
            for (int mt = 0; mt < 4; mt++) {
                int off = (wm * 64 + mt * 16 + frow) * GPITCH + ko * 2;
                ldsm_x4(af[mt], aA + off);
            }
#pragma unroll
            for (int bt = 0; bt < 2; bt++) {
                int off = (wn * 32 + bt * 16 + frow) * GPITCH + ko * 2;
                ldsm_x4(bf[bt], aW + off);
            }
#pragma unroll
            for (int mt = 0; mt < 4; mt++)
#pragma unroll
                for (int bt = 0; bt < 2; bt++)
#pragma unroll
                    for (int h = 0; h < 2; h++) {
                        int nt = bt * 2 + h;
                        mma_f16(acc[mt][nt], af[mt], bf[bt][h], bf[bt][h + 2]);
                    }
        }
        __syncthreads();
    }

    int tr = lane >> 2, tc = (lane & 3) * 2;
#pragma unroll
    for (int mt = 0; mt < 4; mt++) {
#pragma unroll
        for (int nt = 0; nt < 4; nt++) {
            int col = col0 + wn * 32 + nt * 8 + tc;   // even
            float2 bv = *(const float2*)(bias + col);
            int r0 = row0 + wm * 64 + mt * 16 + tr;
            float o[4];
            o[0] = acc[mt][nt][0] + bv.x;
            o[1] = acc[mt][nt][1] + bv.y;
            o[2] = acc[mt][nt][2] + bv.x;
            o[3] = acc[mt][nt][3] + bv.y;
            if (mode == 0) {
                *(float2*)(Cf + (size_t)r0 * N + col) = make_float2(o[0], o[1]);
                *(float2*)(Cf + (size_t)(r0 + 8) * N + col) = make_float2(o[2], o[3]);
            } else if (mode == 1) {
#pragma unroll
                for (int i = 0; i < 4; i++) o[i] = fmaxf(o[i], 0.f);
                *(uint32_t*)(Ch + (size_t)r0 * N + col) = pack_f16x2(o[0], o[1]);
                *(uint32_t*)(Ch + (size_t)(r0 + 8) * N + col) = pack_f16x2(o[2], o[3]);
            } else {
                // mode 2: QKV + RoPE. col pair (col, col+1) = RoPE pair.
                int sector = col >> 10;          // 0=q 1=k 2=v (uniform per CTA)
                int cc = col & 1023;
                int h = cc >> 6;
                int e = cc & 63;
                int i = e >> 1;
#pragma unroll
                for (int rg = 0; rg < 2; rg++) {
                    int r = r0 + rg * 8;
                    int s = r & (Sq - 1);
                    int b = r >> 11;
                    float v0 = o[rg * 2], v1 = o[rg * 2 + 1];
                    if (sector < 2) {
                        float c = g_cos[s * 32 + i];
                        float sn = g_sin[s * 32 + i];
                        float re = v0 * c - v1 * sn;
                        float ro = v0 * sn + v1 * c;
                        v0 = re; v1 = ro;
                    }
                    __half* dst = (sector == 0) ? Qd : (sector == 1) ? Kd : Vd;
                    size_t d = ((size_t)(b * Hh + h) * Sq + s) * 64 + e;
                    *(uint32_t*)(dst + d) = pack_f16x2(v0, v1);
                }
            }
        }
    }
}

// ===========================================================================
// Flash attention, pure fp16: S = Q@K^T (1 pass), O = P@V (1 pass).
// smem: Q 128x144B; K,V 64x144B x 2 stages. Total 55296 bytes.
// ===========================================================================
#define APITCH 144
#define AQ0 0
#define AKV0 18432
#define AARR 9216
#define ATT_SMEM 55296

__global__ __launch_bounds__(256) void attn_mma(
    const __half* __restrict__ Qq, const __half* __restrict__ Kk,
    const __half* __restrict__ Vv, __half* __restrict__ at)
{
    extern __shared__ char dsm[];
    uint32_t sb = smem_u32(dsm);

    int tid = threadIdx.x;
    int lane = tid & 31, warp = tid >> 5;
    int bh = blockIdx.y;
    int b = bh >> 4, hh = bh & 15;
    int q0 = blockIdx.x * 128;

    size_t hbase = (size_t)bh * Sq * 64;

#pragma unroll
    for (int i = 0; i < 4; i++) {
        int f = tid + i * 256;
        int r = f >> 3, q = f & 7;
        cp16(sb + AQ0 + r * APITCH + q * 16,
             Qq + hbase + (size_t)(q0 + r) * 64 + q * 8);
    }
#pragma unroll
    for (int i = 0; i < 4; i++) {
        int f = tid + i * 256;
        int a = f >> 9, rem = f & 511, r = rem >> 3, q = rem & 7;
        const __half* s = (a ? Vv : Kk) + hbase + (size_t)r * 64 + q * 8;
        cp16(sb + AKV0 + a * AARR + r * APITCH + q * 16, s);
    }
    CP_COMMIT();

    int frow = lane & 15;
    int fko  = (lane >> 4) << 3;

    uint32_t aQ[4][4];
    float m0 = -1e30f, m1 = -1e30f, l0 = 0.f, l1 = 0.f;
    float oacc[8][4];
#pragma unroll
    for (int j = 0; j < 8; j++)
#pragma unroll
        for (int f = 0; f < 4; f++) oacc[j][f] = 0.f;

    const int NT = Sq / 64;
    for (int t = 0; t < NT; t++) {
        int buf = t & 1;
        if (t + 1 < NT) {
            int kt = (t + 1) * 64;
            uint32_t stg = sb + AKV0 + (buf ^ 1) * (2 * AARR);
#pragma unroll
            for (int i = 0; i < 4; i++) {
                int f = tid + i * 256;
                int a = f >> 9, rem = f & 511, r = rem >> 3, q = rem & 7;
                const __half* s = (a ? Vv : Kk) + hbase + (size_t)(kt + r) * 64 + q * 8;
                cp16(stg + a * AARR + r * APITCH + q * 16, s);
            }
            CP_COMMIT();
            CP_WAIT1();
        } else {
            CP_WAIT0();
        }
        __syncthreads();

        if (t == 0) {
#pragma unroll
            for (int c = 0; c < 4; c++) {
                int off = (warp * 16 + frow) * APITCH + (c * 16 + fko) * 2;
                ldsm_x4(aQ[c], sb + AQ0 + off);
            }
        }

        uint32_t aKB = sb + AKV0 + buf * (2 * AARR);
        uint32_t aVB = aKB + AARR;

        float sacc[8][4];
#pragma unroll
        for (int j = 0; j < 8; j++)
#pragma unroll
            for (int f = 0; f < 4; f++) sacc[j][f] = 0.f;

#pragma unroll
        for (int kd = 0; kd < 4; kd++) {
#pragma unroll
            for (int bt = 0; bt < 4; bt++) {
                uint32_t kf[4];
                int off = (bt * 16 + frow) * APITCH + (kd * 16 + fko) * 2;
                ldsm_x4(kf, aKB + off);
#pragma unroll
                for (int h = 0; h < 2; h++) {
                    int nt = bt * 2 + h;
                    mma_f16(sacc[nt], aQ[kd], kf[h], kf[h + 2]);
                }
            }
        }

        float rmax0 = -1e30f, rmax1 = -1e30f;
#pragma unroll
        for (int j = 0; j < 8; j++) {
            rmax0 = fmaxf(rmax0, fmaxf(sacc[j][0], sacc[j][1]));
            rmax1 = fmaxf(rmax1, fmaxf(sacc[j][2], sacc[j][3]));
        }
        rmax0 = fmaxf(rmax0, __shfl_xor_sync(0xffffffffu, rmax0, 1));
        rmax0 = fmaxf(rmax0, __shfl_xor_sync(0xffffffffu, rmax0, 2));
        rmax1 = fmaxf(rmax1, __shfl_xor_sync(0xffffffffu, rmax1, 1));
        rmax1 = fmaxf(rmax1, __shfl_xor_sync(0xffffffffu, rmax1, 2));

        float mn0 = fmaxf(m0, 0.125f * rmax0);
        float mn1 = fmaxf(m1, 0.125f * rmax1);
        float corr0 = __expf(m0 - mn0);
        float corr1 = __expf(m1 - mn1);
        m0 = mn0; m1 = mn1;

        uint32_t pah[4][4];
        float ps0 = 0.f, ps1 = 0.f;
#pragma unroll
        for (int c = 0; c < 4; c++) {
#pragma unroll
            for (int u = 0; u < 2; u++) {
                int j = 2 * c + u;
                float p0 = __expf(0.125f * sacc[j][0] - mn0);
                float p1 = __expf(0.125f * sacc[j][1] - mn0);
                float p2 = __expf(0.125f * sacc[j][2] - mn1);
                float p3 = __expf(0.125f * sacc[j][3] - mn1);
                ps0 += p0 + p1;
                ps1 += p2 + p3;
                pah[c][2 * u + 0] = pack_f16x2(p0, p1);
                pah[c][2 * u + 1] = pack_f16x2(p2, p3);
            }
        }
        ps0 += __shfl_xor_sync(0xffffffffu, ps0, 1);
        ps0 += __shfl_xor_sync(0xffffffffu, ps0, 2);
        ps1 += __shfl_xor_sync(0xffffffffu, ps1, 1);
        ps1 += __shfl_xor_sync(0xffffffffu, ps1, 2);
        l0 = l0 * corr0 + ps0;
        l1 = l1 * corr1 + ps1;

#pragma unroll
        for (int j = 0; j < 8; j++) {
            oacc[j][0] *= corr0; oacc[j][1] *= corr0;
            oacc[j][2] *= corr1; oacc[j][3] *= corr1;
        }

#pragma unroll
        for (int c = 0; c < 4; c++) {
#pragma unroll
            for (int g = 0; g < 4; g++) {
                uint32_t vf[4];
                int off = (c * 16 + frow) * APITCH + (g * 16 + fko) * 2;
                ldsm_x4_t(vf, aVB + off);
#pragma unroll
                for (int h2 = 0; h2 < 2; h2++) {
                    int j = g * 2 + h2;
                    mma_f16(oacc[j], pah[c], vf[2 * h2], vf[2 * h2 + 1]);
                }
            }
        }
        __syncthreads();
    }

    float inv0 = 1.f / l0, inv1 = 1.f / l1;
    int tr = lane >> 2, tc = (lane & 3) * 2;
    int row0 = b * Sq + q0 + warp * 16 + tr;
#pragma unroll
    for (int j = 0; j < 8; j++) {
        int col = hh * 64 + j * 8 + tc;
        *(uint32_t*)(at + (size_t)row0 * Dm + col) =
            pack_f16x2(oacc[j][0] * inv0, oacc[j][1] * inv0);
        *(uint32_t*)(at + (size_t)(row0 + 8) * Dm + col) =
            pack_f16x2(oacc[j][2] * inv1, oacc[j][3] * inv1);
    }
}

// ===========================================================================
// Fused residual add + LayerNorm (+ optional fp16 output)
// ===========================================================================
__device__ __forceinline__ float block_allreduce(float v, float* sred)
{
#pragma unroll
    for (int o = 16; o; o >>= 1) v += __shfl_xor_sync(0xffffffffu, v, o);
    int w = threadIdx.x >> 5;
    if ((threadIdx.x & 31) == 0) sred[w] = v;
    __syncthreads();
    float t = (threadIdx.x < 8) ? sred[threadIdx.x] : 0.f;
    if (threadIdx.x < 32) {
#pragma unroll
        for (int o = 4; o; o >>= 1) t += __shfl_xor_sync(0xffffffffu, t, o);
        if (threadIdx.x == 0) sred[0] = t;
    }
    __syncthreads();
    float r = sred[0];
    __syncthreads();
    return r;
}

__global__ __launch_bounds__(256) void add_ln_kernel(
    const float* __restrict__ x, const float* __restrict__ y,
    const float* __restrict__ g, const float* __restrict__ bta,
    float* __restrict__ out, __half* __restrict__ oh)
{
    __shared__ float sred[8];
    int row = blockIdx.x;
    int tid = threadIdx.x;
    const float* xr = x + (size_t)row * Dm;
    const float* yr = y + (size_t)row * Dm;

    float4 xv = *(const float4*)(xr + tid * 4);
    float4 yv = *(const float4*)(yr + tid * 4);
    float v[4] = {xv.x + yv.x, xv.y + yv.y, xv.z + yv.z, xv.w + yv.w};

    float sum = v[0] + v[1] + v[2] + v[3];
    sum = block_allreduce(sum, sred);
    float mean = sum * (1.f / (float)Dm);

    float sq = 0.f;
#pragma unroll
    for (int i = 0; i < 4; i++) {
        float d = v[i] - mean;
        sq += d * d;
    }
    sq = block_allreduce(sq, sred);
    float inv = rsqrtf(sq * (1.f / (float)Dm) + 1e-5f);

    float4 gv = *(const float4*)(g + tid * 4);
    float4 bv = *(const float4*)(bta + tid * 4);
    float o[4];
    o[0] = (v[0] - mean) * inv * gv.x + bv.x;
    o[1] = (v[1] - mean) * inv * gv.y + bv.y;
    o[2] = (v[2] - mean) * inv * gv.z + bv.z;
    o[3] = (v[3] - mean) * inv * gv.w + bv.w;
    *(float4*)(out + (size_t)row * Dm + tid * 4) =
        make_float4(o[0], o[1], o[2], o[3]);

    if (oh) {
        uint2 hv;
        hv.x = pack_f16x2(o[0], o[1]);
        hv.y = pack_f16x2(o[2], o[3]);
        *(uint2*)(oh + (size_t)row * Dm + tid * 4) = hv;
    }
}

// ===========================================================================
extern "C" void kernel_launch(void* const* d_in, const int* in_sizes, int n_in,
                              void* d_out, int out_size)
{
    const float* x     = (const float*)d_in[0];
    const float* in_w  = (const float*)d_in[1];
    const float* in_b  = (const float*)d_in[2];
    const float* out_w = (const float*)d_in[3];
    const float* out_b = (const float*)d_in[4];
    const float* w1    = (const float*)d_in[5];
    const float* b1    = (const float*)d_in[6];
    const float* w2    = (const float*)d_in[7];
    const float* b2    = (const float*)d_in[8];
    const float* ln1g  = (const float*)d_in[9];
    const float* ln1b  = (const float*)d_in[10];
    const float* ln2g  = (const float*)d_in[11];
    const float* ln2b  = (const float*)d_in[12];
    float* out = (float*)d_out;

    float *tmp, *hbuf;
    __half *xf, *wb, *qq, *kk, *vv, *at, *hf, *ff;
    cudaGetSymbolAddress((void**)&tmp, g_tmp);
    cudaGetSymbolAddress((void**)&hbuf, g_h);
    cudaGetSymbolAddress((void**)&xf, g_xf);
    cudaGetSymbolAddress((void**)&wb, g_wb);
    cudaGetSymbolAddress((void**)&qq, g_qq);
    cudaGetSymbolAddress((void**)&kk, g_kk);
    cudaGetSymbolAddress((void**)&vv, g_vv);
    cudaGetSymbolAddress((void**)&at, g_at);
    cudaGetSymbolAddress((void**)&hf, g_hf);
    cudaGetSymbolAddress((void**)&ff, g_ff);

    cudaFuncSetAttribute(gemm_f16, cudaFuncAttributeMaxDynamicSharedMemorySize,
                         2 * GSTG);
    cudaFuncSetAttribute(attn_mma, cudaFuncAttributeMaxDynamicSharedMemorySize,
                         ATT_SMEM);

    dim3 tb(256);

    rope_table_kernel<<<(Sq * 32 + 255) / 256, tb>>>();
    cvt_all<<<(SEG_W2 + 255) / 256, tb>>>(x, in_w, out_w, w1, w2);

    // QKV projection + fused RoPE -> head-major fp16 Q/K/V
    gemm_f16<<<dim3(3072 / 128, Mrows / 128), tb, 2 * GSTG>>>(
        xf, wb + OFF_INW, in_b, nullptr, nullptr, qq, kk, vv, 3 * Dm, Dm, 2);
    // Attention -> fp16
    attn_mma<<<dim3(Sq / 128, Bq * Hh), tb, ATT_SMEM>>>(qq, kk, vv, at);
    // Output projection -> fp32
    gemm_f16<<<dim3(Dm / 128, Mrows / 128), tb, 2 * GSTG>>>(
        at, wb + OFF_OUTW, out_b, tmp, nullptr, nullptr, nullptr, nullptr,
        Dm, Dm, 0);
    // LN1 -> fp32 h + fp16
    add_ln_kernel<<<Mrows, tb>>>(x, tmp, ln1g, ln1b, hbuf, hf);
    // FF1 + ReLU -> fp16
    gemm_f16<<<dim3(Ff / 128, Mrows / 128), tb, 2 * GSTG>>>(
        hf, wb + OFF_W1, b1, nullptr, ff, nullptr, nullptr, nullptr,
        Ff, Dm, 1);
    // FF2 -> fp32
    gemm_f16<<<dim3(Dm / 128, Mrows / 128), tb, 2 * GSTG>>>(
        ff, wb + OFF_W2, b2, tmp, nullptr, nullptr, nullptr, nullptr,
        Dm, Ff, 0);
    // LN2 -> out
    add_ln_kernel<<<Mrows, tb>>>(hbuf, tmp, ln2g, ln2b, out, nullptr);
}

// round 11
// speedup vs baseline: 6.2005x; 1.0184x over previous
#include <cuda_runtime.h>
#include <cuda_fp16.h>
#include <math.h>
#include <stdint.h>

// Problem constants
#define Bq 2
#define Sq 2048
#define Dm 1024
#define Ff 4096
#define Hh 16
#define Dhd 64
#define Mrows 4096  // B*S

// ---------------------------------------------------------------------------
// Scratch (device globals)
// ---------------------------------------------------------------------------
__device__ float g_tmp[(size_t)Mrows * Dm];
__device__ float g_h[(size_t)Mrows * Dm];
__device__ float g_cos[Sq * 32];
__device__ float g_sin[Sq * 32];

__device__ __half g_xf[(size_t)Mrows * Dm];
__device__ __half g_wb[12582912];
#define OFF_INW 0
#define OFF_OUTW 3145728
#define OFF_W1 4194304
#define OFF_W2 8388608
__device__ __half g_qq[(size_t)Bq * Hh * Sq * 64];
__device__ __half g_kk[(size_t)Bq * Hh * Sq * 64];
__device__ __half g_vv[(size_t)Bq * Hh * Sq * 64];
__device__ __half g_at[(size_t)Mrows * Dm];
__device__ __half g_hf[(size_t)Mrows * Dm];
__device__ __half g_ff[(size_t)Mrows * Ff];

__device__ __forceinline__ uint32_t smem_u32(const void* p) {
    uint32_t a;
    asm("{ .reg .u64 t; cvta.to.shared.u64 t, %1; cvt.u32.u64 %0, t; }"
        : "=r"(a) : "l"(p));
    return a;
}
__device__ __forceinline__ void cp16(uint32_t dst, const void* src) {
    asm volatile("cp.async.cg.shared.global [%0], [%1], 16;"
                 :: "r"(dst), "l"(src));
}
#define CP_COMMIT() asm volatile("cp.async.commit_group;" ::: "memory")
#define CP_WAIT1()  asm volatile("cp.async.wait_group 1;" ::: "memory")
#define CP_WAIT0()  asm volatile("cp.async.wait_group 0;" ::: "memory")

__device__ __forceinline__ void ldsm_x4(uint32_t* r, uint32_t addr)
{
    asm volatile("ldmatrix.sync.aligned.m8n8.x4.shared.b16 {%0,%1,%2,%3}, [%4];"
                 : "=r"(r[0]), "=r"(r[1]), "=r"(r[2]), "=r"(r[3]) : "r"(addr));
}
__device__ __forceinline__ void ldsm_x4_t(uint32_t* r, uint32_t addr)
{
    asm volatile("ldmatrix.sync.aligned.m8n8.x4.trans.shared.b16 {%0,%1,%2,%3}, [%4];"
                 : "=r"(r[0]), "=r"(r[1]), "=r"(r[2]), "=r"(r[3]) : "r"(addr));
}
__device__ __forceinline__ void mma_f16(float* c, const uint32_t* a,
                                        uint32_t b0, uint32_t b1)
{
    asm volatile(
        "mma.sync.aligned.m16n8k16.row.col.f32.f16.f16.f32 "
        "{%0,%1,%2,%3}, {%4,%5,%6,%7}, {%8,%9}, {%0,%1,%2,%3};"
        : "+f"(c[0]), "+f"(c[1]), "+f"(c[2]), "+f"(c[3])
        : "r"(a[0]), "r"(a[1]), "r"(a[2]), "r"(a[3]), "r"(b0), "r"(b1));
}
__device__ __forceinline__ uint32_t pack_f16x2(float lo, float hi)
{
    uint32_t r;
    asm("cvt.rn.f16x2.f32 %0, %1, %2;" : "=r"(r) : "f"(hi), "f"(lo));
    return r;
}

// ===========================================================================
// RoPE table kernel
// ===========================================================================
__global__ __launch_bounds__(256) void rope_table_kernel()
{
    int idx = blockIdx.x * 256 + threadIdx.x;
    if (idx >= Sq * 32) return;
    int s = idx >> 5;
    int i = idx & 31;
    double invd = exp(-(double)i * (9.210340371976184 / 32.0));
    float invf = (float)invd;
    float angf = (float)s * invf;
    double a = (double)angf;
    g_cos[idx] = (float)cos(a);
    g_sin[idx] = (float)sin(a);
}

// ===========================================================================
// Fused fp32 -> fp16 converter: x + 4 weight matrices in one launch.
// ===========================================================================
#define SEG_X   1048576
#define SEG_INW (SEG_X + 786432)
#define SEG_OUW (SEG_INW + 262144)
#define SEG_W1  (SEG_OUW + 1048576)
#define SEG_W2  (SEG_W1 + 1048576)

__global__ __launch_bounds__(256) void cvt_all(
    const float* __restrict__ x, const float* __restrict__ in_w,
    const float* __restrict__ out_w, const float* __restrict__ w1,
    const float* __restrict__ w2)
{
    int idx = blockIdx.x * 256 + threadIdx.x;
    if (idx >= SEG_W2) return;
    const float* src;
    __half* dst;
    int base;
    if (idx < SEG_X)        { src = x;     dst = g_xf;            base = 0; }
    else if (idx < SEG_INW) { src = in_w;  dst = g_wb + OFF_INW;  base = SEG_X; }
    else if (idx < SEG_OUW) { src = out_w; dst = g_wb + OFF_OUTW; base = SEG_INW; }
    else if (idx < SEG_W1)  { src = w1;    dst = g_wb + OFF_W1;   base = SEG_OUW; }
    else                    { src = w2;    dst = g_wb + OFF_W2;   base = SEG_W1; }
    int off = idx - base;
    float4 v = *(const float4*)(src + (size_t)off * 4);
    uint2 hv;
    hv.x = pack_f16x2(v.x, v.y);
    hv.y = pack_f16x2(v.z, v.w);
    *(uint2*)(dst + (size_t)off * 4) = hv;
}

// ===========================================================================
// Pure fp16 1-pass GEMM, 3-stage cp.async pipeline.
// CTA 128x128, BK=32, 8 warps. pitch 80B. smem = 3 x 20480 = 61440 B.
// Prefetch for tile t+2 is issued AFTER the barrier at tile t, targeting the
// buffer last read at tile t-1 (all reads complete before that barrier).
// mode 0: fp32 out. mode 1: relu + fp16 out. mode 2: QKV + RoPE epilogue.
// ===========================================================================
#define GPITCH 80
#define GARR 10240
#define GSTG 20480

__global__ __launch_bounds__(256) void gemm_f16(
    const __half* __restrict__ A, const __half* __restrict__ W,
    const float* __restrict__ bias, float* __restrict__ Cf,
    __half* __restrict__ Ch, __half* __restrict__ Qd,
    __half* __restrict__ Kd, __half* __restrict__ Vd,
    int N, int K, int mode)
{
    extern __shared__ char dsm[];
    uint32_t sb = smem_u32(dsm);

    int tid = threadIdx.x;
    int lane = tid & 31, warp = tid >> 5;
    int wm = warp & 1;
    int wn = warp >> 1;
    int row0 = blockIdx.y * 128;
    int col0 = blockIdx.x * 128;

    float acc[4][4][4];
#pragma unroll
    for (int i = 0; i < 4; i++)
#pragma unroll
        for (int j = 0; j < 4; j++)
#pragma unroll
            for (int f = 0; f < 4; f++) acc[i][j][f] = 0.f;

    int frow = lane & 15;
    int fko  = (lane >> 4) << 3;

    // staging map: 1024 16B-chunks per stage, 4 per thread
    const __half* gsrc[4];
    uint32_t soff[4];
#pragma unroll
    for (int i = 0; i < 4; i++) {
        int f = tid + i * 256;
        int a = f >> 9;
        int rem = f & 511;
        int r = rem >> 2, q = rem & 3;
        gsrc[i] = (a ? (W + (size_t)(col0 + r) * K)
                     : (A + (size_t)(row0 + r) * K)) + q * 8;
        soff[i] = a * GARR + r * GPITCH + q * 16;
    }

    int nk = K >> 5;

    // prologue: stages for tiles 0 and 1
#pragma unroll
    for (int p = 0; p < 2; p++) {
        uint32_t stg = sb + p * GSTG;
#pragma unroll
        for (int i = 0; i < 4; i++)
            cp16(stg + soff[i], gsrc[i] + p * 32);
        CP_COMMIT();
    }

    int buf = 0;
    for (int t = 0; t < nk; t++) {
        if (t + 1 < nk) CP_WAIT1(); else CP_WAIT0();
        __syncthreads();
        if (t + 2 < nk) {
            int pbuf = buf + 2; if (pbuf >= 3) pbuf -= 3;
            uint32_t stg = sb + pbuf * GSTG;
            int kt = (t + 2) * 32;
#pragma unroll
            for (int i = 0; i < 4; i++)
                cp16(stg + soff[i], gsrc[i] + kt);
            CP_COMMIT();
        }

        uint32_t aA = sb + buf * GSTG;
        uint32_t aW = aA + GARR;

#pragma unroll
        for (int s = 0; s < 2; s++) {
            int ko = s * 16 + fko;
            uint32_t af[4][4], bf[2][4];
#pragma unroll
            for (int mt = 0; mt < 4; mt++) {
                int off = (wm * 64 + mt * 16 + frow) * GPITCH + ko * 2;
                ldsm_x4(af[mt], aA + off);
            }
#pragma unroll
            for (int bt = 0; bt < 2; bt++) {
                int off = (wn * 32 + bt * 16 + frow) * GPITCH + ko * 2;
                ldsm_x4(bf[bt], aW + off);
            }
#pragma unroll
            for (int mt = 0; mt < 4; mt++)
#pragma unroll
                for (int bt = 0; bt < 2; bt++)
#pragma unroll
                    for (int h = 0; h < 2; h++) {
                        int nt = bt * 2 + h;
                        mma_f16(acc[mt][nt], af[mt], bf[bt][h], bf[bt][h + 2]);
                    }
        }
        if (++buf == 3) buf = 0;
    }

    int tr = lane >> 2, tc = (lane & 3) * 2;
#pragma unroll
    for (int mt = 0; mt < 4; mt++) {
#pragma unroll
        for (int nt = 0; nt < 4; nt++) {
            int col = col0 + wn * 32 + nt * 8 + tc;
            float2 bv = *(const float2*)(bias + col);
            int r0 = row0 + wm * 64 + mt * 16 + tr;
            float o[4];
            o[0] = acc[mt][nt][0] + bv.x;
            o[1] = acc[mt][nt][1] + bv.y;
            o[2] = acc[mt][nt][2] + bv.x;
            o[3] = acc[mt][nt][3] + bv.y;
            if (mode == 0) {
                *(float2*)(Cf + (size_t)r0 * N + col) = make_float2(o[0], o[1]);
                *(float2*)(Cf + (size_t)(r0 + 8) * N + col) = make_float2(o[2], o[3]);
            } else if (mode == 1) {
#pragma unroll
                for (int i = 0; i < 4; i++) o[i] = fmaxf(o[i], 0.f);
                *(uint32_t*)(Ch + (size_t)r0 * N + col) = pack_f16x2(o[0], o[1]);
                *(uint32_t*)(Ch + (size_t)(r0 + 8) * N + col) = pack_f16x2(o[2], o[3]);
            } else {
                int sector = col >> 10;
                int cc = col & 1023;
                int h = cc >> 6;
                int e = cc & 63;
                int i = e >> 1;
#pragma unroll
                for (int rg = 0; rg < 2; rg++) {
                    int r = r0 + rg * 8;
                    int s = r & (Sq - 1);
                    int b = r >> 11;
                    float v0 = o[rg * 2], v1 = o[rg * 2 + 1];
                    if (sector < 2) {
                        float c = g_cos[s * 32 + i];
                        float sn = g_sin[s * 32 + i];
                        float re = v0 * c - v1 * sn;
                        float ro = v0 * sn + v1 * c;
                        v0 = re; v1 = ro;
                    }
                    __half* dst = (sector == 0) ? Qd : (sector == 1) ? Kd : Vd;
                    size_t d = ((size_t)(b * Hh + h) * Sq + s) * 64 + e;
                    *(uint32_t*)(dst + d) = pack_f16x2(v0, v1);
                }
            }
        }
    }
}

// ===========================================================================
// Flash attention, pure fp16, 3-stage cp.async K/V pipeline.
// smem: Q 128x144B (18432) + 3 stages x (K+V = 18432) = 73728 bytes.
// ===========================================================================
#define APITCH 144
#define AQ0 0
#define AKV0 18432
#define AARR 9216
#define KVSTG 18432
#define ATT_SMEM 73728

__global__ __launch_bounds__(256) void attn_mma(
    const __half* __restrict__ Qq, const __half* __restrict__ Kk,
    const __half* __restrict__ Vv, __half* __restrict__ at)
{
    extern __shared__ char dsm[];
    uint32_t sb = smem_u32(dsm);

    int tid = threadIdx.x;
    int lane = tid & 31, warp = tid >> 5;
    int bh = blockIdx.y;
    int b = bh >> 4, hh = bh & 15;
    int q0 = blockIdx.x * 128;

    size_t hbase = (size_t)bh * Sq * 64;

    // KV staging map: 1024 chunks per stage, 4 per thread
    const __half* kvsrc[4];
    uint32_t kvoff[4];
#pragma unroll
    for (int i = 0; i < 4; i++) {
        int f = tid + i * 256;
        int a = f >> 9, rem = f & 511, r = rem >> 3, q = rem & 7;
        kvsrc[i] = (a ? Vv : Kk) + hbase + (size_t)r * 64 + q * 8;
        kvoff[i] = a * AARR + r * APITCH + q * 16;
    }

    // stage Q + KV tile 0 (group 0)
#pragma unroll
    for (int i = 0; i < 4; i++) {
        int f = tid + i * 256;
        int r = f >> 3, q = f & 7;
        cp16(sb + AQ0 + r * APITCH + q * 16,
             Qq + hbase + (size_t)(q0 + r) * 64 + q * 8);
    }
#pragma unroll
    for (int i = 0; i < 4; i++)
        cp16(sb + AKV0 + kvoff[i], kvsrc[i]);
    CP_COMMIT();
    // KV tile 1 (group 1)
#pragma unroll
    for (int i = 0; i < 4; i++)
        cp16(sb + AKV0 + KVSTG + kvoff[i], kvsrc[i] + (size_t)64 * 64);
    CP_COMMIT();

    int frow = lane & 15;
    int fko  = (lane >> 4) << 3;

    uint32_t aQ[4][4];
    float m0 = -1e30f, m1 = -1e30f, l0 = 0.f, l1 = 0.f;
    float oacc[8][4];
#pragma unroll
    for (int j = 0; j < 8; j++)
#pragma unroll
        for (int f = 0; f < 4; f++) oacc[j][f] = 0.f;

    const int NT = Sq / 64;
    int buf = 0;
    for (int t = 0; t < NT; t++) {
        if (t + 1 < NT) CP_WAIT1(); else CP_WAIT0();
        __syncthreads();
        if (t + 2 < NT) {
            int pbuf = buf + 2; if (pbuf >= 3) pbuf -= 3;
            uint32_t stg = sb + AKV0 + pbuf * KVSTG;
            size_t kofs = (size_t)(t + 2) * 64 * 64;
#pragma unroll
            for (int i = 0; i < 4; i++)
                cp16(stg + kvoff[i], kvsrc[i] + kofs);
            CP_COMMIT();
        }

        if (t == 0) {
#pragma unroll
            for (int c = 0; c < 4; c++) {
                int off = (warp * 16 + frow) * APITCH + (c * 16 + fko) * 2;
                ldsm_x4(aQ[c], sb + AQ0 + off);
            }
        }

        uint32_t aKB = sb + AKV0 + buf * KVSTG;
        uint32_t aVB = aKB + AARR;

        float sacc[8][4];
#pragma unroll
        for (int j = 0; j < 8; j++)
#pragma unroll
            for (int f = 0; f < 4; f++) sacc[j][f] = 0.f;

#pragma unroll
        for (int kd = 0; kd < 4; kd++) {
#pragma unroll
            for (int bt = 0; bt < 4; bt++) {
                uint32_t kf[4];
                int off = (bt * 16 + frow) * APITCH + (kd * 16 + fko) * 2;
                ldsm_x4(kf, aKB + off);
#pragma unroll
                for (int h = 0; h < 2; h++) {
                    int nt = bt * 2 + h;
                    mma_f16(sacc[nt], aQ[kd], kf[h], kf[h + 2]);
                }
            }
        }

        float rmax0 = -1e30f, rmax1 = -1e30f;
#pragma unroll
        for (int j = 0; j < 8; j++) {
            rmax0 = fmaxf(rmax0, fmaxf(sacc[j][0], sacc[j][1]));
            rmax1 = fmaxf(rmax1, fmaxf(sacc[j][2], sacc[j][3]));
        }
        rmax0 = fmaxf(rmax0, __shfl_xor_sync(0xffffffffu, rmax0, 1));
        rmax0 = fmaxf(rmax0, __shfl_xor_sync(0xffffffffu, rmax0, 2));
        rmax1 = fmaxf(rmax1, __shfl_xor_sync(0xffffffffu, rmax1, 1));
        rmax1 = fmaxf(rmax1, __shfl_xor_sync(0xffffffffu, rmax1, 2));

        float mn0 = fmaxf(m0, 0.125f * rmax0);
        float mn1 = fmaxf(m1, 0.125f * rmax1);
        float corr0 = __expf(m0 - mn0);
        float corr1 = __expf(m1 - mn1);
        m0 = mn0; m1 = mn1;

        uint32_t pah[4][4];
        float ps0 = 0.f, ps1 = 0.f;
#pragma unroll
        for (int c = 0; c < 4; c++) {
#pragma unroll
            for (int u = 0; u < 2; u++) {
                int j = 2 * c + u;
                float p0 = __expf(0.125f * sacc[j][0] - mn0);
                float p1 = __expf(0.125f * sacc[j][1] - mn0);
                float p2 = __expf(0.125f * sacc[j][2] - mn1);
                float p3 = __expf(0.125f * sacc[j][3] - mn1);
                ps0 += p0 + p1;
                ps1 += p2 + p3;
                pah[c][2 * u + 0] = pack_f16x2(p0, p1);
                pah[c][2 * u + 1] = pack_f16x2(p2, p3);
            }
        }
        ps0 += __shfl_xor_sync(0xffffffffu, ps0, 1);
        ps0 += __shfl_xor_sync(0xffffffffu, ps0, 2);
        ps1 += __shfl_xor_sync(0xffffffffu, ps1, 1);
        ps1 += __shfl_xor_sync(0xffffffffu, ps1, 2);
        l0 = l0 * corr0 + ps0;
        l1 = l1 * corr1 + ps1;

#pragma unroll
        for (int j = 0; j < 8; j++) {
            oacc[j][0] *= corr0; oacc[j][1] *= corr0;
            oacc[j][2] *= corr1; oacc[j][3] *= corr1;
        }

#pragma unroll
        for (int c = 0; c < 4; c++) {
#pragma unroll
            for (int g = 0; g < 4; g++) {
                uint32_t vf[4];
                int off = (c * 16 + frow) * APITCH + (g * 16 + fko) * 2;
                ldsm_x4_t(vf, aVB + off);
#pragma unroll
                for (int h2 = 0; h2 < 2; h2++) {
                    int j = g * 2 + h2;
                    mma_f16(oacc[j], pah[c], vf[2 * h2], vf[2 * h2 + 1]);
                }
            }
        }
        if (++buf == 3) buf = 0;
    }

    float inv0 = 1.f / l0, inv1 = 1.f / l1;
    int tr = lane >> 2, tc = (lane & 3) * 2;
    int row0 = b * Sq + q0 + warp * 16 + tr;
#pragma unroll
    for (int j = 0; j < 8; j++) {
        int col = hh * 64 + j * 8 + tc;
        *(uint32_t*)(at + (size_t)row0 * Dm + col) =
            pack_f16x2(oacc[j][0] * inv0, oacc[j][1] * inv0);
        *(uint32_t*)(at + (size_t)(row0 + 8) * Dm + col) =
            pack_f16x2(oacc[j][2] * inv1, oacc[j][3] * inv1);
    }
}

// ===========================================================================
// Fused residual add + LayerNorm (+ optional fp16 output)
// ===========================================================================
__device__ __forceinline__ float block_allreduce(float v, float* sred)
{
#pragma unroll
    for (int o = 16; o; o >>= 1) v += __shfl_xor_sync(0xffffffffu, v, o);
    int w = threadIdx.x >> 5;
    if ((threadIdx.x & 31) == 0) sred[w] = v;
    __syncthreads();
    float t = (threadIdx.x < 8) ? sred[threadIdx.x] : 0.f;
    if (threadIdx.x < 32) {
#pragma unroll
        for (int o = 4; o; o >>= 1) t += __shfl_xor_sync(0xffffffffu, t, o);
        if (threadIdx.x == 0) sred[0] = t;
    }
    __syncthreads();
    float r = sred[0];
    __syncthreads();
    return r;
}

__global__ __launch_bounds__(256) void add_ln_kernel(
    const float* __restrict__ x, const float* __restrict__ y,
    const float* __restrict__ g, const float* __restrict__ bta,
    float* __restrict__ out, __half* __restrict__ oh)
{
    __shared__ float sred[8];
    int row = blockIdx.x;
    int tid = threadIdx.x;
    const float* xr = x + (size_t)row * Dm;
    const float* yr = y + (size_t)row * Dm;

    float4 xv = *(const float4*)(xr + tid * 4);
    float4 yv = *(const float4*)(yr + tid * 4);
    float v[4] = {xv.x + yv.x, xv.y + yv.y, xv.z + yv.z, xv.w + yv.w};

    float sum = v[0] + v[1] + v[2] + v[3];
    sum = block_allreduce(sum, sred);
    float mean = sum * (1.f / (float)Dm);

    float sq = 0.f;
#pragma unroll
    for (int i = 0; i < 4; i++) {
        float d = v[i] - mean;
        sq += d * d;
    }
    sq = block_allreduce(sq, sred);
    float inv = rsqrtf(sq * (1.f / (float)Dm) + 1e-5f);

    float4 gv = *(const float4*)(g + tid * 4);
    float4 bv = *(const float4*)(bta + tid * 4);
    float o[4];
    o[0] = (v[0] - mean) * inv * gv.x + bv.x;
    o[1] = (v[1] - mean) * inv * gv.y + bv.y;
    o[2] = (v[2] - mean) * inv * gv.z + bv.z;
    o[3] = (v[3] - mean) * inv * gv.w + bv.w;
    *(float4*)(out + (size_t)row * Dm + tid * 4) =
        make_float4(o[0], o[1], o[2], o[3]);

    if (oh) {
        uint2 hv;
        hv.x = pack_f16x2(o[0], o[1]);
        hv.y = pack_f16x2(o[2], o[3]);
        *(uint2*)(oh + (size_t)row * Dm + tid * 4) = hv;
    }
}

// ===========================================================================
extern "C" void kernel_launch(void* const* d_in, const int* in_sizes, int n_in,
                              void* d_out, int out_size)
{
    const float* x     = (const float*)d_in[0];
    const float* in_w  = (const float*)d_in[1];
    const float* in_b  = (const float*)d_in[2];
    const float* out_w = (const float*)d_in[3];
    const float* out_b = (const float*)d_in[4];
    const float* w1    = (const float*)d_in[5];
    const float* b1    = (const float*)d_in[6];
    const float* w2    = (const float*)d_in[7];
    const float* b2    = (const float*)d_in[8];
    const float* ln1g  = (const float*)d_in[9];
    const float* ln1b  = (const float*)d_in[10];
    const float* ln2g  = (const float*)d_in[11];
    const float* ln2b  = (const float*)d_in[12];
    float* out = (float*)d_out;

    float *tmp, *hbuf;
    __half *xf, *wb, *qq, *kk, *vv, *at, *hf, *ff;
    cudaGetSymbolAddress((void**)&tmp, g_tmp);
    cudaGetSymbolAddress((void**)&hbuf, g_h);
    cudaGetSymbolAddress((void**)&xf, g_xf);
    cudaGetSymbolAddress((void**)&wb, g_wb);
    cudaGetSymbolAddress((void**)&qq, g_qq);
    cudaGetSymbolAddress((void**)&kk, g_kk);
    cudaGetSymbolAddress((void**)&vv, g_vv);
    cudaGetSymbolAddress((void**)&at, g_at);
    cudaGetSymbolAddress((void**)&hf, g_hf);
    cudaGetSymbolAddress((void**)&ff, g_ff);

    cudaFuncSetAttribute(gemm_f16, cudaFuncAttributeMaxDynamicSharedMemorySize,
                         3 * GSTG);
    cudaFuncSetAttribute(attn_mma, cudaFuncAttributeMaxDynamicSharedMemorySize,
                         ATT_SMEM);

    dim3 tb(256);

    rope_table_kernel<<<(Sq * 32 + 255) / 256, tb>>>();
    cvt_all<<<(SEG_W2 + 255) / 256, tb>>>(x, in_w, out_w, w1, w2);

    // QKV projection + fused RoPE -> head-major fp16 Q/K/V
    gemm_f16<<<dim3(3072 / 128, Mrows / 128), tb, 3 * GSTG>>>(
        xf, wb + OFF_INW, in_b, nullptr, nullptr, qq, kk, vv, 3 * Dm, Dm, 2);
    // Attention -> fp16
    attn_mma<<<dim3(Sq / 128, Bq * Hh), tb, ATT_SMEM>>>(qq, kk, vv, at);
    // Output projection -> fp32
    gemm_f16<<<dim3(Dm / 128, Mrows / 128), tb, 3 * GSTG>>>(
        at, wb + OFF_OUTW, out_b, tmp, nullptr, nullptr, nullptr, nullptr,
        Dm, Dm, 0);
    // LN1 -> fp32 h + fp16
    add_ln_kernel<<<Mrows, tb>>>(x, tmp, ln1g, ln1b, hbuf, hf);
    // FF1 + ReLU -> fp16
    gemm_f16<<<dim3(Ff / 128, Mrows / 128), tb, 3 * GSTG>>>(
        hf, wb + OFF_W1, b1, nullptr, ff, nullptr, nullptr, nullptr,
        Ff, Dm, 1);
    // FF2 -> fp32
    gemm_f16<<<dim3(Dm / 128, Mrows / 128), tb, 3 * GSTG>>>(
        ff, wb + OFF_W2, b2, tmp, nullptr, nullptr, nullptr, nullptr,
        Dm, Ff, 0);
    // LN2 -> out
    add_ln_kernel<<<Mrows, tb>>>(hbuf, tmp, ln2g, ln2b, out, nullptr);
}